// round 11
// baseline (speedup 1.0000x reference)
#include <cuda_runtime.h>
#include <cuda_fp16.h>
#include <cstdint>
#include <cstddef>

// Problem constants
#define TLEN   512
#define BATCH  4
#define HEADS  16
#define HDIM   64
#define EDIM   1024
#define ROWS_ALL 6144          // (1+NGRAM)*T * B
#define BH     64
#define TGT    1536
#define KA     2048            // activation split-K (fp16 [hi|lo])
#define KB     1024            // weight K (fp16 hi only)

// ---------------- scratch (static device globals; no allocation) -------------
__device__ float g_q[(size_t)BH * TGT * HDIM];
__device__ float g_k[(size_t)BH * TGT * HDIM];
__device__ float g_v[(size_t)BH * TGT * HDIM];
__device__ float g_relvals[(size_t)ROWS_ALL * 512];
__device__ __half g_A2[(size_t)ROWS_ALL * KA];       // [hi|lo] activations
__device__ __half g_Wqkv2[(size_t)3072 * KB];
__device__ __half g_Wrel2[(size_t)512 * KB];
__device__ __half g_Wout2[(size_t)1024 * KB];

__device__ __forceinline__ uint32_t smem_u32(const void* p) {
    uint32_t a;
    asm("{ .reg .u64 t; cvta.to.shared.u64 t, %1; cvt.u32.u64 %0, t; }" : "=r"(a) : "l"(p));
    return a;
}
__device__ __forceinline__ uint32_t pack_h2(__half a, __half b) {
    __half2 t = __halves2half2(a, b);
    return *reinterpret_cast<uint32_t*>(&t);
}

// ---------------- fused conversion (1 launch) ---------------------------------
// blocks [0,6144): hidden -> A2 split ; [6144,9216): w_in ; [9216,9728): rel_w ;
// [9728,10752): out_w
__global__ __launch_bounds__(256)
void convert_all(const float* __restrict__ hidden, const float* __restrict__ w_in,
                 const float* __restrict__ rel_w, const float* __restrict__ out_w,
                 __half* __restrict__ A2, __half* __restrict__ Wq,
                 __half* __restrict__ Wr, __half* __restrict__ Wo)
{
    int bid = blockIdx.x;
    if (bid < 6144) {
        int i4 = (bid * 256 + threadIdx.x) * 4;
        float4 a = *(const float4*)(hidden + i4);
        int r = i4 >> 10, k = i4 & 1023;
        size_t base = (size_t)r * KA + k;
        float av[4] = {a.x, a.y, a.z, a.w};
        __half h[4], l[4];
#pragma unroll
        for (int j = 0; j < 4; j++) {
            h[j] = __float2half_rn(av[j]);
            l[j] = __float2half_rn(av[j] - __half2float(h[j]));
        }
        *(__half2*)(A2 + base + 0) = __halves2half2(h[0], h[1]);
        *(__half2*)(A2 + base + 2) = __halves2half2(h[2], h[3]);
        *(__half2*)(A2 + base + 1024) = __halves2half2(l[0], l[1]);
        *(__half2*)(A2 + base + 1026) = __halves2half2(l[2], l[3]);
    } else {
        const float* src; __half* dst; int rb;
        if (bid < 9216)      { src = w_in;  dst = Wq; rb = bid - 6144; }
        else if (bid < 9728) { src = rel_w; dst = Wr; rb = bid - 9216; }
        else                 { src = out_w; dst = Wo; rb = bid - 9728; }
        int i4 = (rb * 256 + threadIdx.x) * 4;
        float4 a = *(const float4*)(src + i4);
        *(__half2*)(dst + i4 + 0) = __halves2half2(__float2half_rn(a.x), __float2half_rn(a.y));
        *(__half2*)(dst + i4 + 2) = __halves2half2(__float2half_rn(a.z), __float2half_rn(a.w));
    }
}

// ---------------- mma.sync fp16 GEMM (QKV+rel fused launch) -------------------
#define GSTAGES 3
#define STAGE_BYTES 16384
#define SMEM_A 0
#define SMEM_B (GSTAGES * STAGE_BYTES)
#define GEMM_SMEM (2 * GSTAGES * STAGE_BYTES)   // 96 KB

#define LOAD_STAGE(ld) do {                                                    \
        int _s = (ld) % 3;                                                     \
        uint32_t _ab = sb + SMEM_A + _s * STAGE_BYTES;                         \
        uint32_t _bb = sb + SMEM_B + _s * STAGE_BYTES;                         \
        const __half* _ag = Ab + (ld) * 64;                                    \
        const __half* _bg = Bb + ((ld) & 15) * 64;                             \
        _Pragma("unroll")                                                      \
        for (int _c = 0; _c < 4; _c++) {                                       \
            int _chunk = tid + _c * 256;                                       \
            int _row = _chunk >> 3, _c16 = _chunk & 7;                         \
            uint32_t _off = (uint32_t)(_row * 128 + _c16 * 16);                \
            _off ^= ((_off >> 3) & 0x70);                                      \
            asm volatile("cp.async.cg.shared.global [%0], [%1], 16;"           \
                :: "r"(_ab + _off), "l"(_ag + (size_t)_row * KA + _c16 * 8));  \
            asm volatile("cp.async.cg.shared.global [%0], [%1], 16;"           \
                :: "r"(_bb + _off), "l"(_bg + (size_t)_row * KB + _c16 * 8));  \
        }                                                                      \
        asm volatile("cp.async.commit_group;");                                \
    } while (0)

#define LDSM_X4(f, addr)                                                       \
    asm volatile("ldmatrix.sync.aligned.m8n8.x4.shared.b16 {%0,%1,%2,%3}, [%4];" \
        : "=r"((f)[0]), "=r"((f)[1]), "=r"((f)[2]), "=r"((f)[3]) : "r"(addr))

#define LDSM_X4T(f, addr)                                                      \
    asm volatile("ldmatrix.sync.aligned.m8n8.x4.trans.shared.b16 {%0,%1,%2,%3}, [%4];" \
        : "=r"((f)[0]), "=r"((f)[1]), "=r"((f)[2]), "=r"((f)[3]) : "r"(addr))

#define MMA16816(d, a, b0, b1)                                                 \
    asm volatile("mma.sync.aligned.m16n8k16.row.col.f32.f16.f16.f32 "          \
        "{%0,%1,%2,%3}, {%4,%5,%6,%7}, {%8,%9}, {%0,%1,%2,%3};"                \
        : "+f"((d)[0]), "+f"((d)[1]), "+f"((d)[2]), "+f"((d)[3])               \
        : "r"((a)[0]), "r"((a)[1]), "r"((a)[2]), "r"((a)[3]),                  \
          "r"(b0), "r"(b1))

#define LOAD_FRAGS(ks) do {                                                    \
        _Pragma("unroll")                                                      \
        for (int _mt = 0; _mt < 2; _mt++)                                      \
            LDSM_X4(af[_mt], aB + aRowByte[_mt] +                              \
                    ((uint32_t)(((ks) * 2 + achunk)) ^ xa) * 16u);             \
        _Pragma("unroll")                                                      \
        for (int _nt2 = 0; _nt2 < 4; _nt2++)                                   \
            LDSM_X4(bf[_nt2], bB + bRowByte[_nt2] +                            \
                    ((uint32_t)(((ks) * 2 + bchunk)) ^ xb) * 16u);             \
    } while (0)

// If B2 != nullptr, blocks with blockIdx.x >= qkv_cols run the secondary
// (rel) problem: B2/bias2/C2, N2=512, nkit2=16, plain epilogue.
__global__ __launch_bounds__(256, 2)
void gemm_mma(const __half* __restrict__ A, const __half* __restrict__ B,
              const float* __restrict__ bias, float* __restrict__ C,
              int N, int nkit, int qkv_mode,
              float* __restrict__ qp, float* __restrict__ kp, float* __restrict__ vp,
              const __half* __restrict__ B2, const float* __restrict__ bias2,
              float* __restrict__ C2, int qkv_cols)
{
    extern __shared__ char smraw[];
    uint32_t sb = smem_u32(smraw);
    const int tid = threadIdx.x;
    const int wid = tid >> 5, lane = tid & 31;
    const int wm = wid & 3, wn = wid >> 2;
    int bn = blockIdx.x;
    const int bm = blockIdx.y;
    const __half* Bp = B;
    const float* biasp = bias;
    float* Cp = C;
    if (B2 != nullptr && bn >= qkv_cols) {
        bn -= qkv_cols;
        Bp = B2; biasp = bias2; Cp = C2;
        N = 512; nkit = 16; qkv_mode = 0;
    }
    const __half* Ab = A + (size_t)bm * 128 * KA;
    const __half* Bb = Bp + (size_t)bn * 128 * KB;

    float acc[2][8][4];
#pragma unroll
    for (int i = 0; i < 2; i++)
#pragma unroll
        for (int j = 0; j < 8; j++)
#pragma unroll
            for (int c = 0; c < 4; c++) acc[i][j][c] = 0.f;

    const int g = lane >> 3, r = lane & 7;
    const int rowA = wm * 32 + (g & 1) * 8 + r;
    const int achunk = (g >> 1);
    const uint32_t xa = (uint32_t)(rowA & 7);
    uint32_t aRowByte[2];
#pragma unroll
    for (int mt = 0; mt < 2; mt++) aRowByte[mt] = (uint32_t)((rowA + mt * 16) * 128);
    const int rowB = wn * 64 + (g >> 1) * 8 + r;
    const int bchunk = (g & 1);
    const uint32_t xb = (uint32_t)(rowB & 7);
    uint32_t bRowByte[4];
#pragma unroll
    for (int nt2 = 0; nt2 < 4; nt2++) bRowByte[nt2] = (uint32_t)((rowB + nt2 * 16) * 128);

    LOAD_STAGE(0); LOAD_STAGE(1);

    uint32_t af[2][4];
    uint32_t bf[4][4];

    for (int it = 0; it < nkit; it++) {
        if (it + 1 < nkit) asm volatile("cp.async.wait_group 1;");
        else               asm volatile("cp.async.wait_group 0;");
        __syncthreads();
        if (it + 2 < nkit) LOAD_STAGE(it + 2);

        const uint32_t aB = sb + SMEM_A + (uint32_t)((it % 3) * STAGE_BYTES);
        const uint32_t bB = sb + SMEM_B + (uint32_t)((it % 3) * STAGE_BYTES);
#pragma unroll
        for (int ks = 0; ks < 4; ks++) {
            LOAD_FRAGS(ks);
#pragma unroll
            for (int mt = 0; mt < 2; mt++)
#pragma unroll
                for (int nt = 0; nt < 8; nt++) {
                    const uint32_t* bp = bf[nt >> 1];
                    int o = (nt & 1) * 2;
                    MMA16816(acc[mt][nt], af[mt], bp[o], bp[o + 1]);
                }
        }
    }

    const int mrow0 = bm * 128 + wm * 32 + (lane >> 2);
    const int colb  = bn * 128 + wn * 64;
    if (!qkv_mode) {
#pragma unroll
        for (int mt = 0; mt < 2; mt++)
#pragma unroll
            for (int nt = 0; nt < 8; nt++) {
                int col = colb + nt * 8 + (lane & 3) * 2;
                float2 b2 = *(const float2*)&biasp[col];
                int row = mrow0 + mt * 16;
                *(float2*)&Cp[(size_t)row * N + col] =
                    make_float2(acc[mt][nt][0] + b2.x, acc[mt][nt][1] + b2.y);
                *(float2*)&Cp[(size_t)(row + 8) * N + col] =
                    make_float2(acc[mt][nt][2] + b2.x, acc[mt][nt][3] + b2.y);
            }
    } else {
        const int which = colb >> 10;
        const int hh = (colb >> 6) & 15;
        float* dst = (which == 0) ? qp : (which == 1) ? kp : vp;
        const float scale = (which == 0) ? 0.125f : 1.0f;
#pragma unroll
        for (int mt = 0; mt < 2; mt++)
#pragma unroll
            for (int nt = 0; nt < 8; nt++) {
                int dd = nt * 8 + (lane & 3) * 2;
                float2 b2 = *(const float2*)&biasp[colb + dd];
#pragma unroll
                for (int half = 0; half < 2; half++) {
                    int row = mrow0 + mt * 16 + half * 8;
                    int t = row >> 2, b3 = row & 3;
                    float* basep = dst + ((size_t)((b3 << 4) + hh) * TGT + t) * HDIM + dd;
                    *(float2*)basep = make_float2(
                        (acc[mt][nt][half * 2 + 0] + b2.x) * scale,
                        (acc[mt][nt][half * 2 + 1] + b2.y) * scale);
                }
            }
    }
}

// ---------------- tensor-core flash attention ---------------------------------
struct AttnTc {
    __half qh[4096];
    __half ql[4096];
    __half kh[4096];
    __half vh[4096];
    float relrow[64][32];
    float Ld[64];
};

__global__ __launch_bounds__(128)
void attn_tc(const float* __restrict__ q, const float* __restrict__ k,
             const float* __restrict__ v, const float* __restrict__ relvals,
             const int* __restrict__ bkm, const int* __restrict__ bkn,
             __half* __restrict__ a2out)
{
    extern __shared__ char smraw[];
    AttnTc& sm = *reinterpret_cast<AttnTc*>(smraw);
    const int qt = blockIdx.x, bh = blockIdx.y, mode = blockIdx.z;
    const int b = bh >> 4, h = bh & 15;
    const int tid = threadIdx.x, wid = tid >> 5, lane = tid & 31;
    const int t0 = qt * 64, n = mode - 1, grow0 = mode * 512 + t0;
    const int qr = lane >> 2, qc = lane & 3;
    const int g = lane >> 3, r8 = lane & 7;

    const float* qb = q + ((size_t)bh * TGT + grow0) * HDIM;
    for (int i = tid; i < 512; i += 128) {
        int row = i >> 3, c = i & 7;
        const float* src = qb + row * 64 + c * 8;
        float4 x0 = *(const float4*)src, x1 = *(const float4*)(src + 4);
        float xs[8] = {x0.x, x0.y, x0.z, x0.w, x1.x, x1.y, x1.z, x1.w};
        __half hh[8], ll[8];
#pragma unroll
        for (int j = 0; j < 8; j++) {
            hh[j] = __float2half_rn(xs[j]);
            ll[j] = __float2half_rn(xs[j] - __half2float(hh[j]));
        }
        int idx = row * 64 + ((c ^ (row & 7)) << 3);
        uint4 hv, lv;
        hv.x = pack_h2(hh[0], hh[1]); hv.y = pack_h2(hh[2], hh[3]);
        hv.z = pack_h2(hh[4], hh[5]); hv.w = pack_h2(hh[6], hh[7]);
        lv.x = pack_h2(ll[0], ll[1]); lv.y = pack_h2(ll[2], ll[3]);
        lv.z = pack_h2(ll[4], ll[5]); lv.w = pack_h2(ll[6], ll[7]);
        *(uint4*)&sm.qh[idx] = hv;
        *(uint4*)&sm.ql[idx] = lv;
    }
    for (int idx = tid; idx < 2048; idx += 128) {
        int i = idx >> 5, nb = idx & 31;
        sm.relrow[i][nb] = relvals[((size_t)(grow0 + i) * 4 + b) * 512 + nb * 16 + h];
    }
    __syncthreads();

    const uint32_t qh_base = smem_u32(sm.qh), ql_base = smem_u32(sm.ql);
    const uint32_t kh_base = smem_u32(sm.kh), vh_base = smem_u32(sm.vh);
    const int arow = wid * 16 + (g & 1) * 8 + r8;
    const int achunk = g >> 1;
    uint32_t afh[4][4], afl[4][4];
#pragma unroll
    for (int ks = 0; ks < 4; ks++) {
        uint32_t off = (uint32_t)(arow * 128 + (((ks * 2 + achunk) ^ (arow & 7)) * 16));
        LDSM_X4(afh[ks], qh_base + off);
        LDSM_X4(afl[ks], ql_base + off);
    }

    const int brow8 = (g >> 1) * 8 + r8;
    const int bchunk = g & 1;
    const int vrow8 = (g & 1) * 8 + r8;
    const int vdo = g >> 1;

    float m_i[2] = {-1e30f, -1e30f}, l_i[2] = {0.f, 0.f};
    float of[8][4];
#pragma unroll
    for (int nt = 0; nt < 8; nt++)
#pragma unroll
        for (int c = 0; c < 4; c++) of[nt][c] = 0.f;

    const int nloop = qt + 1;
    const int bstride = (mode == 0) ? 512 : 1024;
    const int* bkp = (mode == 0) ? bkm : bkn;

    for (int ci = 0; ci < nloop; ci++) {
        const int s0 = ci * 64;
        __syncthreads();
        {
            const float* kb = k + ((size_t)bh * TGT + s0) * HDIM;
            const float* vb = v + ((size_t)bh * TGT + s0) * HDIM;
            for (int i = tid; i < 512; i += 128) {
                int row = i >> 3, c = i & 7;
                int idx = row * 64 + ((c ^ (row & 7)) << 3);
                const float* ks_ = kb + row * 64 + c * 8;
                float4 a0 = *(const float4*)ks_, a1 = *(const float4*)(ks_ + 4);
                uint4 kv;
                kv.x = pack_h2(__float2half_rn(a0.x), __float2half_rn(a0.y));
                kv.y = pack_h2(__float2half_rn(a0.z), __float2half_rn(a0.w));
                kv.z = pack_h2(__float2half_rn(a1.x), __float2half_rn(a1.y));
                kv.w = pack_h2(__float2half_rn(a1.z), __float2half_rn(a1.w));
                *(uint4*)&sm.kh[idx] = kv;
                const float* vs_ = vb + row * 64 + c * 8;
                float4 b0 = *(const float4*)vs_, b1 = *(const float4*)(vs_ + 4);
                uint4 vv;
                vv.x = pack_h2(__float2half_rn(b0.x), __float2half_rn(b0.y));
                vv.y = pack_h2(__float2half_rn(b0.z), __float2half_rn(b0.w));
                vv.z = pack_h2(__float2half_rn(b1.x), __float2half_rn(b1.y));
                vv.w = pack_h2(__float2half_rn(b1.z), __float2half_rn(b1.w));
                *(uint4*)&sm.vh[idx] = vv;
            }
        }
        __syncthreads();

        float sacc[8][4];
#pragma unroll
        for (int nt = 0; nt < 8; nt++)
#pragma unroll
            for (int c = 0; c < 4; c++) sacc[nt][c] = 0.f;
#pragma unroll
        for (int ks = 0; ks < 4; ks++) {
            uint32_t bq[4][4];
#pragma unroll
            for (int nt2 = 0; nt2 < 4; nt2++) {
                int krow = nt2 * 16 + brow8;
                uint32_t off = (uint32_t)(krow * 128 + (((ks * 2 + bchunk) ^ (krow & 7)) * 16));
                LDSM_X4(bq[nt2], kh_base + off);
            }
#pragma unroll
            for (int nt2 = 0; nt2 < 4; nt2++) {
                MMA16816(sacc[2 * nt2],     afh[ks], bq[nt2][0], bq[nt2][1]);
                MMA16816(sacc[2 * nt2 + 1], afh[ks], bq[nt2][2], bq[nt2][3]);
                MMA16816(sacc[2 * nt2],     afl[ks], bq[nt2][0], bq[nt2][1]);
                MMA16816(sacc[2 * nt2 + 1], afl[ks], bq[nt2][2], bq[nt2][3]);
            }
        }

#pragma unroll
        for (int rh = 0; rh < 2; rh++) {
            int rl = wid * 16 + qr + rh * 8;
            int t_loc = t0 + rl;
            const int* bkrow = bkp + (size_t)t_loc * bstride + s0 + qc * 2;
#pragma unroll
            for (int nt = 0; nt < 8; nt++) {
                int2 bk2 = *(const int2*)(bkrow + nt * 8);
                int sg = s0 + nt * 8 + qc * 2;
                sacc[nt][rh * 2 + 0] += sm.relrow[rl][bk2.x] + ((sg     <= t_loc) ? 0.f : -10000.f);
                sacc[nt][rh * 2 + 1] += sm.relrow[rl][bk2.y] + ((sg + 1 <= t_loc) ? 0.f : -10000.f);
            }
        }

#pragma unroll
        for (int rh = 0; rh < 2; rh++) {
            float mc = -1e30f;
#pragma unroll
            for (int nt = 0; nt < 8; nt++) {
                mc = fmaxf(mc, sacc[nt][rh * 2]);
                mc = fmaxf(mc, sacc[nt][rh * 2 + 1]);
            }
            mc = fmaxf(mc, __shfl_xor_sync(0xFFFFFFFFu, mc, 1));
            mc = fmaxf(mc, __shfl_xor_sync(0xFFFFFFFFu, mc, 2));
            float mnew = fmaxf(m_i[rh], mc);
            float al = __expf(m_i[rh] - mnew);
            float ls = 0.f;
#pragma unroll
            for (int nt = 0; nt < 8; nt++) {
                float e0 = __expf(sacc[nt][rh * 2]     - mnew);
                float e1 = __expf(sacc[nt][rh * 2 + 1] - mnew);
                sacc[nt][rh * 2] = e0; sacc[nt][rh * 2 + 1] = e1;
                ls += e0 + e1;
            }
            ls += __shfl_xor_sync(0xFFFFFFFFu, ls, 1);
            ls += __shfl_xor_sync(0xFFFFFFFFu, ls, 2);
            l_i[rh] = l_i[rh] * al + ls;
            m_i[rh] = mnew;
#pragma unroll
            for (int nt = 0; nt < 8; nt++) {
                of[nt][rh * 2] *= al; of[nt][rh * 2 + 1] *= al;
            }
        }

#pragma unroll
        for (int ks = 0; ks < 4; ks++) {
            uint32_t bv[4][4];
#pragma unroll
            for (int nt2 = 0; nt2 < 4; nt2++) {
                int srow = ks * 16 + vrow8;
                int dchunk = nt2 * 2 + vdo;
                uint32_t off = (uint32_t)(srow * 128 + ((dchunk ^ (srow & 7)) * 16));
                LDSM_X4T(bv[nt2], vh_base + off);
            }
            uint32_t ph[4], pl[4];
            {
                float e[8] = {sacc[2*ks][0], sacc[2*ks][1], sacc[2*ks][2], sacc[2*ks][3],
                              sacc[2*ks+1][0], sacc[2*ks+1][1], sacc[2*ks+1][2], sacc[2*ks+1][3]};
                __half eh[8], el[8];
#pragma unroll
                for (int j = 0; j < 8; j++) {
                    eh[j] = __float2half_rn(e[j]);
                    el[j] = __float2half_rn(e[j] - __half2float(eh[j]));
                }
                ph[0] = pack_h2(eh[0], eh[1]); ph[1] = pack_h2(eh[2], eh[3]);
                ph[2] = pack_h2(eh[4], eh[5]); ph[3] = pack_h2(eh[6], eh[7]);
                pl[0] = pack_h2(el[0], el[1]); pl[1] = pack_h2(el[2], el[3]);
                pl[2] = pack_h2(el[4], el[5]); pl[3] = pack_h2(el[6], el[7]);
            }
#pragma unroll
            for (int nt2 = 0; nt2 < 4; nt2++) {
                MMA16816(of[2 * nt2],     ph, bv[nt2][0], bv[nt2][1]);
                MMA16816(of[2 * nt2 + 1], ph, bv[nt2][2], bv[nt2][3]);
                MMA16816(of[2 * nt2],     pl, bv[nt2][0], bv[nt2][1]);
                MMA16816(of[2 * nt2 + 1], pl, bv[nt2][2], bv[nt2][3]);
            }
        }
    }

    if (mode != 0) {
        {
            int row = tid >> 1, hf = tid & 1;
            int t_loc = t0 + row;
            int krow = n * 512 + 512 + t_loc;
            const float* kr = k + ((size_t)bh * TGT + krow) * HDIM + hf * 32;
            const float* qr2 = qb + row * 64 + hf * 32;
            float dot = 0.f;
#pragma unroll
            for (int j = 0; j < 8; j++) {
                float4 qa = *(const float4*)(qr2 + j * 4);
                float4 ka = *(const float4*)(kr + j * 4);
                dot += qa.x * ka.x + qa.y * ka.y + qa.z * ka.z + qa.w * ka.w;
            }
            dot += __shfl_xor_sync(0xFFFFFFFFu, dot, 1);
            int bk = bkn[(size_t)t_loc * 1024 + 512 + t_loc];
            float L = dot + sm.relrow[row][bk];
            if (!hf) sm.Ld[row] = L;
        }
        __syncthreads();
#pragma unroll
        for (int rh = 0; rh < 2; rh++) {
            int rl = wid * 16 + qr + rh * 8;
            int t_loc = t0 + rl;
            float L = sm.Ld[rl];
            float mnew = fmaxf(m_i[rh], L);
            float al = __expf(m_i[rh] - mnew);
            float p = __expf(L - mnew);
            l_i[rh] = l_i[rh] * al + p;
            m_i[rh] = mnew;
            const float* vr = v + ((size_t)bh * TGT + n * 512 + 512 + t_loc) * HDIM + qc * 2;
#pragma unroll
            for (int nt = 0; nt < 8; nt++) {
                float2 v2 = *(const float2*)(vr + nt * 8);
                of[nt][rh * 2]     = of[nt][rh * 2]     * al + p * v2.x;
                of[nt][rh * 2 + 1] = of[nt][rh * 2 + 1] * al + p * v2.y;
            }
        }
    }

    // epilogue: normalize + write fp16 [hi|lo] split straight into A2
#pragma unroll
    for (int rh = 0; rh < 2; rh++) {
        int rl = wid * 16 + qr + rh * 8;
        float inv = 1.0f / l_i[rh];
        size_t base = ((size_t)(grow0 + rl) * 4 + b) * KA + h * 64 + qc * 2;
#pragma unroll
        for (int nt = 0; nt < 8; nt++) {
            float x0 = of[nt][rh * 2] * inv;
            float x1 = of[nt][rh * 2 + 1] * inv;
            __half h0 = __float2half_rn(x0);
            __half h1 = __float2half_rn(x1);
            __half l0 = __float2half_rn(x0 - __half2float(h0));
            __half l1 = __float2half_rn(x1 - __half2float(h1));
            *(__half2*)&a2out[base + nt * 8]        = __halves2half2(h0, h1);
            *(__half2*)&a2out[base + nt * 8 + 1024] = __halves2half2(l0, l1);
        }
    }
}

// ---------------- launch -----------------------------------------------------
extern "C" void kernel_launch(void* const* d_in, const int* in_sizes, int n_in,
                              void* d_out, int out_size)
{
    const float* hidden = (const float*)d_in[0];
    const float* w_in   = (const float*)d_in[1];
    const float* b_in   = (const float*)d_in[2];
    const float* rel_w  = (const float*)d_in[3];
    const float* rel_b  = (const float*)d_in[4];
    const float* out_w  = (const float*)d_in[5];
    const float* out_b  = (const float*)d_in[6];
    const int* bkm = (const int*)d_in[9];
    const int* bkn = (const int*)d_in[10];
    float* out = (float*)d_out;

    float *qp, *kp, *vp, *rv;
    __half *A2, *Wqkv2, *Wrel2, *Wout2;
    cudaGetSymbolAddress((void**)&qp,  g_q);
    cudaGetSymbolAddress((void**)&kp,  g_k);
    cudaGetSymbolAddress((void**)&vp,  g_v);
    cudaGetSymbolAddress((void**)&rv,  g_relvals);
    cudaGetSymbolAddress((void**)&A2,    g_A2);
    cudaGetSymbolAddress((void**)&Wqkv2, g_Wqkv2);
    cudaGetSymbolAddress((void**)&Wrel2, g_Wrel2);
    cudaGetSymbolAddress((void**)&Wout2, g_Wout2);

    cudaFuncSetAttribute(gemm_mma, cudaFuncAttributeMaxDynamicSharedMemorySize, GEMM_SMEM);
    cudaFuncSetAttribute(attn_tc, cudaFuncAttributeMaxDynamicSharedMemorySize,
                         (int)sizeof(AttnTc));

    // 0) one fused conversion launch
    convert_all<<<10752, 256>>>(hidden, w_in, rel_w, out_w, A2, Wqkv2, Wrel2, Wout2);

    // 1) QKV projection + rel values fused in one launch (grid.x = 24 + 4)
    gemm_mma<<<dim3(28, ROWS_ALL / 128), 256, GEMM_SMEM>>>(
        A2, Wqkv2, b_in, nullptr, 3072, 32, 1, qp, kp, vp,
        Wrel2, rel_b, rv, 24);

    // 2) tensor-core flash attention -> writes fp16 split directly into A2
    attn_tc<<<dim3(8, 64, 3), 128, sizeof(AttnTc)>>>(qp, kp, vp, rv, bkm, bkn, A2);

    // 3) output projection
    gemm_mma<<<dim3(8, ROWS_ALL / 128), 256, GEMM_SMEM>>>(
        A2, Wout2, out_b, out, 1024, 32, 0, nullptr, nullptr, nullptr,
        nullptr, nullptr, nullptr, 0);
}

// round 12
// speedup vs baseline: 1.5032x; 1.5032x over previous
#include <cuda_runtime.h>
#include <cuda_fp16.h>
#include <cstdint>
#include <cstddef>

// Problem constants
#define TLEN   512
#define BATCH  4
#define HEADS  16
#define HDIM   64
#define EDIM   1024
#define ROWS_ALL 6144          // (1+NGRAM)*T * B
#define BH     64
#define TGT    1536
#define KA     2048            // activation split-K (fp16 [hi|lo])
#define KB     1024            // weight K (fp16 hi only)

// ---------------- scratch (static device globals; no allocation) -------------
__device__ float g_q[(size_t)BH * TGT * HDIM];
__device__ float g_k[(size_t)BH * TGT * HDIM];
__device__ float g_v[(size_t)BH * TGT * HDIM];
__device__ float g_relvals[(size_t)ROWS_ALL * 512];
__device__ float g_ctx[(size_t)ROWS_ALL * EDIM];
__device__ __half g_A2[(size_t)ROWS_ALL * KA];       // [hi|lo] activations
__device__ __half g_Wqkv2[(size_t)3072 * KB];
__device__ __half g_Wrel2[(size_t)512 * KB];
__device__ __half g_Wout2[(size_t)1024 * KB];

__device__ __forceinline__ uint32_t smem_u32(const void* p) {
    uint32_t a;
    asm("{ .reg .u64 t; cvta.to.shared.u64 t, %1; cvt.u32.u64 %0, t; }" : "=r"(a) : "l"(p));
    return a;
}
__device__ __forceinline__ uint32_t pack_h2(__half a, __half b) {
    __half2 t = __halves2half2(a, b);
    return *reinterpret_cast<uint32_t*>(&t);
}

// ---------------- conversions --------------------------------------------------
// activations: f32 [rows][1024] -> fp16 [rows][2048] as [hi|lo]
__global__ __launch_bounds__(256)
void convert_act(const float* __restrict__ src, __half* __restrict__ dst)
{
    int i4 = (blockIdx.x * blockDim.x + threadIdx.x) * 4;
    float4 a = *(const float4*)(src + i4);
    int r = i4 >> 10, k = i4 & 1023;
    size_t base = (size_t)r * KA + k;
    float av[4] = {a.x, a.y, a.z, a.w};
    __half h[4], l[4];
#pragma unroll
    for (int j = 0; j < 4; j++) {
        h[j] = __float2half_rn(av[j]);
        l[j] = __float2half_rn(av[j] - __half2float(h[j]));
    }
    *(__half2*)(dst + base + 0) = __halves2half2(h[0], h[1]);
    *(__half2*)(dst + base + 2) = __halves2half2(h[2], h[3]);
    *(__half2*)(dst + base + 1024) = __halves2half2(l[0], l[1]);
    *(__half2*)(dst + base + 1026) = __halves2half2(l[2], l[3]);
}

// fused first-round conversion: hidden split + all 3 weight casts, one launch.
// blocks [0,6144): hidden ; [6144,9216): w_in ; [9216,9728): rel_w ; [9728,10752): out_w
__global__ __launch_bounds__(256)
void convert_all(const float* __restrict__ hidden, const float* __restrict__ w_in,
                 const float* __restrict__ rel_w, const float* __restrict__ out_w,
                 __half* __restrict__ A2, __half* __restrict__ Wq,
                 __half* __restrict__ Wr, __half* __restrict__ Wo)
{
    int bid = blockIdx.x;
    if (bid < 6144) {
        int i4 = (bid * 256 + threadIdx.x) * 4;
        float4 a = *(const float4*)(hidden + i4);
        int r = i4 >> 10, k = i4 & 1023;
        size_t base = (size_t)r * KA + k;
        float av[4] = {a.x, a.y, a.z, a.w};
        __half h[4], l[4];
#pragma unroll
        for (int j = 0; j < 4; j++) {
            h[j] = __float2half_rn(av[j]);
            l[j] = __float2half_rn(av[j] - __half2float(h[j]));
        }
        *(__half2*)(A2 + base + 0) = __halves2half2(h[0], h[1]);
        *(__half2*)(A2 + base + 2) = __halves2half2(h[2], h[3]);
        *(__half2*)(A2 + base + 1024) = __halves2half2(l[0], l[1]);
        *(__half2*)(A2 + base + 1026) = __halves2half2(l[2], l[3]);
    } else {
        const float* src; __half* dst; int rb;
        if (bid < 9216)      { src = w_in;  dst = Wq; rb = bid - 6144; }
        else if (bid < 9728) { src = rel_w; dst = Wr; rb = bid - 9216; }
        else                 { src = out_w; dst = Wo; rb = bid - 9728; }
        int i4 = (rb * 256 + threadIdx.x) * 4;
        float4 a = *(const float4*)(src + i4);
        *(__half2*)(dst + i4 + 0) = __halves2half2(__float2half_rn(a.x), __float2half_rn(a.y));
        *(__half2*)(dst + i4 + 2) = __halves2half2(__float2half_rn(a.z), __float2half_rn(a.w));
    }
}

// ---------------- mma.sync fp16 GEMM (R10-exact; register-critical) -----------
#define GSTAGES 3
#define STAGE_BYTES 16384
#define SMEM_A 0
#define SMEM_B (GSTAGES * STAGE_BYTES)
#define GEMM_SMEM (2 * GSTAGES * STAGE_BYTES)   // 96 KB

#define LOAD_STAGE(ld) do {                                                    \
        int _s = (ld) % 3;                                                     \
        uint32_t _ab = sb + SMEM_A + _s * STAGE_BYTES;                         \
        uint32_t _bb = sb + SMEM_B + _s * STAGE_BYTES;                         \
        const __half* _ag = Ab + (ld) * 64;                                    \
        const __half* _bg = Bb + ((ld) & 15) * 64;                             \
        _Pragma("unroll")                                                      \
        for (int _c = 0; _c < 4; _c++) {                                       \
            int _chunk = tid + _c * 256;                                       \
            int _row = _chunk >> 3, _c16 = _chunk & 7;                         \
            uint32_t _off = (uint32_t)(_row * 128 + _c16 * 16);                \
            _off ^= ((_off >> 3) & 0x70);                                      \
            asm volatile("cp.async.cg.shared.global [%0], [%1], 16;"           \
                :: "r"(_ab + _off), "l"(_ag + (size_t)_row * KA + _c16 * 8));  \
            asm volatile("cp.async.cg.shared.global [%0], [%1], 16;"           \
                :: "r"(_bb + _off), "l"(_bg + (size_t)_row * KB + _c16 * 8));  \
        }                                                                      \
        asm volatile("cp.async.commit_group;");                                \
    } while (0)

#define LDSM_X4(f, addr)                                                       \
    asm volatile("ldmatrix.sync.aligned.m8n8.x4.shared.b16 {%0,%1,%2,%3}, [%4];" \
        : "=r"((f)[0]), "=r"((f)[1]), "=r"((f)[2]), "=r"((f)[3]) : "r"(addr))

#define LDSM_X4T(f, addr)                                                      \
    asm volatile("ldmatrix.sync.aligned.m8n8.x4.trans.shared.b16 {%0,%1,%2,%3}, [%4];" \
        : "=r"((f)[0]), "=r"((f)[1]), "=r"((f)[2]), "=r"((f)[3]) : "r"(addr))

#define MMA16816(d, a, b0, b1)                                                 \
    asm volatile("mma.sync.aligned.m16n8k16.row.col.f32.f16.f16.f32 "          \
        "{%0,%1,%2,%3}, {%4,%5,%6,%7}, {%8,%9}, {%0,%1,%2,%3};"                \
        : "+f"((d)[0]), "+f"((d)[1]), "+f"((d)[2]), "+f"((d)[3])               \
        : "r"((a)[0]), "r"((a)[1]), "r"((a)[2]), "r"((a)[3]),                  \
          "r"(b0), "r"(b1))

#define LOAD_FRAGS(ks) do {                                                    \
        _Pragma("unroll")                                                      \
        for (int _mt = 0; _mt < 2; _mt++)                                      \
            LDSM_X4(af[_mt], aB + aRowByte[_mt] +                              \
                    ((uint32_t)(((ks) * 2 + achunk)) ^ xa) * 16u);             \
        _Pragma("unroll")                                                      \
        for (int _nt2 = 0; _nt2 < 4; _nt2++)                                   \
            LDSM_X4(bf[_nt2], bB + bRowByte[_nt2] +                            \
                    ((uint32_t)(((ks) * 2 + bchunk)) ^ xb) * 16u);             \
    } while (0)

__global__ __launch_bounds__(256, 2)
void gemm_mma(const __half* __restrict__ A, const __half* __restrict__ B,
              const float* __restrict__ bias, float* __restrict__ C,
              int N, int nkit, int qkv_mode,
              float* __restrict__ qp, float* __restrict__ kp, float* __restrict__ vp)
{
    extern __shared__ char smraw[];
    uint32_t sb = smem_u32(smraw);
    const int tid = threadIdx.x;
    const int wid = tid >> 5, lane = tid & 31;
    const int wm = wid & 3, wn = wid >> 2;
    const int bn = blockIdx.x, bm = blockIdx.y;
    const __half* Ab = A + (size_t)bm * 128 * KA;
    const __half* Bb = B + (size_t)bn * 128 * KB;

    float acc[2][8][4];
#pragma unroll
    for (int i = 0; i < 2; i++)
#pragma unroll
        for (int j = 0; j < 8; j++)
#pragma unroll
            for (int c = 0; c < 4; c++) acc[i][j][c] = 0.f;

    const int g = lane >> 3, r = lane & 7;
    const int rowA = wm * 32 + (g & 1) * 8 + r;
    const int achunk = (g >> 1);
    const uint32_t xa = (uint32_t)(rowA & 7);
    uint32_t aRowByte[2];
#pragma unroll
    for (int mt = 0; mt < 2; mt++) aRowByte[mt] = (uint32_t)((rowA + mt * 16) * 128);
    const int rowB = wn * 64 + (g >> 1) * 8 + r;
    const int bchunk = (g & 1);
    const uint32_t xb = (uint32_t)(rowB & 7);
    uint32_t bRowByte[4];
#pragma unroll
    for (int nt2 = 0; nt2 < 4; nt2++) bRowByte[nt2] = (uint32_t)((rowB + nt2 * 16) * 128);

    LOAD_STAGE(0); LOAD_STAGE(1);

    uint32_t af[2][4];
    uint32_t bf[4][4];

    for (int it = 0; it < nkit; it++) {
        if (it + 1 < nkit) asm volatile("cp.async.wait_group 1;");
        else               asm volatile("cp.async.wait_group 0;");
        __syncthreads();
        if (it + 2 < nkit) LOAD_STAGE(it + 2);

        const uint32_t aB = sb + SMEM_A + (uint32_t)((it % 3) * STAGE_BYTES);
        const uint32_t bB = sb + SMEM_B + (uint32_t)((it % 3) * STAGE_BYTES);
#pragma unroll
        for (int ks = 0; ks < 4; ks++) {
            LOAD_FRAGS(ks);
#pragma unroll
            for (int mt = 0; mt < 2; mt++)
#pragma unroll
                for (int nt = 0; nt < 8; nt++) {
                    const uint32_t* bp = bf[nt >> 1];
                    int o = (nt & 1) * 2;
                    MMA16816(acc[mt][nt], af[mt], bp[o], bp[o + 1]);
                }
        }
    }

    const int mrow0 = bm * 128 + wm * 32 + (lane >> 2);
    const int colb  = bn * 128 + wn * 64;
    if (!qkv_mode) {
#pragma unroll
        for (int mt = 0; mt < 2; mt++)
#pragma unroll
            for (int nt = 0; nt < 8; nt++) {
                int col = colb + nt * 8 + (lane & 3) * 2;
                float2 b2 = *(const float2*)&bias[col];
                int row = mrow0 + mt * 16;
                *(float2*)&C[(size_t)row * N + col] =
                    make_float2(acc[mt][nt][0] + b2.x, acc[mt][nt][1] + b2.y);
                *(float2*)&C[(size_t)(row + 8) * N + col] =
                    make_float2(acc[mt][nt][2] + b2.x, acc[mt][nt][3] + b2.y);
            }
    } else {
        const int which = colb >> 10;
        const int hh = (colb >> 6) & 15;
        float* dst = (which == 0) ? qp : (which == 1) ? kp : vp;
        const float scale = (which == 0) ? 0.125f : 1.0f;
#pragma unroll
        for (int mt = 0; mt < 2; mt++)
#pragma unroll
            for (int nt = 0; nt < 8; nt++) {
                int dd = nt * 8 + (lane & 3) * 2;
                float2 b2 = *(const float2*)&bias[colb + dd];
#pragma unroll
                for (int half = 0; half < 2; half++) {
                    int row = mrow0 + mt * 16 + half * 8;
                    int t = row >> 2, b3 = row & 3;
                    float* basep = dst + ((size_t)((b3 << 4) + hh) * TGT + t) * HDIM + dd;
                    *(float2*)basep = make_float2(
                        (acc[mt][nt][half * 2 + 0] + b2.x) * scale,
                        (acc[mt][nt][half * 2 + 1] + b2.y) * scale);
                }
            }
    }
}

// ---------------- tensor-core flash attention (R10-exact) ---------------------
struct AttnTc {
    __half qh[4096];
    __half ql[4096];
    __half kh[4096];
    __half vh[4096];
    float relrow[64][32];
    float Ld[64];
};

__global__ __launch_bounds__(128)
void attn_tc(const float* __restrict__ q, const float* __restrict__ k,
             const float* __restrict__ v, const float* __restrict__ relvals,
             const int* __restrict__ bkm, const int* __restrict__ bkn,
             float* __restrict__ ctx)
{
    extern __shared__ char smraw[];
    AttnTc& sm = *reinterpret_cast<AttnTc*>(smraw);
    const int qt = blockIdx.x, bh = blockIdx.y, mode = blockIdx.z;
    const int b = bh >> 4, h = bh & 15;
    const int tid = threadIdx.x, wid = tid >> 5, lane = tid & 31;
    const int t0 = qt * 64, n = mode - 1, grow0 = mode * 512 + t0;
    const int qr = lane >> 2, qc = lane & 3;
    const int g = lane >> 3, r8 = lane & 7;

    const float* qb = q + ((size_t)bh * TGT + grow0) * HDIM;
    for (int i = tid; i < 512; i += 128) {
        int row = i >> 3, c = i & 7;
        const float* src = qb + row * 64 + c * 8;
        float4 x0 = *(const float4*)src, x1 = *(const float4*)(src + 4);
        float xs[8] = {x0.x, x0.y, x0.z, x0.w, x1.x, x1.y, x1.z, x1.w};
        __half hh[8], ll[8];
#pragma unroll
        for (int j = 0; j < 8; j++) {
            hh[j] = __float2half_rn(xs[j]);
            ll[j] = __float2half_rn(xs[j] - __half2float(hh[j]));
        }
        int idx = row * 64 + ((c ^ (row & 7)) << 3);
        uint4 hv, lv;
        hv.x = pack_h2(hh[0], hh[1]); hv.y = pack_h2(hh[2], hh[3]);
        hv.z = pack_h2(hh[4], hh[5]); hv.w = pack_h2(hh[6], hh[7]);
        lv.x = pack_h2(ll[0], ll[1]); lv.y = pack_h2(ll[2], ll[3]);
        lv.z = pack_h2(ll[4], ll[5]); lv.w = pack_h2(ll[6], ll[7]);
        *(uint4*)&sm.qh[idx] = hv;
        *(uint4*)&sm.ql[idx] = lv;
    }
    for (int idx = tid; idx < 2048; idx += 128) {
        int i = idx >> 5, nb = idx & 31;
        sm.relrow[i][nb] = relvals[((size_t)(grow0 + i) * 4 + b) * 512 + nb * 16 + h];
    }
    __syncthreads();

    const uint32_t qh_base = smem_u32(sm.qh), ql_base = smem_u32(sm.ql);
    const uint32_t kh_base = smem_u32(sm.kh), vh_base = smem_u32(sm.vh);
    const int arow = wid * 16 + (g & 1) * 8 + r8;
    const int achunk = g >> 1;
    uint32_t afh[4][4], afl[4][4];
#pragma unroll
    for (int ks = 0; ks < 4; ks++) {
        uint32_t off = (uint32_t)(arow * 128 + (((ks * 2 + achunk) ^ (arow & 7)) * 16));
        LDSM_X4(afh[ks], qh_base + off);
        LDSM_X4(afl[ks], ql_base + off);
    }

    const int brow8 = (g >> 1) * 8 + r8;
    const int bchunk = g & 1;
    const int vrow8 = (g & 1) * 8 + r8;
    const int vdo = g >> 1;

    float m_i[2] = {-1e30f, -1e30f}, l_i[2] = {0.f, 0.f};
    float of[8][4];
#pragma unroll
    for (int nt = 0; nt < 8; nt++)
#pragma unroll
        for (int c = 0; c < 4; c++) of[nt][c] = 0.f;

    const int nloop = qt + 1;
    const int bstride = (mode == 0) ? 512 : 1024;
    const int* bkp = (mode == 0) ? bkm : bkn;

    for (int ci = 0; ci < nloop; ci++) {
        const int s0 = ci * 64;
        __syncthreads();
        {
            const float* kb = k + ((size_t)bh * TGT + s0) * HDIM;
            const float* vb = v + ((size_t)bh * TGT + s0) * HDIM;
            for (int i = tid; i < 512; i += 128) {
                int row = i >> 3, c = i & 7;
                int idx = row * 64 + ((c ^ (row & 7)) << 3);
                const float* ks_ = kb + row * 64 + c * 8;
                float4 a0 = *(const float4*)ks_, a1 = *(const float4*)(ks_ + 4);
                uint4 kv;
                kv.x = pack_h2(__float2half_rn(a0.x), __float2half_rn(a0.y));
                kv.y = pack_h2(__float2half_rn(a0.z), __float2half_rn(a0.w));
                kv.z = pack_h2(__float2half_rn(a1.x), __float2half_rn(a1.y));
                kv.w = pack_h2(__float2half_rn(a1.z), __float2half_rn(a1.w));
                *(uint4*)&sm.kh[idx] = kv;
                const float* vs_ = vb + row * 64 + c * 8;
                float4 b0 = *(const float4*)vs_, b1 = *(const float4*)(vs_ + 4);
                uint4 vv;
                vv.x = pack_h2(__float2half_rn(b0.x), __float2half_rn(b0.y));
                vv.y = pack_h2(__float2half_rn(b0.z), __float2half_rn(b0.w));
                vv.z = pack_h2(__float2half_rn(b1.x), __float2half_rn(b1.y));
                vv.w = pack_h2(__float2half_rn(b1.z), __float2half_rn(b1.w));
                *(uint4*)&sm.vh[idx] = vv;
            }
        }
        __syncthreads();

        float sacc[8][4];
#pragma unroll
        for (int nt = 0; nt < 8; nt++)
#pragma unroll
            for (int c = 0; c < 4; c++) sacc[nt][c] = 0.f;
#pragma unroll
        for (int ks = 0; ks < 4; ks++) {
            uint32_t bq[4][4];
#pragma unroll
            for (int nt2 = 0; nt2 < 4; nt2++) {
                int krow = nt2 * 16 + brow8;
                uint32_t off = (uint32_t)(krow * 128 + (((ks * 2 + bchunk) ^ (krow & 7)) * 16));
                LDSM_X4(bq[nt2], kh_base + off);
            }
#pragma unroll
            for (int nt2 = 0; nt2 < 4; nt2++) {
                MMA16816(sacc[2 * nt2],     afh[ks], bq[nt2][0], bq[nt2][1]);
                MMA16816(sacc[2 * nt2 + 1], afh[ks], bq[nt2][2], bq[nt2][3]);
                MMA16816(sacc[2 * nt2],     afl[ks], bq[nt2][0], bq[nt2][1]);
                MMA16816(sacc[2 * nt2 + 1], afl[ks], bq[nt2][2], bq[nt2][3]);
            }
        }

#pragma unroll
        for (int rh = 0; rh < 2; rh++) {
            int rl = wid * 16 + qr + rh * 8;
            int t_loc = t0 + rl;
            const int* bkrow = bkp + (size_t)t_loc * bstride + s0 + qc * 2;
#pragma unroll
            for (int nt = 0; nt < 8; nt++) {
                int2 bk2 = *(const int2*)(bkrow + nt * 8);
                int sg = s0 + nt * 8 + qc * 2;
                sacc[nt][rh * 2 + 0] += sm.relrow[rl][bk2.x] + ((sg     <= t_loc) ? 0.f : -10000.f);
                sacc[nt][rh * 2 + 1] += sm.relrow[rl][bk2.y] + ((sg + 1 <= t_loc) ? 0.f : -10000.f);
            }
        }

#pragma unroll
        for (int rh = 0; rh < 2; rh++) {
            float mc = -1e30f;
#pragma unroll
            for (int nt = 0; nt < 8; nt++) {
                mc = fmaxf(mc, sacc[nt][rh * 2]);
                mc = fmaxf(mc, sacc[nt][rh * 2 + 1]);
            }
            mc = fmaxf(mc, __shfl_xor_sync(0xFFFFFFFFu, mc, 1));
            mc = fmaxf(mc, __shfl_xor_sync(0xFFFFFFFFu, mc, 2));
            float mnew = fmaxf(m_i[rh], mc);
            float al = __expf(m_i[rh] - mnew);
            float ls = 0.f;
#pragma unroll
            for (int nt = 0; nt < 8; nt++) {
                float e0 = __expf(sacc[nt][rh * 2]     - mnew);
                float e1 = __expf(sacc[nt][rh * 2 + 1] - mnew);
                sacc[nt][rh * 2] = e0; sacc[nt][rh * 2 + 1] = e1;
                ls += e0 + e1;
            }
            ls += __shfl_xor_sync(0xFFFFFFFFu, ls, 1);
            ls += __shfl_xor_sync(0xFFFFFFFFu, ls, 2);
            l_i[rh] = l_i[rh] * al + ls;
            m_i[rh] = mnew;
#pragma unroll
            for (int nt = 0; nt < 8; nt++) {
                of[nt][rh * 2] *= al; of[nt][rh * 2 + 1] *= al;
            }
        }

#pragma unroll
        for (int ks = 0; ks < 4; ks++) {
            uint32_t bv[4][4];
#pragma unroll
            for (int nt2 = 0; nt2 < 4; nt2++) {
                int srow = ks * 16 + vrow8;
                int dchunk = nt2 * 2 + vdo;
                uint32_t off = (uint32_t)(srow * 128 + ((dchunk ^ (srow & 7)) * 16));
                LDSM_X4T(bv[nt2], vh_base + off);
            }
            uint32_t ph[4], pl[4];
            {
                float e[8] = {sacc[2*ks][0], sacc[2*ks][1], sacc[2*ks][2], sacc[2*ks][3],
                              sacc[2*ks+1][0], sacc[2*ks+1][1], sacc[2*ks+1][2], sacc[2*ks+1][3]};
                __half eh[8], el[8];
#pragma unroll
                for (int j = 0; j < 8; j++) {
                    eh[j] = __float2half_rn(e[j]);
                    el[j] = __float2half_rn(e[j] - __half2float(eh[j]));
                }
                ph[0] = pack_h2(eh[0], eh[1]); ph[1] = pack_h2(eh[2], eh[3]);
                ph[2] = pack_h2(eh[4], eh[5]); ph[3] = pack_h2(eh[6], eh[7]);
                pl[0] = pack_h2(el[0], el[1]); pl[1] = pack_h2(el[2], el[3]);
                pl[2] = pack_h2(el[4], el[5]); pl[3] = pack_h2(el[6], el[7]);
            }
#pragma unroll
            for (int nt2 = 0; nt2 < 4; nt2++) {
                MMA16816(of[2 * nt2],     ph, bv[nt2][0], bv[nt2][1]);
                MMA16816(of[2 * nt2 + 1], ph, bv[nt2][2], bv[nt2][3]);
                MMA16816(of[2 * nt2],     pl, bv[nt2][0], bv[nt2][1]);
                MMA16816(of[2 * nt2 + 1], pl, bv[nt2][2], bv[nt2][3]);
            }
        }
    }

    if (mode != 0) {
        {
            int row = tid >> 1, hf = tid & 1;
            int t_loc = t0 + row;
            int krow = n * 512 + 512 + t_loc;
            const float* kr = k + ((size_t)bh * TGT + krow) * HDIM + hf * 32;
            const float* qr2 = qb + row * 64 + hf * 32;
            float dot = 0.f;
#pragma unroll
            for (int j = 0; j < 8; j++) {
                float4 qa = *(const float4*)(qr2 + j * 4);
                float4 ka = *(const float4*)(kr + j * 4);
                dot += qa.x * ka.x + qa.y * ka.y + qa.z * ka.z + qa.w * ka.w;
            }
            dot += __shfl_xor_sync(0xFFFFFFFFu, dot, 1);
            int bk = bkn[(size_t)t_loc * 1024 + 512 + t_loc];
            float L = dot + sm.relrow[row][bk];
            if (!hf) sm.Ld[row] = L;
        }
        __syncthreads();
#pragma unroll
        for (int rh = 0; rh < 2; rh++) {
            int rl = wid * 16 + qr + rh * 8;
            int t_loc = t0 + rl;
            float L = sm.Ld[rl];
            float mnew = fmaxf(m_i[rh], L);
            float al = __expf(m_i[rh] - mnew);
            float p = __expf(L - mnew);
            l_i[rh] = l_i[rh] * al + p;
            m_i[rh] = mnew;
            const float* vr = v + ((size_t)bh * TGT + n * 512 + 512 + t_loc) * HDIM + qc * 2;
#pragma unroll
            for (int nt = 0; nt < 8; nt++) {
                float2 v2 = *(const float2*)(vr + nt * 8);
                of[nt][rh * 2]     = of[nt][rh * 2]     * al + p * v2.x;
                of[nt][rh * 2 + 1] = of[nt][rh * 2 + 1] * al + p * v2.y;
            }
        }
    }

#pragma unroll
    for (int rh = 0; rh < 2; rh++) {
        int rl = wid * 16 + qr + rh * 8;
        float inv = 1.0f / l_i[rh];
        float* cb = ctx + ((size_t)(grow0 + rl) * 4 + b) * EDIM + h * 64 + qc * 2;
#pragma unroll
        for (int nt = 0; nt < 8; nt++)
            *(float2*)(cb + nt * 8) = make_float2(of[nt][rh * 2] * inv,
                                                  of[nt][rh * 2 + 1] * inv);
    }
}

// ---------------- launch -----------------------------------------------------
extern "C" void kernel_launch(void* const* d_in, const int* in_sizes, int n_in,
                              void* d_out, int out_size)
{
    const float* hidden = (const float*)d_in[0];
    const float* w_in   = (const float*)d_in[1];
    const float* b_in   = (const float*)d_in[2];
    const float* rel_w  = (const float*)d_in[3];
    const float* rel_b  = (const float*)d_in[4];
    const float* out_w  = (const float*)d_in[5];
    const float* out_b  = (const float*)d_in[6];
    const int* bkm = (const int*)d_in[9];
    const int* bkn = (const int*)d_in[10];
    float* out = (float*)d_out;

    float *qp, *kp, *vp, *rv, *ctx;
    __half *A2, *Wqkv2, *Wrel2, *Wout2;
    cudaGetSymbolAddress((void**)&qp,  g_q);
    cudaGetSymbolAddress((void**)&kp,  g_k);
    cudaGetSymbolAddress((void**)&vp,  g_v);
    cudaGetSymbolAddress((void**)&rv,  g_relvals);
    cudaGetSymbolAddress((void**)&ctx, g_ctx);
    cudaGetSymbolAddress((void**)&A2,    g_A2);
    cudaGetSymbolAddress((void**)&Wqkv2, g_Wqkv2);
    cudaGetSymbolAddress((void**)&Wrel2, g_Wrel2);
    cudaGetSymbolAddress((void**)&Wout2, g_Wout2);

    cudaFuncSetAttribute(gemm_mma, cudaFuncAttributeMaxDynamicSharedMemorySize, GEMM_SMEM);
    cudaFuncSetAttribute(attn_tc, cudaFuncAttributeMaxDynamicSharedMemorySize,
                         (int)sizeof(AttnTc));

    // 0) fused conversion: hidden split + 3 weight casts in one launch
    convert_all<<<10752, 256>>>(hidden, w_in, rel_w, out_w, A2, Wqkv2, Wrel2, Wout2);

    // 1) QKV projection
    gemm_mma<<<dim3(3072 / 128, ROWS_ALL / 128), 256, GEMM_SMEM>>>(
        A2, Wqkv2, b_in, nullptr, 3072, 32, 1, qp, kp, vp);

    // 2) rel values (hi-only K=1024)
    gemm_mma<<<dim3(512 / 128, ROWS_ALL / 128), 256, GEMM_SMEM>>>(
        A2, Wrel2, rel_b, rv, 512, 16, 0, nullptr, nullptr, nullptr);

    // 3) tensor-core flash attention
    attn_tc<<<dim3(8, 64, 3), 128, sizeof(AttnTc)>>>(qp, kp, vp, rv, bkm, bkn, ctx);

    // 4) output projection
    convert_act<<<ROWS_ALL, 256>>>(ctx, A2);
    gemm_mma<<<dim3(1024 / 128, ROWS_ALL / 128), 256, GEMM_SMEM>>>(
        A2, Wout2, out_b, out, 1024, 32, 0, nullptr, nullptr, nullptr);
}

// round 13
// speedup vs baseline: 1.5404x; 1.0248x over previous
#include <cuda_runtime.h>
#include <cuda_fp16.h>
#include <cstdint>
#include <cstddef>

// Problem constants
#define TLEN   512
#define BATCH  4
#define HEADS  16
#define HDIM   64
#define EDIM   1024
#define ROWS_ALL 6144          // (1+NGRAM)*T * B
#define BH     64
#define TGT    1536
#define KA     2048            // activation split-K (fp16 [hi|lo])
#define KB     1024            // weight K (fp16 hi only)

// ---------------- scratch (static device globals; no allocation) -------------
__device__ float g_q[(size_t)BH * TGT * HDIM];
__device__ __half g_kh[(size_t)BH * TGT * HDIM];     // fp16 K (hi)
__device__ __half g_vh[(size_t)BH * TGT * HDIM];     // fp16 V (hi)
__device__ float g_relvals[(size_t)ROWS_ALL * 512];
__device__ float g_ctx[(size_t)ROWS_ALL * EDIM];
__device__ __half g_A2[(size_t)ROWS_ALL * KA];       // [hi|lo] activations
__device__ __half g_Wqkv2[(size_t)3072 * KB];
__device__ __half g_Wrel2[(size_t)512 * KB];
__device__ __half g_Wout2[(size_t)1024 * KB];

__device__ __forceinline__ uint32_t smem_u32(const void* p) {
    uint32_t a;
    asm("{ .reg .u64 t; cvta.to.shared.u64 t, %1; cvt.u32.u64 %0, t; }" : "=r"(a) : "l"(p));
    return a;
}
__device__ __forceinline__ uint32_t pack_h2(__half a, __half b) {
    __half2 t = __halves2half2(a, b);
    return *reinterpret_cast<uint32_t*>(&t);
}

// ---------------- conversions --------------------------------------------------
__global__ __launch_bounds__(256)
void convert_act(const float* __restrict__ src, __half* __restrict__ dst)
{
    int i4 = (blockIdx.x * blockDim.x + threadIdx.x) * 4;
    float4 a = *(const float4*)(src + i4);
    int r = i4 >> 10, k = i4 & 1023;
    size_t base = (size_t)r * KA + k;
    float av[4] = {a.x, a.y, a.z, a.w};
    __half h[4], l[4];
#pragma unroll
    for (int j = 0; j < 4; j++) {
        h[j] = __float2half_rn(av[j]);
        l[j] = __float2half_rn(av[j] - __half2float(h[j]));
    }
    *(__half2*)(dst + base + 0) = __halves2half2(h[0], h[1]);
    *(__half2*)(dst + base + 2) = __halves2half2(h[2], h[3]);
    *(__half2*)(dst + base + 1024) = __halves2half2(l[0], l[1]);
    *(__half2*)(dst + base + 1026) = __halves2half2(l[2], l[3]);
}

// fused first-round conversion (hidden split + 3 weight casts)
__global__ __launch_bounds__(256)
void convert_all(const float* __restrict__ hidden, const float* __restrict__ w_in,
                 const float* __restrict__ rel_w, const float* __restrict__ out_w,
                 __half* __restrict__ A2, __half* __restrict__ Wq,
                 __half* __restrict__ Wr, __half* __restrict__ Wo)
{
    int bid = blockIdx.x;
    if (bid < 6144) {
        int i4 = (bid * 256 + threadIdx.x) * 4;
        float4 a = *(const float4*)(hidden + i4);
        int r = i4 >> 10, k = i4 & 1023;
        size_t base = (size_t)r * KA + k;
        float av[4] = {a.x, a.y, a.z, a.w};
        __half h[4], l[4];
#pragma unroll
        for (int j = 0; j < 4; j++) {
            h[j] = __float2half_rn(av[j]);
            l[j] = __float2half_rn(av[j] - __half2float(h[j]));
        }
        *(__half2*)(A2 + base + 0) = __halves2half2(h[0], h[1]);
        *(__half2*)(A2 + base + 2) = __halves2half2(h[2], h[3]);
        *(__half2*)(A2 + base + 1024) = __halves2half2(l[0], l[1]);
        *(__half2*)(A2 + base + 1026) = __halves2half2(l[2], l[3]);
    } else {
        const float* src; __half* dst; int rb;
        if (bid < 9216)      { src = w_in;  dst = Wq; rb = bid - 6144; }
        else if (bid < 9728) { src = rel_w; dst = Wr; rb = bid - 9216; }
        else                 { src = out_w; dst = Wo; rb = bid - 9728; }
        int i4 = (rb * 256 + threadIdx.x) * 4;
        float4 a = *(const float4*)(src + i4);
        *(__half2*)(dst + i4 + 0) = __halves2half2(__float2half_rn(a.x), __float2half_rn(a.y));
        *(__half2*)(dst + i4 + 2) = __halves2half2(__float2half_rn(a.z), __float2half_rn(a.w));
    }
}

// ---------------- mma.sync fp16 GEMM ------------------------------------------
#define GSTAGES 3
#define STAGE_BYTES 16384
#define SMEM_A 0
#define SMEM_B (GSTAGES * STAGE_BYTES)
#define GEMM_SMEM (2 * GSTAGES * STAGE_BYTES)   // 96 KB

#define LOAD_STAGE(ld) do {                                                    \
        int _s = (ld) % 3;                                                     \
        uint32_t _ab = sb + SMEM_A + _s * STAGE_BYTES;                         \
        uint32_t _bb = sb + SMEM_B + _s * STAGE_BYTES;                         \
        const __half* _ag = Ab + (ld) * 64;                                    \
        const __half* _bg = Bb + ((ld) & 15) * 64;                             \
        _Pragma("unroll")                                                      \
        for (int _c = 0; _c < 4; _c++) {                                       \
            int _chunk = tid + _c * 256;                                       \
            int _row = _chunk >> 3, _c16 = _chunk & 7;                         \
            uint32_t _off = (uint32_t)(_row * 128 + _c16 * 16);                \
            _off ^= ((_off >> 3) & 0x70);                                      \
            asm volatile("cp.async.cg.shared.global [%0], [%1], 16;"           \
                :: "r"(_ab + _off), "l"(_ag + (size_t)_row * KA + _c16 * 8));  \
            asm volatile("cp.async.cg.shared.global [%0], [%1], 16;"           \
                :: "r"(_bb + _off), "l"(_bg + (size_t)_row * KB + _c16 * 8));  \
        }                                                                      \
        asm volatile("cp.async.commit_group;");                                \
    } while (0)

#define LDSM_X4(f, addr)                                                       \
    asm volatile("ldmatrix.sync.aligned.m8n8.x4.shared.b16 {%0,%1,%2,%3}, [%4];" \
        : "=r"((f)[0]), "=r"((f)[1]), "=r"((f)[2]), "=r"((f)[3]) : "r"(addr))

#define LDSM_X4T(f, addr)                                                      \
    asm volatile("ldmatrix.sync.aligned.m8n8.x4.trans.shared.b16 {%0,%1,%2,%3}, [%4];" \
        : "=r"((f)[0]), "=r"((f)[1]), "=r"((f)[2]), "=r"((f)[3]) : "r"(addr))

#define MMA16816(d, a, b0, b1)                                                 \
    asm volatile("mma.sync.aligned.m16n8k16.row.col.f32.f16.f16.f32 "          \
        "{%0,%1,%2,%3}, {%4,%5,%6,%7}, {%8,%9}, {%0,%1,%2,%3};"                \
        : "+f"((d)[0]), "+f"((d)[1]), "+f"((d)[2]), "+f"((d)[3])               \
        : "r"((a)[0]), "r"((a)[1]), "r"((a)[2]), "r"((a)[3]),                  \
          "r"(b0), "r"(b1))

#define LOAD_FRAGS(ks) do {                                                    \
        _Pragma("unroll")                                                      \
        for (int _mt = 0; _mt < 2; _mt++)                                      \
            LDSM_X4(af[_mt], aB + aRowByte[_mt] +                              \
                    ((uint32_t)(((ks) * 2 + achunk)) ^ xa) * 16u);             \
        _Pragma("unroll")                                                      \
        for (int _nt2 = 0; _nt2 < 4; _nt2++)                                   \
            LDSM_X4(bf[_nt2], bB + bRowByte[_nt2] +                            \
                    ((uint32_t)(((ks) * 2 + bchunk)) ^ xb) * 16u);             \
    } while (0)

__global__ __launch_bounds__(256, 2)
void gemm_mma(const __half* __restrict__ A, const __half* __restrict__ B,
              const float* __restrict__ bias, float* __restrict__ C,
              int N, int nkit, int qkv_mode,
              float* __restrict__ qp, __half* __restrict__ khp, __half* __restrict__ vhp)
{
    extern __shared__ char smraw[];
    uint32_t sb = smem_u32(smraw);
    const int tid = threadIdx.x;
    const int wid = tid >> 5, lane = tid & 31;
    const int wm = wid & 3, wn = wid >> 2;
    const int bn = blockIdx.x, bm = blockIdx.y;
    const __half* Ab = A + (size_t)bm * 128 * KA;
    const __half* Bb = B + (size_t)bn * 128 * KB;

    float acc[2][8][4];
#pragma unroll
    for (int i = 0; i < 2; i++)
#pragma unroll
        for (int j = 0; j < 8; j++)
#pragma unroll
            for (int c = 0; c < 4; c++) acc[i][j][c] = 0.f;

    const int g = lane >> 3, r = lane & 7;
    const int rowA = wm * 32 + (g & 1) * 8 + r;
    const int achunk = (g >> 1);
    const uint32_t xa = (uint32_t)(rowA & 7);
    uint32_t aRowByte[2];
#pragma unroll
    for (int mt = 0; mt < 2; mt++) aRowByte[mt] = (uint32_t)((rowA + mt * 16) * 128);
    const int rowB = wn * 64 + (g >> 1) * 8 + r;
    const int bchunk = (g & 1);
    const uint32_t xb = (uint32_t)(rowB & 7);
    uint32_t bRowByte[4];
#pragma unroll
    for (int nt2 = 0; nt2 < 4; nt2++) bRowByte[nt2] = (uint32_t)((rowB + nt2 * 16) * 128);

    LOAD_STAGE(0); LOAD_STAGE(1);

    uint32_t af[2][4];
    uint32_t bf[4][4];

    for (int it = 0; it < nkit; it++) {
        if (it + 1 < nkit) asm volatile("cp.async.wait_group 1;");
        else               asm volatile("cp.async.wait_group 0;");
        __syncthreads();
        if (it + 2 < nkit) LOAD_STAGE(it + 2);

        const uint32_t aB = sb + SMEM_A + (uint32_t)((it % 3) * STAGE_BYTES);
        const uint32_t bB = sb + SMEM_B + (uint32_t)((it % 3) * STAGE_BYTES);
#pragma unroll
        for (int ks = 0; ks < 4; ks++) {
            LOAD_FRAGS(ks);
#pragma unroll
            for (int mt = 0; mt < 2; mt++)
#pragma unroll
                for (int nt = 0; nt < 8; nt++) {
                    const uint32_t* bp = bf[nt >> 1];
                    int o = (nt & 1) * 2;
                    MMA16816(acc[mt][nt], af[mt], bp[o], bp[o + 1]);
                }
        }
    }

    const int mrow0 = bm * 128 + wm * 32 + (lane >> 2);
    const int colb  = bn * 128 + wn * 64;
    if (!qkv_mode) {
#pragma unroll
        for (int mt = 0; mt < 2; mt++)
#pragma unroll
            for (int nt = 0; nt < 8; nt++) {
                int col = colb + nt * 8 + (lane & 3) * 2;
                float2 b2 = *(const float2*)&bias[col];
                int row = mrow0 + mt * 16;
                *(float2*)&C[(size_t)row * N + col] =
                    make_float2(acc[mt][nt][0] + b2.x, acc[mt][nt][1] + b2.y);
                *(float2*)&C[(size_t)(row + 8) * N + col] =
                    make_float2(acc[mt][nt][2] + b2.x, acc[mt][nt][3] + b2.y);
            }
    } else {
        const int which = colb >> 10;
        const int hh = (colb >> 6) & 15;
        if (which == 0) {
            // Q: fp32, pre-scaled by d^-0.5
#pragma unroll
            for (int mt = 0; mt < 2; mt++)
#pragma unroll
                for (int nt = 0; nt < 8; nt++) {
                    int dd = nt * 8 + (lane & 3) * 2;
                    float2 b2 = *(const float2*)&bias[colb + dd];
#pragma unroll
                    for (int half = 0; half < 2; half++) {
                        int row = mrow0 + mt * 16 + half * 8;
                        int t = row >> 2, b3 = row & 3;
                        float* basep = qp + ((size_t)((b3 << 4) + hh) * TGT + t) * HDIM + dd;
                        *(float2*)basep = make_float2(
                            (acc[mt][nt][half * 2 + 0] + b2.x) * 0.125f,
                            (acc[mt][nt][half * 2 + 1] + b2.y) * 0.125f);
                    }
                }
        } else {
            // K/V: fp16 hi (exactly what the attention MMAs consume)
            __half* dsth = (which == 1) ? khp : vhp;
#pragma unroll
            for (int mt = 0; mt < 2; mt++)
#pragma unroll
                for (int nt = 0; nt < 8; nt++) {
                    int dd = nt * 8 + (lane & 3) * 2;
                    float2 b2 = *(const float2*)&bias[colb + dd];
#pragma unroll
                    for (int half = 0; half < 2; half++) {
                        int row = mrow0 + mt * 16 + half * 8;
                        int t = row >> 2, b3 = row & 3;
                        __half* basep = dsth + ((size_t)((b3 << 4) + hh) * TGT + t) * HDIM + dd;
                        *(__half2*)basep = __halves2half2(
                            __float2half_rn(acc[mt][nt][half * 2 + 0] + b2.x),
                            __float2half_rn(acc[mt][nt][half * 2 + 1] + b2.y));
                    }
                }
        }
    }
}

// ---------------- tensor-core flash attention ---------------------------------
// K/V arrive pre-converted fp16; chunk fill is pure cp.async, double-buffered.
struct AttnTc {
    __half qh[4096];
    __half ql[4096];
    __half kh[2][4096];
    __half vh[2][4096];
    float relrow[64][32];
    float Ld[64];
};

#define LOAD_KV(ci, buf) do {                                                  \
        const __half* _kg = kg + (size_t)(ci) * 64 * HDIM;                     \
        const __half* _vg = vg + (size_t)(ci) * 64 * HDIM;                     \
        uint32_t _kb = kh_base + (uint32_t)(buf) * 8192u;                      \
        uint32_t _vb = vh_base + (uint32_t)(buf) * 8192u;                      \
        _Pragma("unroll")                                                      \
        for (int _c = 0; _c < 4; _c++) {                                       \
            int _ch = tid + _c * 128;                                          \
            int _row = _ch >> 3, _c16 = _ch & 7;                               \
            uint32_t _off = (uint32_t)(_row * 128 + ((_c16 ^ (_row & 7)) * 16)); \
            asm volatile("cp.async.cg.shared.global [%0], [%1], 16;"           \
                :: "r"(_kb + _off), "l"(_kg + _row * 64 + _c16 * 8));          \
            asm volatile("cp.async.cg.shared.global [%0], [%1], 16;"           \
                :: "r"(_vb + _off), "l"(_vg + _row * 64 + _c16 * 8));          \
        }                                                                      \
        asm volatile("cp.async.commit_group;");                                \
    } while (0)

__global__ __launch_bounds__(128)
void attn_tc(const float* __restrict__ q, const __half* __restrict__ kh,
             const __half* __restrict__ vh, const float* __restrict__ relvals,
             const int* __restrict__ bkm, const int* __restrict__ bkn,
             float* __restrict__ ctx)
{
    extern __shared__ char smraw[];
    AttnTc& sm = *reinterpret_cast<AttnTc*>(smraw);
    const int qt = blockIdx.x, bh = blockIdx.y, mode = blockIdx.z;
    const int b = bh >> 4, h = bh & 15;
    const int tid = threadIdx.x, wid = tid >> 5, lane = tid & 31;
    const int t0 = qt * 64, n = mode - 1, grow0 = mode * 512 + t0;
    const int qr = lane >> 2, qc = lane & 3;
    const int g = lane >> 3, r8 = lane & 7;

    const uint32_t kh_base = smem_u32(sm.kh), vh_base = smem_u32(sm.vh);
    const __half* kg = kh + (size_t)bh * TGT * HDIM;   // main rows 0..511
    const __half* vg = vh + (size_t)bh * TGT * HDIM;
    const int nloop = qt + 1;

    // prefetch chunk 0 immediately
    LOAD_KV(0, 0);

    // ---- load Q (split hi/lo) and relrow ----
    const float* qb = q + ((size_t)bh * TGT + grow0) * HDIM;
    for (int i = tid; i < 512; i += 128) {
        int row = i >> 3, c = i & 7;
        const float* src = qb + row * 64 + c * 8;
        float4 x0 = *(const float4*)src, x1 = *(const float4*)(src + 4);
        float xs[8] = {x0.x, x0.y, x0.z, x0.w, x1.x, x1.y, x1.z, x1.w};
        __half hh[8], ll[8];
#pragma unroll
        for (int j = 0; j < 8; j++) {
            hh[j] = __float2half_rn(xs[j]);
            ll[j] = __float2half_rn(xs[j] - __half2float(hh[j]));
        }
        int idx = row * 64 + ((c ^ (row & 7)) << 3);
        uint4 hv, lv;
        hv.x = pack_h2(hh[0], hh[1]); hv.y = pack_h2(hh[2], hh[3]);
        hv.z = pack_h2(hh[4], hh[5]); hv.w = pack_h2(hh[6], hh[7]);
        lv.x = pack_h2(ll[0], ll[1]); lv.y = pack_h2(ll[2], ll[3]);
        lv.z = pack_h2(ll[4], ll[5]); lv.w = pack_h2(ll[6], ll[7]);
        *(uint4*)&sm.qh[idx] = hv;
        *(uint4*)&sm.ql[idx] = lv;
    }
    for (int idx = tid; idx < 2048; idx += 128) {
        int i = idx >> 5, nb = idx & 31;
        sm.relrow[i][nb] = relvals[((size_t)(grow0 + i) * 4 + b) * 512 + nb * 16 + h];
    }
    __syncthreads();

    const uint32_t qh_base = smem_u32(sm.qh), ql_base = smem_u32(sm.ql);
    const int arow = wid * 16 + (g & 1) * 8 + r8;
    const int achunk = g >> 1;
    uint32_t afh[4][4], afl[4][4];
#pragma unroll
    for (int ks = 0; ks < 4; ks++) {
        uint32_t off = (uint32_t)(arow * 128 + (((ks * 2 + achunk) ^ (arow & 7)) * 16));
        LDSM_X4(afh[ks], qh_base + off);
        LDSM_X4(afl[ks], ql_base + off);
    }

    const int brow8 = (g >> 1) * 8 + r8;
    const int bchunk = g & 1;
    const int vrow8 = (g & 1) * 8 + r8;
    const int vdo = g >> 1;

    float m_i[2] = {-1e30f, -1e30f}, l_i[2] = {0.f, 0.f};
    float of[8][4];
#pragma unroll
    for (int nt = 0; nt < 8; nt++)
#pragma unroll
        for (int c = 0; c < 4; c++) of[nt][c] = 0.f;

    const int bstride = (mode == 0) ? 512 : 1024;
    const int* bkp = (mode == 0) ? bkm : bkn;

    for (int ci = 0; ci < nloop; ci++) {
        const int s0 = ci * 64;
        if (ci + 1 < nloop) {
            LOAD_KV(ci + 1, (ci + 1) & 1);
            asm volatile("cp.async.wait_group 1;");
        } else {
            asm volatile("cp.async.wait_group 0;");
        }
        __syncthreads();
        const uint32_t kbase = kh_base + (uint32_t)(ci & 1) * 8192u;
        const uint32_t vbase = vh_base + (uint32_t)(ci & 1) * 8192u;

        // ---- S = [qhi|qlo] @ khi^T ----
        float sacc[8][4];
#pragma unroll
        for (int nt = 0; nt < 8; nt++)
#pragma unroll
            for (int c = 0; c < 4; c++) sacc[nt][c] = 0.f;
#pragma unroll
        for (int ks = 0; ks < 4; ks++) {
            uint32_t bq[4][4];
#pragma unroll
            for (int nt2 = 0; nt2 < 4; nt2++) {
                int krow = nt2 * 16 + brow8;
                uint32_t off = (uint32_t)(krow * 128 + (((ks * 2 + bchunk) ^ (krow & 7)) * 16));
                LDSM_X4(bq[nt2], kbase + off);
            }
#pragma unroll
            for (int nt2 = 0; nt2 < 4; nt2++) {
                MMA16816(sacc[2 * nt2],     afh[ks], bq[nt2][0], bq[nt2][1]);
                MMA16816(sacc[2 * nt2 + 1], afh[ks], bq[nt2][2], bq[nt2][3]);
                MMA16816(sacc[2 * nt2],     afl[ks], bq[nt2][0], bq[nt2][1]);
                MMA16816(sacc[2 * nt2 + 1], afl[ks], bq[nt2][2], bq[nt2][3]);
            }
        }

        // ---- rel + mask ----
#pragma unroll
        for (int rh = 0; rh < 2; rh++) {
            int rl = wid * 16 + qr + rh * 8;
            int t_loc = t0 + rl;
            const int* bkrow = bkp + (size_t)t_loc * bstride + s0 + qc * 2;
#pragma unroll
            for (int nt = 0; nt < 8; nt++) {
                int2 bk2 = *(const int2*)(bkrow + nt * 8);
                int sg = s0 + nt * 8 + qc * 2;
                sacc[nt][rh * 2 + 0] += sm.relrow[rl][bk2.x] + ((sg     <= t_loc) ? 0.f : -10000.f);
                sacc[nt][rh * 2 + 1] += sm.relrow[rl][bk2.y] + ((sg + 1 <= t_loc) ? 0.f : -10000.f);
            }
        }

        // ---- online softmax ----
#pragma unroll
        for (int rh = 0; rh < 2; rh++) {
            float mc = -1e30f;
#pragma unroll
            for (int nt = 0; nt < 8; nt++) {
                mc = fmaxf(mc, sacc[nt][rh * 2]);
                mc = fmaxf(mc, sacc[nt][rh * 2 + 1]);
            }
            mc = fmaxf(mc, __shfl_xor_sync(0xFFFFFFFFu, mc, 1));
            mc = fmaxf(mc, __shfl_xor_sync(0xFFFFFFFFu, mc, 2));
            float mnew = fmaxf(m_i[rh], mc);
            float al = __expf(m_i[rh] - mnew);
            float ls = 0.f;
#pragma unroll
            for (int nt = 0; nt < 8; nt++) {
                float e0 = __expf(sacc[nt][rh * 2]     - mnew);
                float e1 = __expf(sacc[nt][rh * 2 + 1] - mnew);
                sacc[nt][rh * 2] = e0; sacc[nt][rh * 2 + 1] = e1;
                ls += e0 + e1;
            }
            ls += __shfl_xor_sync(0xFFFFFFFFu, ls, 1);
            ls += __shfl_xor_sync(0xFFFFFFFFu, ls, 2);
            l_i[rh] = l_i[rh] * al + ls;
            m_i[rh] = mnew;
#pragma unroll
            for (int nt = 0; nt < 8; nt++) {
                of[nt][rh * 2] *= al; of[nt][rh * 2 + 1] *= al;
            }
        }

        // ---- O += [Phi|Plo] @ vhi ----
#pragma unroll
        for (int ks = 0; ks < 4; ks++) {
            uint32_t bv[4][4];
#pragma unroll
            for (int nt2 = 0; nt2 < 4; nt2++) {
                int srow = ks * 16 + vrow8;
                int dchunk = nt2 * 2 + vdo;
                uint32_t off = (uint32_t)(srow * 128 + ((dchunk ^ (srow & 7)) * 16));
                LDSM_X4T(bv[nt2], vbase + off);
            }
            uint32_t ph[4], pl[4];
            {
                float e[8] = {sacc[2*ks][0], sacc[2*ks][1], sacc[2*ks][2], sacc[2*ks][3],
                              sacc[2*ks+1][0], sacc[2*ks+1][1], sacc[2*ks+1][2], sacc[2*ks+1][3]};
                __half eh[8], el[8];
#pragma unroll
                for (int j = 0; j < 8; j++) {
                    eh[j] = __float2half_rn(e[j]);
                    el[j] = __float2half_rn(e[j] - __half2float(eh[j]));
                }
                ph[0] = pack_h2(eh[0], eh[1]); ph[1] = pack_h2(eh[2], eh[3]);
                ph[2] = pack_h2(eh[4], eh[5]); ph[3] = pack_h2(eh[6], eh[7]);
                pl[0] = pack_h2(el[0], el[1]); pl[1] = pack_h2(el[2], el[3]);
                pl[2] = pack_h2(el[4], el[5]); pl[3] = pack_h2(el[6], el[7]);
            }
#pragma unroll
            for (int nt2 = 0; nt2 < 4; nt2++) {
                MMA16816(of[2 * nt2],     ph, bv[nt2][0], bv[nt2][1]);
                MMA16816(of[2 * nt2 + 1], ph, bv[nt2][2], bv[nt2][3]);
                MMA16816(of[2 * nt2],     pl, bv[nt2][0], bv[nt2][1]);
                MMA16816(of[2 * nt2 + 1], pl, bv[nt2][2], bv[nt2][3]);
            }
        }
        __syncthreads();   // buffer (ci&1) free for prefetch of ci+2
    }

    // ---- analytic ngram diagonal (fp16 k/v — consistent with MMA precision) ----
    if (mode != 0) {
        {
            int row = tid >> 1, hf = tid & 1;
            int t_loc = t0 + row;
            int krow = n * 512 + 512 + t_loc;
            const __half* kr = kh + ((size_t)bh * TGT + krow) * HDIM + hf * 32;
            const float* qr2 = qb + row * 64 + hf * 32;
            float dot = 0.f;
#pragma unroll
            for (int j = 0; j < 16; j++) {
                float2 q2 = *(const float2*)(qr2 + j * 2);
                float2 kf = __half22float2(*(const __half2*)(kr + j * 2));
                dot += q2.x * kf.x + q2.y * kf.y;
            }
            dot += __shfl_xor_sync(0xFFFFFFFFu, dot, 1);
            int bk = bkn[(size_t)t_loc * 1024 + 512 + t_loc];
            float L = dot + sm.relrow[row][bk];
            if (!hf) sm.Ld[row] = L;
        }
        __syncthreads();
#pragma unroll
        for (int rh = 0; rh < 2; rh++) {
            int rl = wid * 16 + qr + rh * 8;
            int t_loc = t0 + rl;
            float L = sm.Ld[rl];
            float mnew = fmaxf(m_i[rh], L);
            float al = __expf(m_i[rh] - mnew);
            float p = __expf(L - mnew);
            l_i[rh] = l_i[rh] * al + p;
            m_i[rh] = mnew;
            const __half* vr = vh + ((size_t)bh * TGT + n * 512 + 512 + t_loc) * HDIM + qc * 2;
#pragma unroll
            for (int nt = 0; nt < 8; nt++) {
                float2 v2 = __half22float2(*(const __half2*)(vr + nt * 8));
                of[nt][rh * 2]     = of[nt][rh * 2]     * al + p * v2.x;
                of[nt][rh * 2 + 1] = of[nt][rh * 2 + 1] * al + p * v2.y;
            }
        }
    }

    // ---- epilogue: normalize + write fp32 ctx (coalesced) ----
#pragma unroll
    for (int rh = 0; rh < 2; rh++) {
        int rl = wid * 16 + qr + rh * 8;
        float inv = 1.0f / l_i[rh];
        float* cb = ctx + ((size_t)(grow0 + rl) * 4 + b) * EDIM + h * 64 + qc * 2;
#pragma unroll
        for (int nt = 0; nt < 8; nt++)
            *(float2*)(cb + nt * 8) = make_float2(of[nt][rh * 2] * inv,
                                                  of[nt][rh * 2 + 1] * inv);
    }
}

// ---------------- launch -----------------------------------------------------
extern "C" void kernel_launch(void* const* d_in, const int* in_sizes, int n_in,
                              void* d_out, int out_size)
{
    const float* hidden = (const float*)d_in[0];
    const float* w_in   = (const float*)d_in[1];
    const float* b_in   = (const float*)d_in[2];
    const float* rel_w  = (const float*)d_in[3];
    const float* rel_b  = (const float*)d_in[4];
    const float* out_w  = (const float*)d_in[5];
    const float* out_b  = (const float*)d_in[6];
    const int* bkm = (const int*)d_in[9];
    const int* bkn = (const int*)d_in[10];
    float* out = (float*)d_out;

    float *qp, *rv, *ctx;
    __half *khp, *vhp, *A2, *Wqkv2, *Wrel2, *Wout2;
    cudaGetSymbolAddress((void**)&qp,  g_q);
    cudaGetSymbolAddress((void**)&khp, g_kh);
    cudaGetSymbolAddress((void**)&vhp, g_vh);
    cudaGetSymbolAddress((void**)&rv,  g_relvals);
    cudaGetSymbolAddress((void**)&ctx, g_ctx);
    cudaGetSymbolAddress((void**)&A2,    g_A2);
    cudaGetSymbolAddress((void**)&Wqkv2, g_Wqkv2);
    cudaGetSymbolAddress((void**)&Wrel2, g_Wrel2);
    cudaGetSymbolAddress((void**)&Wout2, g_Wout2);

    cudaFuncSetAttribute(gemm_mma, cudaFuncAttributeMaxDynamicSharedMemorySize, GEMM_SMEM);
    cudaFuncSetAttribute(attn_tc, cudaFuncAttributeMaxDynamicSharedMemorySize,
                         (int)sizeof(AttnTc));

    // 0) fused conversion
    convert_all<<<10752, 256>>>(hidden, w_in, rel_w, out_w, A2, Wqkv2, Wrel2, Wout2);

    // 1) QKV projection (q fp32 scaled; k/v stored fp16)
    gemm_mma<<<dim3(3072 / 128, ROWS_ALL / 128), 256, GEMM_SMEM>>>(
        A2, Wqkv2, b_in, nullptr, 3072, 32, 1, qp, khp, vhp);

    // 2) rel values (hi-only K=1024)
    gemm_mma<<<dim3(512 / 128, ROWS_ALL / 128), 256, GEMM_SMEM>>>(
        A2, Wrel2, rel_b, rv, 512, 16, 0, nullptr, nullptr, nullptr);

    // 3) tensor-core flash attention (cp.async fp16 K/V, double-buffered)
    attn_tc<<<dim3(8, 64, 3), 128, sizeof(AttnTc)>>>(qp, khp, vhp, rv, bkm, bkn, ctx);

    // 4) output projection
    convert_act<<<ROWS_ALL, 256>>>(ctx, A2);
    gemm_mma<<<dim3(1024 / 128, ROWS_ALL / 128), 256, GEMM_SMEM>>>(
        A2, Wout2, out_b, out, 1024, 32, 0, nullptr, nullptr, nullptr);
}

// round 14
// speedup vs baseline: 1.6308x; 1.0587x over previous
#include <cuda_runtime.h>
#include <cuda_fp16.h>
#include <cstdint>
#include <cstddef>

// Problem constants
#define TLEN   512
#define BATCH  4
#define HEADS  16
#define HDIM   64
#define EDIM   1024
#define ROWS_ALL 6144          // (1+NGRAM)*T * B
#define BH     64
#define TGT    1536
#define KA     2048            // activation split-K (fp16 [hi|lo])
#define KB     1024            // weight K (fp16 hi only)

// ---------------- scratch (static device globals; no allocation) -------------
__device__ float g_q[(size_t)BH * TGT * HDIM];
__device__ __half g_kh[(size_t)BH * TGT * HDIM];     // fp16 K (hi)
__device__ __half g_vh[(size_t)BH * TGT * HDIM];     // fp16 V (hi)
__device__ float g_relvals[(size_t)ROWS_ALL * 512];
__device__ float g_ctx[(size_t)ROWS_ALL * EDIM];
__device__ __half g_A2[(size_t)ROWS_ALL * KA];       // [hi|lo] activations
__device__ __half g_Wqkv2[(size_t)3072 * KB];
__device__ __half g_Wrel2[(size_t)512 * KB];
__device__ __half g_Wout2[(size_t)1024 * KB];

__device__ __forceinline__ uint32_t smem_u32(const void* p) {
    uint32_t a;
    asm("{ .reg .u64 t; cvta.to.shared.u64 t, %1; cvt.u32.u64 %0, t; }" : "=r"(a) : "l"(p));
    return a;
}
__device__ __forceinline__ uint32_t pack_h2(__half a, __half b) {
    __half2 t = __halves2half2(a, b);
    return *reinterpret_cast<uint32_t*>(&t);
}

// ---------------- conversions --------------------------------------------------
__global__ __launch_bounds__(256)
void convert_act(const float* __restrict__ src, __half* __restrict__ dst)
{
    int i4 = (blockIdx.x * blockDim.x + threadIdx.x) * 4;
    float4 a = *(const float4*)(src + i4);
    int r = i4 >> 10, k = i4 & 1023;
    size_t base = (size_t)r * KA + k;
    float av[4] = {a.x, a.y, a.z, a.w};
    __half h[4], l[4];
#pragma unroll
    for (int j = 0; j < 4; j++) {
        h[j] = __float2half_rn(av[j]);
        l[j] = __float2half_rn(av[j] - __half2float(h[j]));
    }
    *(__half2*)(dst + base + 0) = __halves2half2(h[0], h[1]);
    *(__half2*)(dst + base + 2) = __halves2half2(h[2], h[3]);
    *(__half2*)(dst + base + 1024) = __halves2half2(l[0], l[1]);
    *(__half2*)(dst + base + 1026) = __halves2half2(l[2], l[3]);
}

// fused first-round conversion (hidden split + 3 weight casts)
__global__ __launch_bounds__(256)
void convert_all(const float* __restrict__ hidden, const float* __restrict__ w_in,
                 const float* __restrict__ rel_w, const float* __restrict__ out_w,
                 __half* __restrict__ A2, __half* __restrict__ Wq,
                 __half* __restrict__ Wr, __half* __restrict__ Wo)
{
    int bid = blockIdx.x;
    if (bid < 6144) {
        int i4 = (bid * 256 + threadIdx.x) * 4;
        float4 a = *(const float4*)(hidden + i4);
        int r = i4 >> 10, k = i4 & 1023;
        size_t base = (size_t)r * KA + k;
        float av[4] = {a.x, a.y, a.z, a.w};
        __half h[4], l[4];
#pragma unroll
        for (int j = 0; j < 4; j++) {
            h[j] = __float2half_rn(av[j]);
            l[j] = __float2half_rn(av[j] - __half2float(h[j]));
        }
        *(__half2*)(A2 + base + 0) = __halves2half2(h[0], h[1]);
        *(__half2*)(A2 + base + 2) = __halves2half2(h[2], h[3]);
        *(__half2*)(A2 + base + 1024) = __halves2half2(l[0], l[1]);
        *(__half2*)(A2 + base + 1026) = __halves2half2(l[2], l[3]);
    } else {
        const float* src; __half* dst; int rb;
        if (bid < 9216)      { src = w_in;  dst = Wq; rb = bid - 6144; }
        else if (bid < 9728) { src = rel_w; dst = Wr; rb = bid - 9216; }
        else                 { src = out_w; dst = Wo; rb = bid - 9728; }
        int i4 = (rb * 256 + threadIdx.x) * 4;
        float4 a = *(const float4*)(src + i4);
        *(__half2*)(dst + i4 + 0) = __halves2half2(__float2half_rn(a.x), __float2half_rn(a.y));
        *(__half2*)(dst + i4 + 2) = __halves2half2(__float2half_rn(a.z), __float2half_rn(a.w));
    }
}

// ---------------- mma.sync fp16 GEMM ------------------------------------------
#define GSTAGES 3
#define STAGE_BYTES 16384
#define SMEM_A 0
#define SMEM_B (GSTAGES * STAGE_BYTES)
#define GEMM_SMEM (2 * GSTAGES * STAGE_BYTES)   // 96 KB

#define LOAD_STAGE(ld) do {                                                    \
        int _s = (ld) % 3;                                                     \
        uint32_t _ab = sb + SMEM_A + _s * STAGE_BYTES;                         \
        uint32_t _bb = sb + SMEM_B + _s * STAGE_BYTES;                         \
        const __half* _ag = Ab + (ld) * 64;                                    \
        const __half* _bg = Bb + ((ld) & 15) * 64;                             \
        _Pragma("unroll")                                                      \
        for (int _c = 0; _c < 4; _c++) {                                       \
            int _chunk = tid + _c * 256;                                       \
            int _row = _chunk >> 3, _c16 = _chunk & 7;                         \
            uint32_t _off = (uint32_t)(_row * 128 + _c16 * 16);                \
            _off ^= ((_off >> 3) & 0x70);                                      \
            asm volatile("cp.async.cg.shared.global [%0], [%1], 16;"           \
                :: "r"(_ab + _off), "l"(_ag + (size_t)_row * KA + _c16 * 8));  \
            asm volatile("cp.async.cg.shared.global [%0], [%1], 16;"           \
                :: "r"(_bb + _off), "l"(_bg + (size_t)_row * KB + _c16 * 8));  \
        }                                                                      \
        asm volatile("cp.async.commit_group;");                                \
    } while (0)

#define LDSM_X4(f, addr)                                                       \
    asm volatile("ldmatrix.sync.aligned.m8n8.x4.shared.b16 {%0,%1,%2,%3}, [%4];" \
        : "=r"((f)[0]), "=r"((f)[1]), "=r"((f)[2]), "=r"((f)[3]) : "r"(addr))

#define LDSM_X4T(f, addr)                                                      \
    asm volatile("ldmatrix.sync.aligned.m8n8.x4.trans.shared.b16 {%0,%1,%2,%3}, [%4];" \
        : "=r"((f)[0]), "=r"((f)[1]), "=r"((f)[2]), "=r"((f)[3]) : "r"(addr))

#define MMA16816(d, a, b0, b1)                                                 \
    asm volatile("mma.sync.aligned.m16n8k16.row.col.f32.f16.f16.f32 "          \
        "{%0,%1,%2,%3}, {%4,%5,%6,%7}, {%8,%9}, {%0,%1,%2,%3};"                \
        : "+f"((d)[0]), "+f"((d)[1]), "+f"((d)[2]), "+f"((d)[3])               \
        : "r"((a)[0]), "r"((a)[1]), "r"((a)[2]), "r"((a)[3]),                  \
          "r"(b0), "r"(b1))

#define LOAD_FRAGS(ks) do {                                                    \
        _Pragma("unroll")                                                      \
        for (int _mt = 0; _mt < 2; _mt++)                                      \
            LDSM_X4(af[_mt], aB + aRowByte[_mt] +                              \
                    ((uint32_t)(((ks) * 2 + achunk)) ^ xa) * 16u);             \
        _Pragma("unroll")                                                      \
        for (int _nt2 = 0; _nt2 < 4; _nt2++)                                   \
            LDSM_X4(bf[_nt2], bB + bRowByte[_nt2] +                            \
                    ((uint32_t)(((ks) * 2 + bchunk)) ^ xb) * 16u);             \
    } while (0)

__global__ __launch_bounds__(256, 2)
void gemm_mma(const __half* __restrict__ A, const __half* __restrict__ B,
              const float* __restrict__ bias, float* __restrict__ C,
              int N, int nkit, int qkv_mode,
              float* __restrict__ qp, __half* __restrict__ khp, __half* __restrict__ vhp)
{
    extern __shared__ char smraw[];
    uint32_t sb = smem_u32(smraw);
    const int tid = threadIdx.x;
    const int wid = tid >> 5, lane = tid & 31;
    const int wm = wid & 3, wn = wid >> 2;
    const int bn = blockIdx.x, bm = blockIdx.y;
    const __half* Ab = A + (size_t)bm * 128 * KA;
    const __half* Bb = B + (size_t)bn * 128 * KB;

    float acc[2][8][4];
#pragma unroll
    for (int i = 0; i < 2; i++)
#pragma unroll
        for (int j = 0; j < 8; j++)
#pragma unroll
            for (int c = 0; c < 4; c++) acc[i][j][c] = 0.f;

    const int g = lane >> 3, r = lane & 7;
    const int rowA = wm * 32 + (g & 1) * 8 + r;
    const int achunk = (g >> 1);
    const uint32_t xa = (uint32_t)(rowA & 7);
    uint32_t aRowByte[2];
#pragma unroll
    for (int mt = 0; mt < 2; mt++) aRowByte[mt] = (uint32_t)((rowA + mt * 16) * 128);
    const int rowB = wn * 64 + (g >> 1) * 8 + r;
    const int bchunk = (g & 1);
    const uint32_t xb = (uint32_t)(rowB & 7);
    uint32_t bRowByte[4];
#pragma unroll
    for (int nt2 = 0; nt2 < 4; nt2++) bRowByte[nt2] = (uint32_t)((rowB + nt2 * 16) * 128);

    LOAD_STAGE(0); LOAD_STAGE(1);

    uint32_t af[2][4];
    uint32_t bf[4][4];

    for (int it = 0; it < nkit; it++) {
        if (it + 1 < nkit) asm volatile("cp.async.wait_group 1;");
        else               asm volatile("cp.async.wait_group 0;");
        __syncthreads();
        if (it + 2 < nkit) LOAD_STAGE(it + 2);

        const uint32_t aB = sb + SMEM_A + (uint32_t)((it % 3) * STAGE_BYTES);
        const uint32_t bB = sb + SMEM_B + (uint32_t)((it % 3) * STAGE_BYTES);
#pragma unroll
        for (int ks = 0; ks < 4; ks++) {
            LOAD_FRAGS(ks);
#pragma unroll
            for (int mt = 0; mt < 2; mt++)
#pragma unroll
                for (int nt = 0; nt < 8; nt++) {
                    const uint32_t* bp = bf[nt >> 1];
                    int o = (nt & 1) * 2;
                    MMA16816(acc[mt][nt], af[mt], bp[o], bp[o + 1]);
                }
        }
    }

    const int mrow0 = bm * 128 + wm * 32 + (lane >> 2);
    const int colb  = bn * 128 + wn * 64;
    if (!qkv_mode) {
#pragma unroll
        for (int mt = 0; mt < 2; mt++)
#pragma unroll
            for (int nt = 0; nt < 8; nt++) {
                int col = colb + nt * 8 + (lane & 3) * 2;
                float2 b2 = *(const float2*)&bias[col];
                int row = mrow0 + mt * 16;
                *(float2*)&C[(size_t)row * N + col] =
                    make_float2(acc[mt][nt][0] + b2.x, acc[mt][nt][1] + b2.y);
                *(float2*)&C[(size_t)(row + 8) * N + col] =
                    make_float2(acc[mt][nt][2] + b2.x, acc[mt][nt][3] + b2.y);
            }
    } else {
        const int which = colb >> 10;
        const int hh = (colb >> 6) & 15;
        if (which == 0) {
#pragma unroll
            for (int mt = 0; mt < 2; mt++)
#pragma unroll
                for (int nt = 0; nt < 8; nt++) {
                    int dd = nt * 8 + (lane & 3) * 2;
                    float2 b2 = *(const float2*)&bias[colb + dd];
#pragma unroll
                    for (int half = 0; half < 2; half++) {
                        int row = mrow0 + mt * 16 + half * 8;
                        int t = row >> 2, b3 = row & 3;
                        float* basep = qp + ((size_t)((b3 << 4) + hh) * TGT + t) * HDIM + dd;
                        *(float2*)basep = make_float2(
                            (acc[mt][nt][half * 2 + 0] + b2.x) * 0.125f,
                            (acc[mt][nt][half * 2 + 1] + b2.y) * 0.125f);
                    }
                }
        } else {
            __half* dsth = (which == 1) ? khp : vhp;
#pragma unroll
            for (int mt = 0; mt < 2; mt++)
#pragma unroll
                for (int nt = 0; nt < 8; nt++) {
                    int dd = nt * 8 + (lane & 3) * 2;
                    float2 b2 = *(const float2*)&bias[colb + dd];
#pragma unroll
                    for (int half = 0; half < 2; half++) {
                        int row = mrow0 + mt * 16 + half * 8;
                        int t = row >> 2, b3 = row & 3;
                        __half* basep = dsth + ((size_t)((b3 << 4) + hh) * TGT + t) * HDIM + dd;
                        *(__half2*)basep = __halves2half2(
                            __float2half_rn(acc[mt][nt][half * 2 + 0] + b2.x),
                            __float2half_rn(acc[mt][nt][half * 2 + 1] + b2.y));
                    }
                }
        }
    }
}

// ---------------- tensor-core flash attention ---------------------------------
// Buckets depend only on (t - s): 512-entry smem LUT replaces the global
// gather (masked entries use lut[0]; -10000 underflows to 0 either way).
struct AttnTc {
    __half qh[4096];
    __half ql[4096];
    __half kh[2][4096];
    __half vh[2][4096];
    float relrow[64][32];
    float Ld[64];
    int lut[512];
};

#define LOAD_KV(ci, buf) do {                                                  \
        const __half* _kg = kg + (size_t)(ci) * 64 * HDIM;                     \
        const __half* _vg = vg + (size_t)(ci) * 64 * HDIM;                     \
        uint32_t _kb = kh_base + (uint32_t)(buf) * 8192u;                      \
        uint32_t _vb = vh_base + (uint32_t)(buf) * 8192u;                      \
        _Pragma("unroll")                                                      \
        for (int _c = 0; _c < 4; _c++) {                                       \
            int _ch = tid + _c * 128;                                          \
            int _row = _ch >> 3, _c16 = _ch & 7;                               \
            uint32_t _off = (uint32_t)(_row * 128 + ((_c16 ^ (_row & 7)) * 16)); \
            asm volatile("cp.async.cg.shared.global [%0], [%1], 16;"           \
                :: "r"(_kb + _off), "l"(_kg + _row * 64 + _c16 * 8));          \
            asm volatile("cp.async.cg.shared.global [%0], [%1], 16;"           \
                :: "r"(_vb + _off), "l"(_vg + _row * 64 + _c16 * 8));          \
        }                                                                      \
        asm volatile("cp.async.commit_group;");                                \
    } while (0)

__global__ __launch_bounds__(128)
void attn_tc(const float* __restrict__ q, const __half* __restrict__ kh,
             const __half* __restrict__ vh, const float* __restrict__ relvals,
             const int* __restrict__ bkm, const int* __restrict__ bkn,
             float* __restrict__ ctx)
{
    extern __shared__ char smraw[];
    AttnTc& sm = *reinterpret_cast<AttnTc*>(smraw);
    const int qt = 7 - blockIdx.x;            // biggest tiles first
    const int bh = blockIdx.y, mode = blockIdx.z;
    const int b = bh >> 4, h = bh & 15;
    const int tid = threadIdx.x, wid = tid >> 5, lane = tid & 31;
    const int t0 = qt * 64, n = mode - 1, grow0 = mode * 512 + t0;
    const int qr = lane >> 2, qc = lane & 3;
    const int g = lane >> 3, r8 = lane & 7;

    const uint32_t kh_base = smem_u32(sm.kh), vh_base = smem_u32(sm.vh);
    const __half* kg = kh + (size_t)bh * TGT * HDIM;
    const __half* vg = vh + (size_t)bh * TGT * HDIM;
    const int nloop = qt + 1;

    LOAD_KV(0, 0);

    // 1-D bucket LUT: lut[d] = bucket row 511, col 511-d
    {
        const int* lutsrc = (mode == 0) ? (bkm + (size_t)511 * 512 + 511)
                                        : (bkn + (size_t)511 * 1024 + 511);
        for (int d = tid; d < 512; d += 128) sm.lut[d] = lutsrc[-d];
    }

    // ---- load Q (split hi/lo) and relrow ----
    const float* qb = q + ((size_t)bh * TGT + grow0) * HDIM;
    for (int i = tid; i < 512; i += 128) {
        int row = i >> 3, c = i & 7;
        const float* src = qb + row * 64 + c * 8;
        float4 x0 = *(const float4*)src, x1 = *(const float4*)(src + 4);
        float xs[8] = {x0.x, x0.y, x0.z, x0.w, x1.x, x1.y, x1.z, x1.w};
        __half hh[8], ll[8];
#pragma unroll
        for (int j = 0; j < 8; j++) {
            hh[j] = __float2half_rn(xs[j]);
            ll[j] = __float2half_rn(xs[j] - __half2float(hh[j]));
        }
        int idx = row * 64 + ((c ^ (row & 7)) << 3);
        uint4 hv, lv;
        hv.x = pack_h2(hh[0], hh[1]); hv.y = pack_h2(hh[2], hh[3]);
        hv.z = pack_h2(hh[4], hh[5]); hv.w = pack_h2(hh[6], hh[7]);
        lv.x = pack_h2(ll[0], ll[1]); lv.y = pack_h2(ll[2], ll[3]);
        lv.z = pack_h2(ll[4], ll[5]); lv.w = pack_h2(ll[6], ll[7]);
        *(uint4*)&sm.qh[idx] = hv;
        *(uint4*)&sm.ql[idx] = lv;
    }
    for (int idx = tid; idx < 2048; idx += 128) {
        int i = idx >> 5, nb = idx & 31;
        sm.relrow[i][nb] = relvals[((size_t)(grow0 + i) * 4 + b) * 512 + nb * 16 + h];
    }
    __syncthreads();

    const uint32_t qh_base = smem_u32(sm.qh), ql_base = smem_u32(sm.ql);
    const int arow = wid * 16 + (g & 1) * 8 + r8;
    const int achunk = g >> 1;
    uint32_t afh[4][4], afl[4][4];
#pragma unroll
    for (int ks = 0; ks < 4; ks++) {
        uint32_t off = (uint32_t)(arow * 128 + (((ks * 2 + achunk) ^ (arow & 7)) * 16));
        LDSM_X4(afh[ks], qh_base + off);
        LDSM_X4(afl[ks], ql_base + off);
    }

    const int brow8 = (g >> 1) * 8 + r8;
    const int bchunk = g & 1;
    const int vrow8 = (g & 1) * 8 + r8;
    const int vdo = g >> 1;

    float m_i[2] = {-1e30f, -1e30f}, l_i[2] = {0.f, 0.f};
    float of[8][4];
#pragma unroll
    for (int nt = 0; nt < 8; nt++)
#pragma unroll
        for (int c = 0; c < 4; c++) of[nt][c] = 0.f;

    for (int ci = 0; ci < nloop; ci++) {
        const int s0 = ci * 64;
        if (ci + 1 < nloop) {
            LOAD_KV(ci + 1, (ci + 1) & 1);
            asm volatile("cp.async.wait_group 1;");
        } else {
            asm volatile("cp.async.wait_group 0;");
        }
        __syncthreads();
        const uint32_t kbase = kh_base + (uint32_t)(ci & 1) * 8192u;
        const uint32_t vbase = vh_base + (uint32_t)(ci & 1) * 8192u;

        // ---- S = [qhi|qlo] @ khi^T ----
        float sacc[8][4];
#pragma unroll
        for (int nt = 0; nt < 8; nt++)
#pragma unroll
            for (int c = 0; c < 4; c++) sacc[nt][c] = 0.f;
#pragma unroll
        for (int ks = 0; ks < 4; ks++) {
            uint32_t bq[4][4];
#pragma unroll
            for (int nt2 = 0; nt2 < 4; nt2++) {
                int krow = nt2 * 16 + brow8;
                uint32_t off = (uint32_t)(krow * 128 + (((ks * 2 + bchunk) ^ (krow & 7)) * 16));
                LDSM_X4(bq[nt2], kbase + off);
            }
#pragma unroll
            for (int nt2 = 0; nt2 < 4; nt2++) {
                MMA16816(sacc[2 * nt2],     afh[ks], bq[nt2][0], bq[nt2][1]);
                MMA16816(sacc[2 * nt2 + 1], afh[ks], bq[nt2][2], bq[nt2][3]);
                MMA16816(sacc[2 * nt2],     afl[ks], bq[nt2][0], bq[nt2][1]);
                MMA16816(sacc[2 * nt2 + 1], afl[ks], bq[nt2][2], bq[nt2][3]);
            }
        }

        // ---- rel (smem LUT on t-s) + mask ----
#pragma unroll
        for (int rh = 0; rh < 2; rh++) {
            int rl = wid * 16 + qr + rh * 8;
            int t_loc = t0 + rl;
            int d0base = t_loc - (s0 + qc * 2);
#pragma unroll
            for (int nt = 0; nt < 8; nt++) {
                int d0 = d0base - nt * 8;
                int d1 = d0 - 1;
                int i0 = d0 < 0 ? 0 : d0;
                int i1 = d1 < 0 ? 0 : d1;
                sacc[nt][rh * 2 + 0] += sm.relrow[rl][sm.lut[i0]] + ((d0 >= 0) ? 0.f : -10000.f);
                sacc[nt][rh * 2 + 1] += sm.relrow[rl][sm.lut[i1]] + ((d1 >= 0) ? 0.f : -10000.f);
            }
        }

        // ---- online softmax ----
#pragma unroll
        for (int rh = 0; rh < 2; rh++) {
            float mc = -1e30f;
#pragma unroll
            for (int nt = 0; nt < 8; nt++) {
                mc = fmaxf(mc, sacc[nt][rh * 2]);
                mc = fmaxf(mc, sacc[nt][rh * 2 + 1]);
            }
            mc = fmaxf(mc, __shfl_xor_sync(0xFFFFFFFFu, mc, 1));
            mc = fmaxf(mc, __shfl_xor_sync(0xFFFFFFFFu, mc, 2));
            float mnew = fmaxf(m_i[rh], mc);
            float al = __expf(m_i[rh] - mnew);
            float ls = 0.f;
#pragma unroll
            for (int nt = 0; nt < 8; nt++) {
                float e0 = __expf(sacc[nt][rh * 2]     - mnew);
                float e1 = __expf(sacc[nt][rh * 2 + 1] - mnew);
                sacc[nt][rh * 2] = e0; sacc[nt][rh * 2 + 1] = e1;
                ls += e0 + e1;
            }
            ls += __shfl_xor_sync(0xFFFFFFFFu, ls, 1);
            ls += __shfl_xor_sync(0xFFFFFFFFu, ls, 2);
            l_i[rh] = l_i[rh] * al + ls;
            m_i[rh] = mnew;
#pragma unroll
            for (int nt = 0; nt < 8; nt++) {
                of[nt][rh * 2] *= al; of[nt][rh * 2 + 1] *= al;
            }
        }

        // ---- O += [Phi|Plo] @ vhi ----
#pragma unroll
        for (int ks = 0; ks < 4; ks++) {
            uint32_t bv[4][4];
#pragma unroll
            for (int nt2 = 0; nt2 < 4; nt2++) {
                int srow = ks * 16 + vrow8;
                int dchunk = nt2 * 2 + vdo;
                uint32_t off = (uint32_t)(srow * 128 + ((dchunk ^ (srow & 7)) * 16));
                LDSM_X4T(bv[nt2], vbase + off);
            }
            uint32_t ph[4], pl[4];
            {
                float e[8] = {sacc[2*ks][0], sacc[2*ks][1], sacc[2*ks][2], sacc[2*ks][3],
                              sacc[2*ks+1][0], sacc[2*ks+1][1], sacc[2*ks+1][2], sacc[2*ks+1][3]};
                __half eh[8], el[8];
#pragma unroll
                for (int j = 0; j < 8; j++) {
                    eh[j] = __float2half_rn(e[j]);
                    el[j] = __float2half_rn(e[j] - __half2float(eh[j]));
                }
                ph[0] = pack_h2(eh[0], eh[1]); ph[1] = pack_h2(eh[2], eh[3]);
                ph[2] = pack_h2(eh[4], eh[5]); ph[3] = pack_h2(eh[6], eh[7]);
                pl[0] = pack_h2(el[0], el[1]); pl[1] = pack_h2(el[2], el[3]);
                pl[2] = pack_h2(el[4], el[5]); pl[3] = pack_h2(el[6], el[7]);
            }
#pragma unroll
            for (int nt2 = 0; nt2 < 4; nt2++) {
                MMA16816(of[2 * nt2],     ph, bv[nt2][0], bv[nt2][1]);
                MMA16816(of[2 * nt2 + 1], ph, bv[nt2][2], bv[nt2][3]);
                MMA16816(of[2 * nt2],     pl, bv[nt2][0], bv[nt2][1]);
                MMA16816(of[2 * nt2 + 1], pl, bv[nt2][2], bv[nt2][3]);
            }
        }
        __syncthreads();
    }

    // ---- analytic ngram diagonal: bucket(0) == 0 ----
    if (mode != 0) {
        {
            int row = tid >> 1, hf = tid & 1;
            int t_loc = t0 + row;
            int krow = n * 512 + 512 + t_loc;
            const __half* kr = kh + ((size_t)bh * TGT + krow) * HDIM + hf * 32;
            const float* qr2 = qb + row * 64 + hf * 32;
            float dot = 0.f;
#pragma unroll
            for (int j = 0; j < 16; j++) {
                float2 q2 = *(const float2*)(qr2 + j * 2);
                float2 kf = __half22float2(*(const __half2*)(kr + j * 2));
                dot += q2.x * kf.x + q2.y * kf.y;
            }
            dot += __shfl_xor_sync(0xFFFFFFFFu, dot, 1);
            float L = dot + sm.relrow[row][0];   // bucket(0) = 0
            if (!hf) sm.Ld[row] = L;
        }
        __syncthreads();
#pragma unroll
        for (int rh = 0; rh < 2; rh++) {
            int rl = wid * 16 + qr + rh * 8;
            int t_loc = t0 + rl;
            float L = sm.Ld[rl];
            float mnew = fmaxf(m_i[rh], L);
            float al = __expf(m_i[rh] - mnew);
            float p = __expf(L - mnew);
            l_i[rh] = l_i[rh] * al + p;
            m_i[rh] = mnew;
            const __half* vr = vh + ((size_t)bh * TGT + n * 512 + 512 + t_loc) * HDIM + qc * 2;
#pragma unroll
            for (int nt = 0; nt < 8; nt++) {
                float2 v2 = __half22float2(*(const __half2*)(vr + nt * 8));
                of[nt][rh * 2]     = of[nt][rh * 2]     * al + p * v2.x;
                of[nt][rh * 2 + 1] = of[nt][rh * 2 + 1] * al + p * v2.y;
            }
        }
    }

    // ---- epilogue ----
#pragma unroll
    for (int rh = 0; rh < 2; rh++) {
        int rl = wid * 16 + qr + rh * 8;
        float inv = 1.0f / l_i[rh];
        float* cb = ctx + ((size_t)(grow0 + rl) * 4 + b) * EDIM + h * 64 + qc * 2;
#pragma unroll
        for (int nt = 0; nt < 8; nt++)
            *(float2*)(cb + nt * 8) = make_float2(of[nt][rh * 2] * inv,
                                                  of[nt][rh * 2 + 1] * inv);
    }
}

// ---------------- launch -----------------------------------------------------
extern "C" void kernel_launch(void* const* d_in, const int* in_sizes, int n_in,
                              void* d_out, int out_size)
{
    const float* hidden = (const float*)d_in[0];
    const float* w_in   = (const float*)d_in[1];
    const float* b_in   = (const float*)d_in[2];
    const float* rel_w  = (const float*)d_in[3];
    const float* rel_b  = (const float*)d_in[4];
    const float* out_w  = (const float*)d_in[5];
    const float* out_b  = (const float*)d_in[6];
    const int* bkm = (const int*)d_in[9];
    const int* bkn = (const int*)d_in[10];
    float* out = (float*)d_out;

    float *qp, *rv, *ctx;
    __half *khp, *vhp, *A2, *Wqkv2, *Wrel2, *Wout2;
    cudaGetSymbolAddress((void**)&qp,  g_q);
    cudaGetSymbolAddress((void**)&khp, g_kh);
    cudaGetSymbolAddress((void**)&vhp, g_vh);
    cudaGetSymbolAddress((void**)&rv,  g_relvals);
    cudaGetSymbolAddress((void**)&ctx, g_ctx);
    cudaGetSymbolAddress((void**)&A2,    g_A2);
    cudaGetSymbolAddress((void**)&Wqkv2, g_Wqkv2);
    cudaGetSymbolAddress((void**)&Wrel2, g_Wrel2);
    cudaGetSymbolAddress((void**)&Wout2, g_Wout2);

    cudaFuncSetAttribute(gemm_mma, cudaFuncAttributeMaxDynamicSharedMemorySize, GEMM_SMEM);
    cudaFuncSetAttribute(attn_tc, cudaFuncAttributeMaxDynamicSharedMemorySize,
                         (int)sizeof(AttnTc));

    // 0) fused conversion
    convert_all<<<10752, 256>>>(hidden, w_in, rel_w, out_w, A2, Wqkv2, Wrel2, Wout2);

    // 1) QKV projection (q fp32 scaled; k/v stored fp16)
    gemm_mma<<<dim3(3072 / 128, ROWS_ALL / 128), 256, GEMM_SMEM>>>(
        A2, Wqkv2, b_in, nullptr, 3072, 32, 1, qp, khp, vhp);

    // 2) rel values (hi-only K=1024)
    gemm_mma<<<dim3(512 / 128, ROWS_ALL / 128), 256, GEMM_SMEM>>>(
        A2, Wrel2, rel_b, rv, 512, 16, 0, nullptr, nullptr, nullptr);

    // 3) tensor-core flash attention (bucket LUT, big tiles first)
    attn_tc<<<dim3(8, 64, 3), 128, sizeof(AttnTc)>>>(qp, khp, vhp, rv, bkm, bkn, ctx);

    // 4) output projection
    convert_act<<<ROWS_ALL, 256>>>(ctx, A2);
    gemm_mma<<<dim3(1024 / 128, ROWS_ALL / 128), 256, GEMM_SMEM>>>(
        A2, Wout2, out_b, out, 1024, 32, 0, nullptr, nullptr, nullptr);
}

// round 15
// speedup vs baseline: 1.6516x; 1.0128x over previous
#include <cuda_runtime.h>
#include <cuda_fp16.h>
#include <cstdint>
#include <cstddef>

// Problem constants
#define TLEN   512
#define BATCH  4
#define HEADS  16
#define HDIM   64
#define EDIM   1024
#define ROWS_ALL 6144          // (1+NGRAM)*T * B
#define BH     64
#define TGT    1536
#define KA     2048            // activation split-K (fp16 [hi|lo])
#define KB     1024            // weight K (fp16 hi only)

// ---------------- scratch (static device globals; no allocation) -------------
__device__ float g_q[(size_t)BH * TGT * HDIM];
__device__ __half g_kh[(size_t)BH * TGT * HDIM];     // fp16 K (hi)
__device__ __half g_vh[(size_t)BH * TGT * HDIM];     // fp16 V (hi)
__device__ float g_relvals[(size_t)ROWS_ALL * 512];
__device__ float g_ctx[(size_t)ROWS_ALL * EDIM];
__device__ __half g_A2[(size_t)ROWS_ALL * KA];       // [hi|lo] activations
__device__ __half g_Wqkv2[(size_t)3072 * KB];
__device__ __half g_Wrel2[(size_t)512 * KB];
__device__ __half g_Wout2[(size_t)1024 * KB];

__device__ __forceinline__ uint32_t smem_u32(const void* p) {
    uint32_t a;
    asm("{ .reg .u64 t; cvta.to.shared.u64 t, %1; cvt.u32.u64 %0, t; }" : "=r"(a) : "l"(p));
    return a;
}
__device__ __forceinline__ uint32_t pack_h2(__half a, __half b) {
    __half2 t = __halves2half2(a, b);
    return *reinterpret_cast<uint32_t*>(&t);
}

// ---------------- conversions --------------------------------------------------
__global__ __launch_bounds__(256)
void convert_act(const float* __restrict__ src, __half* __restrict__ dst)
{
    int i4 = (blockIdx.x * blockDim.x + threadIdx.x) * 4;
    float4 a = *(const float4*)(src + i4);
    int r = i4 >> 10, k = i4 & 1023;
    size_t base = (size_t)r * KA + k;
    float av[4] = {a.x, a.y, a.z, a.w};
    __half h[4], l[4];
#pragma unroll
    for (int j = 0; j < 4; j++) {
        h[j] = __float2half_rn(av[j]);
        l[j] = __float2half_rn(av[j] - __half2float(h[j]));
    }
    *(__half2*)(dst + base + 0) = __halves2half2(h[0], h[1]);
    *(__half2*)(dst + base + 2) = __halves2half2(h[2], h[3]);
    *(__half2*)(dst + base + 1024) = __halves2half2(l[0], l[1]);
    *(__half2*)(dst + base + 1026) = __halves2half2(l[2], l[3]);
}

// fused first-round conversion (hidden split + 3 weight casts)
__global__ __launch_bounds__(256)
void convert_all(const float* __restrict__ hidden, const float* __restrict__ w_in,
                 const float* __restrict__ rel_w, const float* __restrict__ out_w,
                 __half* __restrict__ A2, __half* __restrict__ Wq,
                 __half* __restrict__ Wr, __half* __restrict__ Wo)
{
    int bid = blockIdx.x;
    if (bid < 6144) {
        int i4 = (bid * 256 + threadIdx.x) * 4;
        float4 a = *(const float4*)(hidden + i4);
        int r = i4 >> 10, k = i4 & 1023;
        size_t base = (size_t)r * KA + k;
        float av[4] = {a.x, a.y, a.z, a.w};
        __half h[4], l[4];
#pragma unroll
        for (int j = 0; j < 4; j++) {
            h[j] = __float2half_rn(av[j]);
            l[j] = __float2half_rn(av[j] - __half2float(h[j]));
        }
        *(__half2*)(A2 + base + 0) = __halves2half2(h[0], h[1]);
        *(__half2*)(A2 + base + 2) = __halves2half2(h[2], h[3]);
        *(__half2*)(A2 + base + 1024) = __halves2half2(l[0], l[1]);
        *(__half2*)(A2 + base + 1026) = __halves2half2(l[2], l[3]);
    } else {
        const float* src; __half* dst; int rb;
        if (bid < 9216)      { src = w_in;  dst = Wq; rb = bid - 6144; }
        else if (bid < 9728) { src = rel_w; dst = Wr; rb = bid - 9216; }
        else                 { src = out_w; dst = Wo; rb = bid - 9728; }
        int i4 = (rb * 256 + threadIdx.x) * 4;
        float4 a = *(const float4*)(src + i4);
        *(__half2*)(dst + i4 + 0) = __halves2half2(__float2half_rn(a.x), __float2half_rn(a.y));
        *(__half2*)(dst + i4 + 2) = __halves2half2(__float2half_rn(a.z), __float2half_rn(a.w));
    }
}

// ---------------- mma.sync fp16 GEMM ------------------------------------------
#define GSTAGES 3
#define STAGE_BYTES 16384
#define SMEM_A 0
#define SMEM_B (GSTAGES * STAGE_BYTES)
#define GEMM_SMEM (2 * GSTAGES * STAGE_BYTES)   // 96 KB

#define LOAD_STAGE(ld) do {                                                    \
        int _s = (ld) % 3;                                                     \
        uint32_t _ab = sb + SMEM_A + _s * STAGE_BYTES;                         \
        uint32_t _bb = sb + SMEM_B + _s * STAGE_BYTES;                         \
        const __half* _ag = Ab + (ld) * 64;                                    \
        const __half* _bg = Bb + ((ld) & 15) * 64;                             \
        _Pragma("unroll")                                                      \
        for (int _c = 0; _c < 4; _c++) {                                       \
            int _chunk = tid + _c * 256;                                       \
            int _row = _chunk >> 3, _c16 = _chunk & 7;                         \
            uint32_t _off = (uint32_t)(_row * 128 + _c16 * 16);                \
            _off ^= ((_off >> 3) & 0x70);                                      \
            asm volatile("cp.async.cg.shared.global [%0], [%1], 16;"           \
                :: "r"(_ab + _off), "l"(_ag + (size_t)_row * KA + _c16 * 8));  \
            asm volatile("cp.async.cg.shared.global [%0], [%1], 16;"           \
                :: "r"(_bb + _off), "l"(_bg + (size_t)_row * KB + _c16 * 8));  \
        }                                                                      \
        asm volatile("cp.async.commit_group;");                                \
    } while (0)

#define LDSM_X4(f, addr)                                                       \
    asm volatile("ldmatrix.sync.aligned.m8n8.x4.shared.b16 {%0,%1,%2,%3}, [%4];" \
        : "=r"((f)[0]), "=r"((f)[1]), "=r"((f)[2]), "=r"((f)[3]) : "r"(addr))

#define LDSM_X4T(f, addr)                                                      \
    asm volatile("ldmatrix.sync.aligned.m8n8.x4.trans.shared.b16 {%0,%1,%2,%3}, [%4];" \
        : "=r"((f)[0]), "=r"((f)[1]), "=r"((f)[2]), "=r"((f)[3]) : "r"(addr))

#define MMA16816(d, a, b0, b1)                                                 \
    asm volatile("mma.sync.aligned.m16n8k16.row.col.f32.f16.f16.f32 "          \
        "{%0,%1,%2,%3}, {%4,%5,%6,%7}, {%8,%9}, {%0,%1,%2,%3};"                \
        : "+f"((d)[0]), "+f"((d)[1]), "+f"((d)[2]), "+f"((d)[3])               \
        : "r"((a)[0]), "r"((a)[1]), "r"((a)[2]), "r"((a)[3]),                  \
          "r"(b0), "r"(b1))

#define LOAD_FRAGS(ks) do {                                                    \
        _Pragma("unroll")                                                      \
        for (int _mt = 0; _mt < 2; _mt++)                                      \
            LDSM_X4(af[_mt], aB + aRowByte[_mt] +                              \
                    ((uint32_t)(((ks) * 2 + achunk)) ^ xa) * 16u);             \
        _Pragma("unroll")                                                      \
        for (int _nt2 = 0; _nt2 < 4; _nt2++)                                   \
            LDSM_X4(bf[_nt2], bB + bRowByte[_nt2] +                            \
                    ((uint32_t)(((ks) * 2 + bchunk)) ^ xb) * 16u);             \
    } while (0)

__global__ __launch_bounds__(256, 2)
void gemm_mma(const __half* __restrict__ A, const __half* __restrict__ B,
              const float* __restrict__ bias, float* __restrict__ C,
              int N, int nkit, int qkv_mode,
              float* __restrict__ qp, __half* __restrict__ khp, __half* __restrict__ vhp)
{
    extern __shared__ char smraw[];
    uint32_t sb = smem_u32(smraw);
    const int tid = threadIdx.x;
    const int wid = tid >> 5, lane = tid & 31;
    const int wm = wid & 3, wn = wid >> 2;
    const int bn = blockIdx.x, bm = blockIdx.y;
    const __half* Ab = A + (size_t)bm * 128 * KA;
    const __half* Bb = B + (size_t)bn * 128 * KB;

    float acc[2][8][4];
#pragma unroll
    for (int i = 0; i < 2; i++)
#pragma unroll
        for (int j = 0; j < 8; j++)
#pragma unroll
            for (int c = 0; c < 4; c++) acc[i][j][c] = 0.f;

    const int g = lane >> 3, r = lane & 7;
    const int rowA = wm * 32 + (g & 1) * 8 + r;
    const int achunk = (g >> 1);
    const uint32_t xa = (uint32_t)(rowA & 7);
    uint32_t aRowByte[2];
#pragma unroll
    for (int mt = 0; mt < 2; mt++) aRowByte[mt] = (uint32_t)((rowA + mt * 16) * 128);
    const int rowB = wn * 64 + (g >> 1) * 8 + r;
    const int bchunk = (g & 1);
    const uint32_t xb = (uint32_t)(rowB & 7);
    uint32_t bRowByte[4];
#pragma unroll
    for (int nt2 = 0; nt2 < 4; nt2++) bRowByte[nt2] = (uint32_t)((rowB + nt2 * 16) * 128);

    LOAD_STAGE(0); LOAD_STAGE(1);

    uint32_t af[2][4];
    uint32_t bf[4][4];

    for (int it = 0; it < nkit; it++) {
        if (it + 1 < nkit) asm volatile("cp.async.wait_group 1;");
        else               asm volatile("cp.async.wait_group 0;");
        __syncthreads();
        if (it + 2 < nkit) LOAD_STAGE(it + 2);

        const uint32_t aB = sb + SMEM_A + (uint32_t)((it % 3) * STAGE_BYTES);
        const uint32_t bB = sb + SMEM_B + (uint32_t)((it % 3) * STAGE_BYTES);
#pragma unroll
        for (int ks = 0; ks < 4; ks++) {
            LOAD_FRAGS(ks);
#pragma unroll
            for (int mt = 0; mt < 2; mt++)
#pragma unroll
                for (int nt = 0; nt < 8; nt++) {
                    const uint32_t* bp = bf[nt >> 1];
                    int o = (nt & 1) * 2;
                    MMA16816(acc[mt][nt], af[mt], bp[o], bp[o + 1]);
                }
        }
    }

    const int mrow0 = bm * 128 + wm * 32 + (lane >> 2);
    const int colb  = bn * 128 + wn * 64;
    if (!qkv_mode) {
#pragma unroll
        for (int mt = 0; mt < 2; mt++)
#pragma unroll
            for (int nt = 0; nt < 8; nt++) {
                int col = colb + nt * 8 + (lane & 3) * 2;
                float2 b2 = *(const float2*)&bias[col];
                int row = mrow0 + mt * 16;
                *(float2*)&C[(size_t)row * N + col] =
                    make_float2(acc[mt][nt][0] + b2.x, acc[mt][nt][1] + b2.y);
                *(float2*)&C[(size_t)(row + 8) * N + col] =
                    make_float2(acc[mt][nt][2] + b2.x, acc[mt][nt][3] + b2.y);
            }
    } else {
        const int which = colb >> 10;
        const int hh = (colb >> 6) & 15;
        if (which == 0) {
#pragma unroll
            for (int mt = 0; mt < 2; mt++)
#pragma unroll
                for (int nt = 0; nt < 8; nt++) {
                    int dd = nt * 8 + (lane & 3) * 2;
                    float2 b2 = *(const float2*)&bias[colb + dd];
#pragma unroll
                    for (int half = 0; half < 2; half++) {
                        int row = mrow0 + mt * 16 + half * 8;
                        int t = row >> 2, b3 = row & 3;
                        float* basep = qp + ((size_t)((b3 << 4) + hh) * TGT + t) * HDIM + dd;
                        *(float2*)basep = make_float2(
                            (acc[mt][nt][half * 2 + 0] + b2.x) * 0.125f,
                            (acc[mt][nt][half * 2 + 1] + b2.y) * 0.125f);
                    }
                }
        } else {
            __half* dsth = (which == 1) ? khp : vhp;
#pragma unroll
            for (int mt = 0; mt < 2; mt++)
#pragma unroll
                for (int nt = 0; nt < 8; nt++) {
                    int dd = nt * 8 + (lane & 3) * 2;
                    float2 b2 = *(const float2*)&bias[colb + dd];
#pragma unroll
                    for (int half = 0; half < 2; half++) {
                        int row = mrow0 + mt * 16 + half * 8;
                        int t = row >> 2, b3 = row & 3;
                        __half* basep = dsth + ((size_t)((b3 << 4) + hh) * TGT + t) * HDIM + dd;
                        *(__half2*)basep = __halves2half2(
                            __float2half_rn(acc[mt][nt][half * 2 + 0] + b2.x),
                            __float2half_rn(acc[mt][nt][half * 2 + 1] + b2.y));
                    }
                }
        }
    }
}

// ---------------- tensor-core flash attention ---------------------------------
// Bucket LUT on (t-s); PV uses P-hi only (P in [0,1]; lo term ~2^-12 dropped).
struct AttnTc {
    __half qh[4096];
    __half ql[4096];
    __half kh[2][4096];
    __half vh[2][4096];
    float relrow[64][32];
    float Ld[64];
    int lut[512];
};

#define LOAD_KV(ci, buf) do {                                                  \
        const __half* _kg = kg + (size_t)(ci) * 64 * HDIM;                     \
        const __half* _vg = vg + (size_t)(ci) * 64 * HDIM;                     \
        uint32_t _kb = kh_base + (uint32_t)(buf) * 8192u;                      \
        uint32_t _vb = vh_base + (uint32_t)(buf) * 8192u;                      \
        _Pragma("unroll")                                                      \
        for (int _c = 0; _c < 4; _c++) {                                       \
            int _ch = tid + _c * 128;                                          \
            int _row = _ch >> 3, _c16 = _ch & 7;                               \
            uint32_t _off = (uint32_t)(_row * 128 + ((_c16 ^ (_row & 7)) * 16)); \
            asm volatile("cp.async.cg.shared.global [%0], [%1], 16;"           \
                :: "r"(_kb + _off), "l"(_kg + _row * 64 + _c16 * 8));          \
            asm volatile("cp.async.cg.shared.global [%0], [%1], 16;"           \
                :: "r"(_vb + _off), "l"(_vg + _row * 64 + _c16 * 8));          \
        }                                                                      \
        asm volatile("cp.async.commit_group;");                                \
    } while (0)

__global__ __launch_bounds__(128)
void attn_tc(const float* __restrict__ q, const __half* __restrict__ kh,
             const __half* __restrict__ vh, const float* __restrict__ relvals,
             const int* __restrict__ bkm, const int* __restrict__ bkn,
             float* __restrict__ ctx)
{
    extern __shared__ char smraw[];
    AttnTc& sm = *reinterpret_cast<AttnTc*>(smraw);
    const int qt = 7 - blockIdx.x;            // biggest tiles first
    const int bh = blockIdx.y, mode = blockIdx.z;
    const int b = bh >> 4, h = bh & 15;
    const int tid = threadIdx.x, wid = tid >> 5, lane = tid & 31;
    const int t0 = qt * 64, n = mode - 1, grow0 = mode * 512 + t0;
    const int qr = lane >> 2, qc = lane & 3;
    const int g = lane >> 3, r8 = lane & 7;

    const uint32_t kh_base = smem_u32(sm.kh), vh_base = smem_u32(sm.vh);
    const __half* kg = kh + (size_t)bh * TGT * HDIM;
    const __half* vg = vh + (size_t)bh * TGT * HDIM;
    const int nloop = qt + 1;

    LOAD_KV(0, 0);

    // 1-D bucket LUT: lut[d] = bucket row 511, col 511-d
    {
        const int* lutsrc = (mode == 0) ? (bkm + (size_t)511 * 512 + 511)
                                        : (bkn + (size_t)511 * 1024 + 511);
        for (int d = tid; d < 512; d += 128) sm.lut[d] = lutsrc[-d];
    }

    // ---- load Q (split hi/lo) and relrow ----
    const float* qb = q + ((size_t)bh * TGT + grow0) * HDIM;
    for (int i = tid; i < 512; i += 128) {
        int row = i >> 3, c = i & 7;
        const float* src = qb + row * 64 + c * 8;
        float4 x0 = *(const float4*)src, x1 = *(const float4*)(src + 4);
        float xs[8] = {x0.x, x0.y, x0.z, x0.w, x1.x, x1.y, x1.z, x1.w};
        __half hh[8], ll[8];
#pragma unroll
        for (int j = 0; j < 8; j++) {
            hh[j] = __float2half_rn(xs[j]);
            ll[j] = __float2half_rn(xs[j] - __half2float(hh[j]));
        }
        int idx = row * 64 + ((c ^ (row & 7)) << 3);
        uint4 hv, lv;
        hv.x = pack_h2(hh[0], hh[1]); hv.y = pack_h2(hh[2], hh[3]);
        hv.z = pack_h2(hh[4], hh[5]); hv.w = pack_h2(hh[6], hh[7]);
        lv.x = pack_h2(ll[0], ll[1]); lv.y = pack_h2(ll[2], ll[3]);
        lv.z = pack_h2(ll[4], ll[5]); lv.w = pack_h2(ll[6], ll[7]);
        *(uint4*)&sm.qh[idx] = hv;
        *(uint4*)&sm.ql[idx] = lv;
    }
    for (int idx = tid; idx < 2048; idx += 128) {
        int i = idx >> 5, nb = idx & 31;
        sm.relrow[i][nb] = relvals[((size_t)(grow0 + i) * 4 + b) * 512 + nb * 16 + h];
    }
    __syncthreads();

    const uint32_t qh_base = smem_u32(sm.qh), ql_base = smem_u32(sm.ql);
    const int arow = wid * 16 + (g & 1) * 8 + r8;
    const int achunk = g >> 1;
    uint32_t afh[4][4], afl[4][4];
#pragma unroll
    for (int ks = 0; ks < 4; ks++) {
        uint32_t off = (uint32_t)(arow * 128 + (((ks * 2 + achunk) ^ (arow & 7)) * 16));
        LDSM_X4(afh[ks], qh_base + off);
        LDSM_X4(afl[ks], ql_base + off);
    }

    const int brow8 = (g >> 1) * 8 + r8;
    const int bchunk = g & 1;
    const int vrow8 = (g & 1) * 8 + r8;
    const int vdo = g >> 1;

    float m_i[2] = {-1e30f, -1e30f}, l_i[2] = {0.f, 0.f};
    float of[8][4];
#pragma unroll
    for (int nt = 0; nt < 8; nt++)
#pragma unroll
        for (int c = 0; c < 4; c++) of[nt][c] = 0.f;

    for (int ci = 0; ci < nloop; ci++) {
        const int s0 = ci * 64;
        if (ci + 1 < nloop) {
            LOAD_KV(ci + 1, (ci + 1) & 1);
            asm volatile("cp.async.wait_group 1;");
        } else {
            asm volatile("cp.async.wait_group 0;");
        }
        __syncthreads();
        const uint32_t kbase = kh_base + (uint32_t)(ci & 1) * 8192u;
        const uint32_t vbase = vh_base + (uint32_t)(ci & 1) * 8192u;

        // ---- S = [qhi|qlo] @ khi^T ----
        float sacc[8][4];
#pragma unroll
        for (int nt = 0; nt < 8; nt++)
#pragma unroll
            for (int c = 0; c < 4; c++) sacc[nt][c] = 0.f;
#pragma unroll
        for (int ks = 0; ks < 4; ks++) {
            uint32_t bq[4][4];
#pragma unroll
            for (int nt2 = 0; nt2 < 4; nt2++) {
                int krow = nt2 * 16 + brow8;
                uint32_t off = (uint32_t)(krow * 128 + (((ks * 2 + bchunk) ^ (krow & 7)) * 16));
                LDSM_X4(bq[nt2], kbase + off);
            }
#pragma unroll
            for (int nt2 = 0; nt2 < 4; nt2++) {
                MMA16816(sacc[2 * nt2],     afh[ks], bq[nt2][0], bq[nt2][1]);
                MMA16816(sacc[2 * nt2 + 1], afh[ks], bq[nt2][2], bq[nt2][3]);
                MMA16816(sacc[2 * nt2],     afl[ks], bq[nt2][0], bq[nt2][1]);
                MMA16816(sacc[2 * nt2 + 1], afl[ks], bq[nt2][2], bq[nt2][3]);
            }
        }

        // ---- rel (smem LUT on t-s) + mask ----
#pragma unroll
        for (int rh = 0; rh < 2; rh++) {
            int rl = wid * 16 + qr + rh * 8;
            int t_loc = t0 + rl;
            int d0base = t_loc - (s0 + qc * 2);
#pragma unroll
            for (int nt = 0; nt < 8; nt++) {
                int d0 = d0base - nt * 8;
                int d1 = d0 - 1;
                int i0 = d0 < 0 ? 0 : d0;
                int i1 = d1 < 0 ? 0 : d1;
                sacc[nt][rh * 2 + 0] += sm.relrow[rl][sm.lut[i0]] + ((d0 >= 0) ? 0.f : -10000.f);
                sacc[nt][rh * 2 + 1] += sm.relrow[rl][sm.lut[i1]] + ((d1 >= 0) ? 0.f : -10000.f);
            }
        }

        // ---- online softmax ----
#pragma unroll
        for (int rh = 0; rh < 2; rh++) {
            float mc = -1e30f;
#pragma unroll
            for (int nt = 0; nt < 8; nt++) {
                mc = fmaxf(mc, sacc[nt][rh * 2]);
                mc = fmaxf(mc, sacc[nt][rh * 2 + 1]);
            }
            mc = fmaxf(mc, __shfl_xor_sync(0xFFFFFFFFu, mc, 1));
            mc = fmaxf(mc, __shfl_xor_sync(0xFFFFFFFFu, mc, 2));
            float mnew = fmaxf(m_i[rh], mc);
            float al = __expf(m_i[rh] - mnew);
            float ls = 0.f;
#pragma unroll
            for (int nt = 0; nt < 8; nt++) {
                float e0 = __expf(sacc[nt][rh * 2]     - mnew);
                float e1 = __expf(sacc[nt][rh * 2 + 1] - mnew);
                sacc[nt][rh * 2] = e0; sacc[nt][rh * 2 + 1] = e1;
                ls += e0 + e1;
            }
            ls += __shfl_xor_sync(0xFFFFFFFFu, ls, 1);
            ls += __shfl_xor_sync(0xFFFFFFFFu, ls, 2);
            l_i[rh] = l_i[rh] * al + ls;
            m_i[rh] = mnew;
#pragma unroll
            for (int nt = 0; nt < 8; nt++) {
                of[nt][rh * 2] *= al; of[nt][rh * 2 + 1] *= al;
            }
        }

        // ---- O += Phi @ vhi (P-lo dropped: |err| <= 2^-12 weighted by sum P = 1) ----
#pragma unroll
        for (int ks = 0; ks < 4; ks++) {
            uint32_t bv[4][4];
#pragma unroll
            for (int nt2 = 0; nt2 < 4; nt2++) {
                int srow = ks * 16 + vrow8;
                int dchunk = nt2 * 2 + vdo;
                uint32_t off = (uint32_t)(srow * 128 + ((dchunk ^ (srow & 7)) * 16));
                LDSM_X4T(bv[nt2], vbase + off);
            }
            uint32_t ph[4];
            {
                float e[8] = {sacc[2*ks][0], sacc[2*ks][1], sacc[2*ks][2], sacc[2*ks][3],
                              sacc[2*ks+1][0], sacc[2*ks+1][1], sacc[2*ks+1][2], sacc[2*ks+1][3]};
                ph[0] = pack_h2(__float2half_rn(e[0]), __float2half_rn(e[1]));
                ph[1] = pack_h2(__float2half_rn(e[2]), __float2half_rn(e[3]));
                ph[2] = pack_h2(__float2half_rn(e[4]), __float2half_rn(e[5]));
                ph[3] = pack_h2(__float2half_rn(e[6]), __float2half_rn(e[7]));
            }
#pragma unroll
            for (int nt2 = 0; nt2 < 4; nt2++) {
                MMA16816(of[2 * nt2],     ph, bv[nt2][0], bv[nt2][1]);
                MMA16816(of[2 * nt2 + 1], ph, bv[nt2][2], bv[nt2][3]);
            }
        }
        __syncthreads();
    }

    // ---- analytic ngram diagonal: bucket(0) == 0 ----
    if (mode != 0) {
        {
            int row = tid >> 1, hf = tid & 1;
            int t_loc = t0 + row;
            int krow = n * 512 + 512 + t_loc;
            const __half* kr = kh + ((size_t)bh * TGT + krow) * HDIM + hf * 32;
            const float* qr2 = qb + row * 64 + hf * 32;
            float dot = 0.f;
#pragma unroll
            for (int j = 0; j < 16; j++) {
                float2 q2 = *(const float2*)(qr2 + j * 2);
                float2 kf = __half22float2(*(const __half2*)(kr + j * 2));
                dot += q2.x * kf.x + q2.y * kf.y;
            }
            dot += __shfl_xor_sync(0xFFFFFFFFu, dot, 1);
            float L = dot + sm.relrow[row][0];   // bucket(0) = 0
            if (!hf) sm.Ld[row] = L;
        }
        __syncthreads();
#pragma unroll
        for (int rh = 0; rh < 2; rh++) {
            int rl = wid * 16 + qr + rh * 8;
            int t_loc = t0 + rl;
            float L = sm.Ld[rl];
            float mnew = fmaxf(m_i[rh], L);
            float al = __expf(m_i[rh] - mnew);
            float p = __expf(L - mnew);
            l_i[rh] = l_i[rh] * al + p;
            m_i[rh] = mnew;
            const __half* vr = vh + ((size_t)bh * TGT + n * 512 + 512 + t_loc) * HDIM + qc * 2;
#pragma unroll
            for (int nt = 0; nt < 8; nt++) {
                float2 v2 = __half22float2(*(const __half2*)(vr + nt * 8));
                of[nt][rh * 2]     = of[nt][rh * 2]     * al + p * v2.x;
                of[nt][rh * 2 + 1] = of[nt][rh * 2 + 1] * al + p * v2.y;
            }
        }
    }

    // ---- epilogue ----
#pragma unroll
    for (int rh = 0; rh < 2; rh++) {
        int rl = wid * 16 + qr + rh * 8;
        float inv = 1.0f / l_i[rh];
        float* cb = ctx + ((size_t)(grow0 + rl) * 4 + b) * EDIM + h * 64 + qc * 2;
#pragma unroll
        for (int nt = 0; nt < 8; nt++)
            *(float2*)(cb + nt * 8) = make_float2(of[nt][rh * 2] * inv,
                                                  of[nt][rh * 2 + 1] * inv);
    }
}

// ---------------- launch -----------------------------------------------------
extern "C" void kernel_launch(void* const* d_in, const int* in_sizes, int n_in,
                              void* d_out, int out_size)
{
    const float* hidden = (const float*)d_in[0];
    const float* w_in   = (const float*)d_in[1];
    const float* b_in   = (const float*)d_in[2];
    const float* rel_w  = (const float*)d_in[3];
    const float* rel_b  = (const float*)d_in[4];
    const float* out_w  = (const float*)d_in[5];
    const float* out_b  = (const float*)d_in[6];
    const int* bkm = (const int*)d_in[9];
    const int* bkn = (const int*)d_in[10];
    float* out = (float*)d_out;

    float *qp, *rv, *ctx;
    __half *khp, *vhp, *A2, *Wqkv2, *Wrel2, *Wout2;
    cudaGetSymbolAddress((void**)&qp,  g_q);
    cudaGetSymbolAddress((void**)&khp, g_kh);
    cudaGetSymbolAddress((void**)&vhp, g_vh);
    cudaGetSymbolAddress((void**)&rv,  g_relvals);
    cudaGetSymbolAddress((void**)&ctx, g_ctx);
    cudaGetSymbolAddress((void**)&A2,    g_A2);
    cudaGetSymbolAddress((void**)&Wqkv2, g_Wqkv2);
    cudaGetSymbolAddress((void**)&Wrel2, g_Wrel2);
    cudaGetSymbolAddress((void**)&Wout2, g_Wout2);

    cudaFuncSetAttribute(gemm_mma, cudaFuncAttributeMaxDynamicSharedMemorySize, GEMM_SMEM);
    cudaFuncSetAttribute(attn_tc, cudaFuncAttributeMaxDynamicSharedMemorySize,
                         (int)sizeof(AttnTc));

    // 0) fused conversion
    convert_all<<<10752, 256>>>(hidden, w_in, rel_w, out_w, A2, Wqkv2, Wrel2, Wout2);

    // 1) QKV projection (q fp32 scaled; k/v stored fp16)
    gemm_mma<<<dim3(3072 / 128, ROWS_ALL / 128), 256, GEMM_SMEM>>>(
        A2, Wqkv2, b_in, nullptr, 3072, 32, 1, qp, khp, vhp);

    // 2) rel values (hi-only K=1024)
    gemm_mma<<<dim3(512 / 128, ROWS_ALL / 128), 256, GEMM_SMEM>>>(
        A2, Wrel2, rel_b, rv, 512, 16, 0, nullptr, nullptr, nullptr);

    // 3) tensor-core flash attention (P-hi-only PV)
    attn_tc<<<dim3(8, 64, 3), 128, sizeof(AttnTc)>>>(qp, khp, vhp, rv, bkm, bkn, ctx);

    // 4) output projection
    convert_act<<<ROWS_ALL, 256>>>(ctx, A2);
    gemm_mma<<<dim3(1024 / 128, ROWS_ALL / 128), 256, GEMM_SMEM>>>(
        A2, Wout2, out_b, out, 1024, 32, 0, nullptr, nullptr, nullptr);
}

// round 16
// speedup vs baseline: 1.8386x; 1.1132x over previous
#include <cuda_runtime.h>
#include <cuda_fp16.h>
#include <cstdint>
#include <cstddef>

// Problem constants
#define TLEN   512
#define BATCH  4
#define HEADS  16
#define HDIM   64
#define EDIM   1024
#define ROWS_ALL 6144          // (1+NGRAM)*T * B
#define BH     64
#define TGT    1536
#define KA     2048            // activation split-K (fp16 [hi|lo])
#define KB     1024            // weight K (fp16 hi only)

// ---------------- scratch (static device globals; no allocation) -------------
__device__ float g_q[(size_t)BH * TGT * HDIM];
__device__ __half g_kh[(size_t)BH * TGT * HDIM];     // fp16 K (hi)
__device__ __half g_vh[(size_t)BH * TGT * HDIM];     // fp16 V (hi)
__device__ float g_relvals[(size_t)ROWS_ALL * 512];
__device__ float g_ctx[(size_t)ROWS_ALL * EDIM];
__device__ __half g_A2[(size_t)ROWS_ALL * KA];       // [hi|lo] activations
__device__ __half g_Wqkv2[(size_t)3072 * KB];
__device__ __half g_Wrel2[(size_t)512 * KB];
__device__ __half g_Wout2[(size_t)1024 * KB];

__device__ __forceinline__ uint32_t smem_u32(const void* p) {
    uint32_t a;
    asm("{ .reg .u64 t; cvta.to.shared.u64 t, %1; cvt.u32.u64 %0, t; }" : "=r"(a) : "l"(p));
    return a;
}
__device__ __forceinline__ uint32_t pack_h2(__half a, __half b) {
    __half2 t = __halves2half2(a, b);
    return *reinterpret_cast<uint32_t*>(&t);
}

// ---------------- conversions --------------------------------------------------
__global__ __launch_bounds__(256)
void convert_act(const float* __restrict__ src, __half* __restrict__ dst)
{
    int i4 = (blockIdx.x * blockDim.x + threadIdx.x) * 4;
    float4 a = *(const float4*)(src + i4);
    int r = i4 >> 10, k = i4 & 1023;
    size_t base = (size_t)r * KA + k;
    float av[4] = {a.x, a.y, a.z, a.w};
    __half h[4], l[4];
#pragma unroll
    for (int j = 0; j < 4; j++) {
        h[j] = __float2half_rn(av[j]);
        l[j] = __float2half_rn(av[j] - __half2float(h[j]));
    }
    *(__half2*)(dst + base + 0) = __halves2half2(h[0], h[1]);
    *(__half2*)(dst + base + 2) = __halves2half2(h[2], h[3]);
    *(__half2*)(dst + base + 1024) = __halves2half2(l[0], l[1]);
    *(__half2*)(dst + base + 1026) = __halves2half2(l[2], l[3]);
}

// fused first-round conversion (hidden split + 3 weight casts)
__global__ __launch_bounds__(256)
void convert_all(const float* __restrict__ hidden, const float* __restrict__ w_in,
                 const float* __restrict__ rel_w, const float* __restrict__ out_w,
                 __half* __restrict__ A2, __half* __restrict__ Wq,
                 __half* __restrict__ Wr, __half* __restrict__ Wo)
{
    int bid = blockIdx.x;
    if (bid < 6144) {
        int i4 = (bid * 256 + threadIdx.x) * 4;
        float4 a = *(const float4*)(hidden + i4);
        int r = i4 >> 10, k = i4 & 1023;
        size_t base = (size_t)r * KA + k;
        float av[4] = {a.x, a.y, a.z, a.w};
        __half h[4], l[4];
#pragma unroll
        for (int j = 0; j < 4; j++) {
            h[j] = __float2half_rn(av[j]);
            l[j] = __float2half_rn(av[j] - __half2float(h[j]));
        }
        *(__half2*)(A2 + base + 0) = __halves2half2(h[0], h[1]);
        *(__half2*)(A2 + base + 2) = __halves2half2(h[2], h[3]);
        *(__half2*)(A2 + base + 1024) = __halves2half2(l[0], l[1]);
        *(__half2*)(A2 + base + 1026) = __halves2half2(l[2], l[3]);
    } else {
        const float* src; __half* dst; int rb;
        if (bid < 9216)      { src = w_in;  dst = Wq; rb = bid - 6144; }
        else if (bid < 9728) { src = rel_w; dst = Wr; rb = bid - 9216; }
        else                 { src = out_w; dst = Wo; rb = bid - 9728; }
        int i4 = (rb * 256 + threadIdx.x) * 4;
        float4 a = *(const float4*)(src + i4);
        *(__half2*)(dst + i4 + 0) = __halves2half2(__float2half_rn(a.x), __float2half_rn(a.y));
        *(__half2*)(dst + i4 + 2) = __halves2half2(__float2half_rn(a.z), __float2half_rn(a.w));
    }
}

// ---------------- mma.sync fp16 GEMM ------------------------------------------
#define GSTAGES 3
#define STAGE_BYTES 16384
#define SMEM_A 0
#define SMEM_B (GSTAGES * STAGE_BYTES)
#define GEMM_SMEM (2 * GSTAGES * STAGE_BYTES)   // 96 KB

#define LOAD_STAGE(ld) do {                                                    \
        int _s = (ld) % 3;                                                     \
        uint32_t _ab = sb + SMEM_A + _s * STAGE_BYTES;                         \
        uint32_t _bb = sb + SMEM_B + _s * STAGE_BYTES;                         \
        const __half* _ag = Ab + (ld) * 64;                                    \
        const __half* _bg = Bb + ((ld) & 15) * 64;                             \
        _Pragma("unroll")                                                      \
        for (int _c = 0; _c < 4; _c++) {                                       \
            int _chunk = tid + _c * 256;                                       \
            int _row = _chunk >> 3, _c16 = _chunk & 7;                         \
            uint32_t _off = (uint32_t)(_row * 128 + _c16 * 16);                \
            _off ^= ((_off >> 3) & 0x70);                                      \
            asm volatile("cp.async.cg.shared.global [%0], [%1], 16;"           \
                :: "r"(_ab + _off), "l"(_ag + (size_t)_row * KA + _c16 * 8));  \
            asm volatile("cp.async.cg.shared.global [%0], [%1], 16;"           \
                :: "r"(_bb + _off), "l"(_bg + (size_t)_row * KB + _c16 * 8));  \
        }                                                                      \
        asm volatile("cp.async.commit_group;");                                \
    } while (0)

#define LDSM_X4(f, addr)                                                       \
    asm volatile("ldmatrix.sync.aligned.m8n8.x4.shared.b16 {%0,%1,%2,%3}, [%4];" \
        : "=r"((f)[0]), "=r"((f)[1]), "=r"((f)[2]), "=r"((f)[3]) : "r"(addr))

#define LDSM_X4T(f, addr)                                                      \
    asm volatile("ldmatrix.sync.aligned.m8n8.x4.trans.shared.b16 {%0,%1,%2,%3}, [%4];" \
        : "=r"((f)[0]), "=r"((f)[1]), "=r"((f)[2]), "=r"((f)[3]) : "r"(addr))

#define MMA16816(d, a, b0, b1)                                                 \
    asm volatile("mma.sync.aligned.m16n8k16.row.col.f32.f16.f16.f32 "          \
        "{%0,%1,%2,%3}, {%4,%5,%6,%7}, {%8,%9}, {%0,%1,%2,%3};"                \
        : "+f"((d)[0]), "+f"((d)[1]), "+f"((d)[2]), "+f"((d)[3])               \
        : "r"((a)[0]), "r"((a)[1]), "r"((a)[2]), "r"((a)[3]),                  \
          "r"(b0), "r"(b1))

#define LOAD_FRAGS(ks) do {                                                    \
        _Pragma("unroll")                                                      \
        for (int _mt = 0; _mt < 2; _mt++)                                      \
            LDSM_X4(af[_mt], aB + aRowByte[_mt] +                              \
                    ((uint32_t)(((ks) * 2 + achunk)) ^ xa) * 16u);             \
        _Pragma("unroll")                                                      \
        for (int _nt2 = 0; _nt2 < 4; _nt2++)                                   \
            LDSM_X4(bf[_nt2], bB + bRowByte[_nt2] +                            \
                    ((uint32_t)(((ks) * 2 + bchunk)) ^ xb) * 16u);             \
    } while (0)

__global__ __launch_bounds__(256, 2)
void gemm_mma(const __half* __restrict__ A, const __half* __restrict__ B,
              const float* __restrict__ bias, float* __restrict__ C,
              int N, int nkit, int qkv_mode,
              float* __restrict__ qp, __half* __restrict__ khp, __half* __restrict__ vhp)
{
    extern __shared__ char smraw[];
    uint32_t sb = smem_u32(smraw);
    const int tid = threadIdx.x;
    const int wid = tid >> 5, lane = tid & 31;
    const int wm = wid & 3, wn = wid >> 2;
    const int bn = blockIdx.x, bm = blockIdx.y;
    // K/V outputs are truncated to fp16 in the epilogue anyway — the lo-plane
    // correction (2^-12) is below their rounding error (2^-11). Only Q (fp32,
    // feeds exponentiated logits) uses the full [hi|lo] K=2048.
    if (qkv_mode && bn >= 8) nkit = 16;
    const __half* Ab = A + (size_t)bm * 128 * KA;
    const __half* Bb = B + (size_t)bn * 128 * KB;

    float acc[2][8][4];
#pragma unroll
    for (int i = 0; i < 2; i++)
#pragma unroll
        for (int j = 0; j < 8; j++)
#pragma unroll
            for (int c = 0; c < 4; c++) acc[i][j][c] = 0.f;

    const int g = lane >> 3, r = lane & 7;
    const int rowA = wm * 32 + (g & 1) * 8 + r;
    const int achunk = (g >> 1);
    const uint32_t xa = (uint32_t)(rowA & 7);
    uint32_t aRowByte[2];
#pragma unroll
    for (int mt = 0; mt < 2; mt++) aRowByte[mt] = (uint32_t)((rowA + mt * 16) * 128);
    const int rowB = wn * 64 + (g >> 1) * 8 + r;
    const int bchunk = (g & 1);
    const uint32_t xb = (uint32_t)(rowB & 7);
    uint32_t bRowByte[4];
#pragma unroll
    for (int nt2 = 0; nt2 < 4; nt2++) bRowByte[nt2] = (uint32_t)((rowB + nt2 * 16) * 128);

    LOAD_STAGE(0); LOAD_STAGE(1);

    uint32_t af[2][4];
    uint32_t bf[4][4];

    for (int it = 0; it < nkit; it++) {
        if (it + 1 < nkit) asm volatile("cp.async.wait_group 1;");
        else               asm volatile("cp.async.wait_group 0;");
        __syncthreads();
        if (it + 2 < nkit) LOAD_STAGE(it + 2);

        const uint32_t aB = sb + SMEM_A + (uint32_t)((it % 3) * STAGE_BYTES);
        const uint32_t bB = sb + SMEM_B + (uint32_t)((it % 3) * STAGE_BYTES);
#pragma unroll
        for (int ks = 0; ks < 4; ks++) {
            LOAD_FRAGS(ks);
#pragma unroll
            for (int mt = 0; mt < 2; mt++)
#pragma unroll
                for (int nt = 0; nt < 8; nt++) {
                    const uint32_t* bp = bf[nt >> 1];
                    int o = (nt & 1) * 2;
                    MMA16816(acc[mt][nt], af[mt], bp[o], bp[o + 1]);
                }
        }
    }

    const int mrow0 = bm * 128 + wm * 32 + (lane >> 2);
    const int colb  = bn * 128 + wn * 64;
    if (!qkv_mode) {
#pragma unroll
        for (int mt = 0; mt < 2; mt++)
#pragma unroll
            for (int nt = 0; nt < 8; nt++) {
                int col = colb + nt * 8 + (lane & 3) * 2;
                float2 b2 = *(const float2*)&bias[col];
                int row = mrow0 + mt * 16;
                *(float2*)&C[(size_t)row * N + col] =
                    make_float2(acc[mt][nt][0] + b2.x, acc[mt][nt][1] + b2.y);
                *(float2*)&C[(size_t)(row + 8) * N + col] =
                    make_float2(acc[mt][nt][2] + b2.x, acc[mt][nt][3] + b2.y);
            }
    } else {
        const int which = colb >> 10;
        const int hh = (colb >> 6) & 15;
        if (which == 0) {
#pragma unroll
            for (int mt = 0; mt < 2; mt++)
#pragma unroll
                for (int nt = 0; nt < 8; nt++) {
                    int dd = nt * 8 + (lane & 3) * 2;
                    float2 b2 = *(const float2*)&bias[colb + dd];
#pragma unroll
                    for (int half = 0; half < 2; half++) {
                        int row = mrow0 + mt * 16 + half * 8;
                        int t = row >> 2, b3 = row & 3;
                        float* basep = qp + ((size_t)((b3 << 4) + hh) * TGT + t) * HDIM + dd;
                        *(float2*)basep = make_float2(
                            (acc[mt][nt][half * 2 + 0] + b2.x) * 0.125f,
                            (acc[mt][nt][half * 2 + 1] + b2.y) * 0.125f);
                    }
                }
        } else {
            __half* dsth = (which == 1) ? khp : vhp;
#pragma unroll
            for (int mt = 0; mt < 2; mt++)
#pragma unroll
                for (int nt = 0; nt < 8; nt++) {
                    int dd = nt * 8 + (lane & 3) * 2;
                    float2 b2 = *(const float2*)&bias[colb + dd];
#pragma unroll
                    for (int half = 0; half < 2; half++) {
                        int row = mrow0 + mt * 16 + half * 8;
                        int t = row >> 2, b3 = row & 3;
                        __half* basep = dsth + ((size_t)((b3 << 4) + hh) * TGT + t) * HDIM + dd;
                        *(__half2*)basep = __halves2half2(
                            __float2half_rn(acc[mt][nt][half * 2 + 0] + b2.x),
                            __float2half_rn(acc[mt][nt][half * 2 + 1] + b2.y));
                    }
                }
        }
    }
}

// ---------------- tensor-core flash attention ---------------------------------
// Bucket LUT on (t-s); PV uses P-hi only (P in [0,1]; lo term ~2^-12 dropped).
struct AttnTc {
    __half qh[4096];
    __half ql[4096];
    __half kh[2][4096];
    __half vh[2][4096];
    float relrow[64][32];
    float Ld[64];
    int lut[512];
};

#define LOAD_KV(ci, buf) do {                                                  \
        const __half* _kg = kg + (size_t)(ci) * 64 * HDIM;                     \
        const __half* _vg = vg + (size_t)(ci) * 64 * HDIM;                     \
        uint32_t _kb = kh_base + (uint32_t)(buf) * 8192u;                      \
        uint32_t _vb = vh_base + (uint32_t)(buf) * 8192u;                      \
        _Pragma("unroll")                                                      \
        for (int _c = 0; _c < 4; _c++) {                                       \
            int _ch = tid + _c * 128;                                          \
            int _row = _ch >> 3, _c16 = _ch & 7;                               \
            uint32_t _off = (uint32_t)(_row * 128 + ((_c16 ^ (_row & 7)) * 16)); \
            asm volatile("cp.async.cg.shared.global [%0], [%1], 16;"           \
                :: "r"(_kb + _off), "l"(_kg + _row * 64 + _c16 * 8));          \
            asm volatile("cp.async.cg.shared.global [%0], [%1], 16;"           \
                :: "r"(_vb + _off), "l"(_vg + _row * 64 + _c16 * 8));          \
        }                                                                      \
        asm volatile("cp.async.commit_group;");                                \
    } while (0)

__global__ __launch_bounds__(128)
void attn_tc(const float* __restrict__ q, const __half* __restrict__ kh,
             const __half* __restrict__ vh, const float* __restrict__ relvals,
             const int* __restrict__ bkm, const int* __restrict__ bkn,
             float* __restrict__ ctx)
{
    extern __shared__ char smraw[];
    AttnTc& sm = *reinterpret_cast<AttnTc*>(smraw);
    const int qt = 7 - blockIdx.x;            // biggest tiles first
    const int bh = blockIdx.y, mode = blockIdx.z;
    const int b = bh >> 4, h = bh & 15;
    const int tid = threadIdx.x, wid = tid >> 5, lane = tid & 31;
    const int t0 = qt * 64, n = mode - 1, grow0 = mode * 512 + t0;
    const int qr = lane >> 2, qc = lane & 3;
    const int g = lane >> 3, r8 = lane & 7;

    const uint32_t kh_base = smem_u32(sm.kh), vh_base = smem_u32(sm.vh);
    const __half* kg = kh + (size_t)bh * TGT * HDIM;
    const __half* vg = vh + (size_t)bh * TGT * HDIM;
    const int nloop = qt + 1;

    LOAD_KV(0, 0);

    // 1-D bucket LUT: lut[d] = bucket row 511, col 511-d
    {
        const int* lutsrc = (mode == 0) ? (bkm + (size_t)511 * 512 + 511)
                                        : (bkn + (size_t)511 * 1024 + 511);
        for (int d = tid; d < 512; d += 128) sm.lut[d] = lutsrc[-d];
    }

    // ---- load Q (split hi/lo) and relrow ----
    const float* qb = q + ((size_t)bh * TGT + grow0) * HDIM;
    for (int i = tid; i < 512; i += 128) {
        int row = i >> 3, c = i & 7;
        const float* src = qb + row * 64 + c * 8;
        float4 x0 = *(const float4*)src, x1 = *(const float4*)(src + 4);
        float xs[8] = {x0.x, x0.y, x0.z, x0.w, x1.x, x1.y, x1.z, x1.w};
        __half hh[8], ll[8];
#pragma unroll
        for (int j = 0; j < 8; j++) {
            hh[j] = __float2half_rn(xs[j]);
            ll[j] = __float2half_rn(xs[j] - __half2float(hh[j]));
        }
        int idx = row * 64 + ((c ^ (row & 7)) << 3);
        uint4 hv, lv;
        hv.x = pack_h2(hh[0], hh[1]); hv.y = pack_h2(hh[2], hh[3]);
        hv.z = pack_h2(hh[4], hh[5]); hv.w = pack_h2(hh[6], hh[7]);
        lv.x = pack_h2(ll[0], ll[1]); lv.y = pack_h2(ll[2], ll[3]);
        lv.z = pack_h2(ll[4], ll[5]); lv.w = pack_h2(ll[6], ll[7]);
        *(uint4*)&sm.qh[idx] = hv;
        *(uint4*)&sm.ql[idx] = lv;
    }
    for (int idx = tid; idx < 2048; idx += 128) {
        int i = idx >> 5, nb = idx & 31;
        sm.relrow[i][nb] = relvals[((size_t)(grow0 + i) * 4 + b) * 512 + nb * 16 + h];
    }
    __syncthreads();

    const uint32_t qh_base = smem_u32(sm.qh), ql_base = smem_u32(sm.ql);
    const int arow = wid * 16 + (g & 1) * 8 + r8;
    const int achunk = g >> 1;
    uint32_t afh[4][4], afl[4][4];
#pragma unroll
    for (int ks = 0; ks < 4; ks++) {
        uint32_t off = (uint32_t)(arow * 128 + (((ks * 2 + achunk) ^ (arow & 7)) * 16));
        LDSM_X4(afh[ks], qh_base + off);
        LDSM_X4(afl[ks], ql_base + off);
    }

    const int brow8 = (g >> 1) * 8 + r8;
    const int bchunk = g & 1;
    const int vrow8 = (g & 1) * 8 + r8;
    const int vdo = g >> 1;

    float m_i[2] = {-1e30f, -1e30f}, l_i[2] = {0.f, 0.f};
    float of[8][4];
#pragma unroll
    for (int nt = 0; nt < 8; nt++)
#pragma unroll
        for (int c = 0; c < 4; c++) of[nt][c] = 0.f;

    for (int ci = 0; ci < nloop; ci++) {
        const int s0 = ci * 64;
        if (ci + 1 < nloop) {
            LOAD_KV(ci + 1, (ci + 1) & 1);
            asm volatile("cp.async.wait_group 1;");
        } else {
            asm volatile("cp.async.wait_group 0;");
        }
        __syncthreads();
        const uint32_t kbase = kh_base + (uint32_t)(ci & 1) * 8192u;
        const uint32_t vbase = vh_base + (uint32_t)(ci & 1) * 8192u;

        // ---- S = [qhi|qlo] @ khi^T ----
        float sacc[8][4];
#pragma unroll
        for (int nt = 0; nt < 8; nt++)
#pragma unroll
            for (int c = 0; c < 4; c++) sacc[nt][c] = 0.f;
#pragma unroll
        for (int ks = 0; ks < 4; ks++) {
            uint32_t bq[4][4];
#pragma unroll
            for (int nt2 = 0; nt2 < 4; nt2++) {
                int krow = nt2 * 16 + brow8;
                uint32_t off = (uint32_t)(krow * 128 + (((ks * 2 + bchunk) ^ (krow & 7)) * 16));
                LDSM_X4(bq[nt2], kbase + off);
            }
#pragma unroll
            for (int nt2 = 0; nt2 < 4; nt2++) {
                MMA16816(sacc[2 * nt2],     afh[ks], bq[nt2][0], bq[nt2][1]);
                MMA16816(sacc[2 * nt2 + 1], afh[ks], bq[nt2][2], bq[nt2][3]);
                MMA16816(sacc[2 * nt2],     afl[ks], bq[nt2][0], bq[nt2][1]);
                MMA16816(sacc[2 * nt2 + 1], afl[ks], bq[nt2][2], bq[nt2][3]);
            }
        }

        // ---- rel (smem LUT on t-s) + mask ----
#pragma unroll
        for (int rh = 0; rh < 2; rh++) {
            int rl = wid * 16 + qr + rh * 8;
            int t_loc = t0 + rl;
            int d0base = t_loc - (s0 + qc * 2);
#pragma unroll
            for (int nt = 0; nt < 8; nt++) {
                int d0 = d0base - nt * 8;
                int d1 = d0 - 1;
                int i0 = d0 < 0 ? 0 : d0;
                int i1 = d1 < 0 ? 0 : d1;
                sacc[nt][rh * 2 + 0] += sm.relrow[rl][sm.lut[i0]] + ((d0 >= 0) ? 0.f : -10000.f);
                sacc[nt][rh * 2 + 1] += sm.relrow[rl][sm.lut[i1]] + ((d1 >= 0) ? 0.f : -10000.f);
            }
        }

        // ---- online softmax ----
#pragma unroll
        for (int rh = 0; rh < 2; rh++) {
            float mc = -1e30f;
#pragma unroll
            for (int nt = 0; nt < 8; nt++) {
                mc = fmaxf(mc, sacc[nt][rh * 2]);
                mc = fmaxf(mc, sacc[nt][rh * 2 + 1]);
            }
            mc = fmaxf(mc, __shfl_xor_sync(0xFFFFFFFFu, mc, 1));
            mc = fmaxf(mc, __shfl_xor_sync(0xFFFFFFFFu, mc, 2));
            float mnew = fmaxf(m_i[rh], mc);
            float al = __expf(m_i[rh] - mnew);
            float ls = 0.f;
#pragma unroll
            for (int nt = 0; nt < 8; nt++) {
                float e0 = __expf(sacc[nt][rh * 2]     - mnew);
                float e1 = __expf(sacc[nt][rh * 2 + 1] - mnew);
                sacc[nt][rh * 2] = e0; sacc[nt][rh * 2 + 1] = e1;
                ls += e0 + e1;
            }
            ls += __shfl_xor_sync(0xFFFFFFFFu, ls, 1);
            ls += __shfl_xor_sync(0xFFFFFFFFu, ls, 2);
            l_i[rh] = l_i[rh] * al + ls;
            m_i[rh] = mnew;
#pragma unroll
            for (int nt = 0; nt < 8; nt++) {
                of[nt][rh * 2] *= al; of[nt][rh * 2 + 1] *= al;
            }
        }

        // ---- O += Phi @ vhi ----
#pragma unroll
        for (int ks = 0; ks < 4; ks++) {
            uint32_t bv[4][4];
#pragma unroll
            for (int nt2 = 0; nt2 < 4; nt2++) {
                int srow = ks * 16 + vrow8;
                int dchunk = nt2 * 2 + vdo;
                uint32_t off = (uint32_t)(srow * 128 + ((dchunk ^ (srow & 7)) * 16));
                LDSM_X4T(bv[nt2], vbase + off);
            }
            uint32_t ph[4];
            {
                float e[8] = {sacc[2*ks][0], sacc[2*ks][1], sacc[2*ks][2], sacc[2*ks][3],
                              sacc[2*ks+1][0], sacc[2*ks+1][1], sacc[2*ks+1][2], sacc[2*ks+1][3]};
                ph[0] = pack_h2(__float2half_rn(e[0]), __float2half_rn(e[1]));
                ph[1] = pack_h2(__float2half_rn(e[2]), __float2half_rn(e[3]));
                ph[2] = pack_h2(__float2half_rn(e[4]), __float2half_rn(e[5]));
                ph[3] = pack_h2(__float2half_rn(e[6]), __float2half_rn(e[7]));
            }
#pragma unroll
            for (int nt2 = 0; nt2 < 4; nt2++) {
                MMA16816(of[2 * nt2],     ph, bv[nt2][0], bv[nt2][1]);
                MMA16816(of[2 * nt2 + 1], ph, bv[nt2][2], bv[nt2][3]);
            }
        }
        __syncthreads();
    }

    // ---- analytic ngram diagonal: bucket(0) == 0 ----
    if (mode != 0) {
        {
            int row = tid >> 1, hf = tid & 1;
            int t_loc = t0 + row;
            int krow = n * 512 + 512 + t_loc;
            const __half* kr = kh + ((size_t)bh * TGT + krow) * HDIM + hf * 32;
            const float* qr2 = qb + row * 64 + hf * 32;
            float dot = 0.f;
#pragma unroll
            for (int j = 0; j < 16; j++) {
                float2 q2 = *(const float2*)(qr2 + j * 2);
                float2 kf = __half22float2(*(const __half2*)(kr + j * 2));
                dot += q2.x * kf.x + q2.y * kf.y;
            }
            dot += __shfl_xor_sync(0xFFFFFFFFu, dot, 1);
            float L = dot + sm.relrow[row][0];   // bucket(0) = 0
            if (!hf) sm.Ld[row] = L;
        }
        __syncthreads();
#pragma unroll
        for (int rh = 0; rh < 2; rh++) {
            int rl = wid * 16 + qr + rh * 8;
            int t_loc = t0 + rl;
            float L = sm.Ld[rl];
            float mnew = fmaxf(m_i[rh], L);
            float al = __expf(m_i[rh] - mnew);
            float p = __expf(L - mnew);
            l_i[rh] = l_i[rh] * al + p;
            m_i[rh] = mnew;
            const __half* vr = vh + ((size_t)bh * TGT + n * 512 + 512 + t_loc) * HDIM + qc * 2;
#pragma unroll
            for (int nt = 0; nt < 8; nt++) {
                float2 v2 = __half22float2(*(const __half2*)(vr + nt * 8));
                of[nt][rh * 2]     = of[nt][rh * 2]     * al + p * v2.x;
                of[nt][rh * 2 + 1] = of[nt][rh * 2 + 1] * al + p * v2.y;
            }
        }
    }

    // ---- epilogue ----
#pragma unroll
    for (int rh = 0; rh < 2; rh++) {
        int rl = wid * 16 + qr + rh * 8;
        float inv = 1.0f / l_i[rh];
        float* cb = ctx + ((size_t)(grow0 + rl) * 4 + b) * EDIM + h * 64 + qc * 2;
#pragma unroll
        for (int nt = 0; nt < 8; nt++)
            *(float2*)(cb + nt * 8) = make_float2(of[nt][rh * 2] * inv,
                                                  of[nt][rh * 2 + 1] * inv);
    }
}

// ---------------- launch -----------------------------------------------------
extern "C" void kernel_launch(void* const* d_in, const int* in_sizes, int n_in,
                              void* d_out, int out_size)
{
    const float* hidden = (const float*)d_in[0];
    const float* w_in   = (const float*)d_in[1];
    const float* b_in   = (const float*)d_in[2];
    const float* rel_w  = (const float*)d_in[3];
    const float* rel_b  = (const float*)d_in[4];
    const float* out_w  = (const float*)d_in[5];
    const float* out_b  = (const float*)d_in[6];
    const int* bkm = (const int*)d_in[9];
    const int* bkn = (const int*)d_in[10];
    float* out = (float*)d_out;

    float *qp, *rv, *ctx;
    __half *khp, *vhp, *A2, *Wqkv2, *Wrel2, *Wout2;
    cudaGetSymbolAddress((void**)&qp,  g_q);
    cudaGetSymbolAddress((void**)&khp, g_kh);
    cudaGetSymbolAddress((void**)&vhp, g_vh);
    cudaGetSymbolAddress((void**)&rv,  g_relvals);
    cudaGetSymbolAddress((void**)&ctx, g_ctx);
    cudaGetSymbolAddress((void**)&A2,    g_A2);
    cudaGetSymbolAddress((void**)&Wqkv2, g_Wqkv2);
    cudaGetSymbolAddress((void**)&Wrel2, g_Wrel2);
    cudaGetSymbolAddress((void**)&Wout2, g_Wout2);

    cudaFuncSetAttribute(gemm_mma, cudaFuncAttributeMaxDynamicSharedMemorySize, GEMM_SMEM);
    cudaFuncSetAttribute(attn_tc, cudaFuncAttributeMaxDynamicSharedMemorySize,
                         (int)sizeof(AttnTc));

    // 0) fused conversion
    convert_all<<<10752, 256>>>(hidden, w_in, rel_w, out_w, A2, Wqkv2, Wrel2, Wout2);

    // 1) QKV projection (Q: K=2048 split; K/V columns: K=1024 hi-only)
    gemm_mma<<<dim3(3072 / 128, ROWS_ALL / 128), 256, GEMM_SMEM>>>(
        A2, Wqkv2, b_in, nullptr, 3072, 32, 1, qp, khp, vhp);

    // 2) rel values (hi-only K=1024)
    gemm_mma<<<dim3(512 / 128, ROWS_ALL / 128), 256, GEMM_SMEM>>>(
        A2, Wrel2, rel_b, rv, 512, 16, 0, nullptr, nullptr, nullptr);

    // 3) tensor-core flash attention
    attn_tc<<<dim3(8, 64, 3), 128, sizeof(AttnTc)>>>(qp, khp, vhp, rv, bkm, bkn, ctx);

    // 4) output projection
    convert_act<<<ROWS_ALL, 256>>>(ctx, A2);
    gemm_mma<<<dim3(1024 / 128, ROWS_ALL / 128), 256, GEMM_SMEM>>>(
        A2, Wout2, out_b, out, 1024, 32, 0, nullptr, nullptr, nullptr);
}

// round 17
// speedup vs baseline: 1.8720x; 1.0182x over previous
#include <cuda_runtime.h>
#include <cuda_fp16.h>
#include <cstdint>
#include <cstddef>

// Problem constants
#define TLEN   512
#define BATCH  4
#define HEADS  16
#define HDIM   64
#define EDIM   1024
#define ROWS_ALL 6144          // (1+NGRAM)*T * B
#define BH     64
#define TGT    1536
#define KA     2048            // activation split-K (fp16 [hi|lo])
#define KB     1024            // weight K (fp16 hi only)
#define NCAT   3584            // 3072 qkv cols + 512 rel cols

// ---------------- scratch (static device globals; no allocation) -------------
__device__ float g_q[(size_t)BH * TGT * HDIM];
__device__ __half g_kh[(size_t)BH * TGT * HDIM];     // fp16 K (hi)
__device__ __half g_vh[(size_t)BH * TGT * HDIM];     // fp16 V (hi)
__device__ float g_relvals[(size_t)ROWS_ALL * 512];
__device__ float g_ctx[(size_t)ROWS_ALL * EDIM];
__device__ __half g_A2[(size_t)ROWS_ALL * KA];       // [hi|lo] activations
__device__ __half g_Wcat[(size_t)NCAT * KB];         // [w_in | rel_w] fp16 hi
__device__ __half g_Wout2[(size_t)1024 * KB];
__device__ float g_biascat[NCAT];                    // [b_in | rel_b]

__device__ __forceinline__ uint32_t smem_u32(const void* p) {
    uint32_t a;
    asm("{ .reg .u64 t; cvta.to.shared.u64 t, %1; cvt.u32.u64 %0, t; }" : "=r"(a) : "l"(p));
    return a;
}
__device__ __forceinline__ uint32_t pack_h2(__half a, __half b) {
    __half2 t = __halves2half2(a, b);
    return *reinterpret_cast<uint32_t*>(&t);
}

// ---------------- conversions --------------------------------------------------
__global__ __launch_bounds__(256)
void convert_act(const float* __restrict__ src, __half* __restrict__ dst)
{
    int i4 = (blockIdx.x * blockDim.x + threadIdx.x) * 4;
    float4 a = *(const float4*)(src + i4);
    int r = i4 >> 10, k = i4 & 1023;
    size_t base = (size_t)r * KA + k;
    float av[4] = {a.x, a.y, a.z, a.w};
    __half h[4], l[4];
#pragma unroll
    for (int j = 0; j < 4; j++) {
        h[j] = __float2half_rn(av[j]);
        l[j] = __float2half_rn(av[j] - __half2float(h[j]));
    }
    *(__half2*)(dst + base + 0) = __halves2half2(h[0], h[1]);
    *(__half2*)(dst + base + 2) = __halves2half2(h[2], h[3]);
    *(__half2*)(dst + base + 1024) = __halves2half2(l[0], l[1]);
    *(__half2*)(dst + base + 1026) = __halves2half2(l[2], l[3]);
}

// fused first-round conversion: hidden split + weights (w_in|rel_w concat, out_w)
// + bias concat. blocks [0,6144): hidden ; [6144,9216): w_in -> Wcat[0:3072] ;
// [9216,9728): rel_w -> Wcat[3072:3584] ; [9728,10752): out_w ; 10752: biases
__global__ __launch_bounds__(256)
void convert_all(const float* __restrict__ hidden, const float* __restrict__ w_in,
                 const float* __restrict__ rel_w, const float* __restrict__ out_w,
                 const float* __restrict__ b_in, const float* __restrict__ rel_b,
                 __half* __restrict__ A2, __half* __restrict__ Wcat,
                 __half* __restrict__ Wo, float* __restrict__ biascat)
{
    int bid = blockIdx.x;
    if (bid < 6144) {
        int i4 = (bid * 256 + threadIdx.x) * 4;
        float4 a = *(const float4*)(hidden + i4);
        int r = i4 >> 10, k = i4 & 1023;
        size_t base = (size_t)r * KA + k;
        float av[4] = {a.x, a.y, a.z, a.w};
        __half h[4], l[4];
#pragma unroll
        for (int j = 0; j < 4; j++) {
            h[j] = __float2half_rn(av[j]);
            l[j] = __float2half_rn(av[j] - __half2float(h[j]));
        }
        *(__half2*)(A2 + base + 0) = __halves2half2(h[0], h[1]);
        *(__half2*)(A2 + base + 2) = __halves2half2(h[2], h[3]);
        *(__half2*)(A2 + base + 1024) = __halves2half2(l[0], l[1]);
        *(__half2*)(A2 + base + 1026) = __halves2half2(l[2], l[3]);
    } else if (bid < 10752) {
        const float* src; __half* dst; int rb;
        if (bid < 9216)      { src = w_in;  dst = Wcat;                       rb = bid - 6144; }
        else if (bid < 9728) { src = rel_w; dst = Wcat + (size_t)3072 * KB;   rb = bid - 9216; }
        else                 { src = out_w; dst = Wo;                         rb = bid - 9728; }
        int i4 = (rb * 256 + threadIdx.x) * 4;
        float4 a = *(const float4*)(src + i4);
        *(__half2*)(dst + i4 + 0) = __halves2half2(__float2half_rn(a.x), __float2half_rn(a.y));
        *(__half2*)(dst + i4 + 2) = __halves2half2(__float2half_rn(a.z), __float2half_rn(a.w));
    } else {
        for (int i = threadIdx.x; i < NCAT; i += 256)
            biascat[i] = (i < 3072) ? b_in[i] : rel_b[i - 3072];
    }
}

// ---------------- mma.sync fp16 GEMM ------------------------------------------
#define GSTAGES 3
#define STAGE_BYTES 16384
#define SMEM_A 0
#define SMEM_B (GSTAGES * STAGE_BYTES)
#define GEMM_SMEM (2 * GSTAGES * STAGE_BYTES)   // 96 KB

#define LOAD_STAGE(ld) do {                                                    \
        int _s = (ld) % 3;                                                     \
        uint32_t _ab = sb + SMEM_A + _s * STAGE_BYTES;                         \
        uint32_t _bb = sb + SMEM_B + _s * STAGE_BYTES;                         \
        const __half* _ag = Ab + (ld) * 64;                                    \
        const __half* _bg = Bb + ((ld) & 15) * 64;                             \
        _Pragma("unroll")                                                      \
        for (int _c = 0; _c < 4; _c++) {                                       \
            int _chunk = tid + _c * 256;                                       \
            int _row = _chunk >> 3, _c16 = _chunk & 7;                         \
            uint32_t _off = (uint32_t)(_row * 128 + _c16 * 16);                \
            _off ^= ((_off >> 3) & 0x70);                                      \
            asm volatile("cp.async.cg.shared.global [%0], [%1], 16;"           \
                :: "r"(_ab + _off), "l"(_ag + (size_t)_row * KA + _c16 * 8));  \
            asm volatile("cp.async.cg.shared.global [%0], [%1], 16;"           \
                :: "r"(_bb + _off), "l"(_bg + (size_t)_row * KB + _c16 * 8));  \
        }                                                                      \
        asm volatile("cp.async.commit_group;");                                \
    } while (0)

#define LDSM_X4(f, addr)                                                       \
    asm volatile("ldmatrix.sync.aligned.m8n8.x4.shared.b16 {%0,%1,%2,%3}, [%4];" \
        : "=r"((f)[0]), "=r"((f)[1]), "=r"((f)[2]), "=r"((f)[3]) : "r"(addr))

#define LDSM_X4T(f, addr)                                                      \
    asm volatile("ldmatrix.sync.aligned.m8n8.x4.trans.shared.b16 {%0,%1,%2,%3}, [%4];" \
        : "=r"((f)[0]), "=r"((f)[1]), "=r"((f)[2]), "=r"((f)[3]) : "r"(addr))

#define MMA16816(d, a, b0, b1)                                                 \
    asm volatile("mma.sync.aligned.m16n8k16.row.col.f32.f16.f16.f32 "          \
        "{%0,%1,%2,%3}, {%4,%5,%6,%7}, {%8,%9}, {%0,%1,%2,%3};"                \
        : "+f"((d)[0]), "+f"((d)[1]), "+f"((d)[2]), "+f"((d)[3])               \
        : "r"((a)[0]), "r"((a)[1]), "r"((a)[2]), "r"((a)[3]),                  \
          "r"(b0), "r"(b1))

#define LOAD_FRAGS(ks) do {                                                    \
        _Pragma("unroll")                                                      \
        for (int _mt = 0; _mt < 2; _mt++)                                      \
            LDSM_X4(af[_mt], aB + aRowByte[_mt] +                              \
                    ((uint32_t)(((ks) * 2 + achunk)) ^ xa) * 16u);             \
        _Pragma("unroll")                                                      \
        for (int _nt2 = 0; _nt2 < 4; _nt2++)                                   \
            LDSM_X4(bf[_nt2], bB + bRowByte[_nt2] +                            \
                    ((uint32_t)(((ks) * 2 + bchunk)) ^ xb) * 16u);             \
    } while (0)

__global__ __launch_bounds__(256, 2)
void gemm_mma(const __half* __restrict__ A, const __half* __restrict__ B,
              const float* __restrict__ bias, float* __restrict__ C,
              int N, int nkit, int qkv_mode,
              float* __restrict__ qp, __half* __restrict__ khp, __half* __restrict__ vhp)
{
    extern __shared__ char smraw[];
    uint32_t sb = smem_u32(smraw);
    const int tid = threadIdx.x;
    const int wid = tid >> 5, lane = tid & 31;
    const int wm = wid & 3, wn = wid >> 2;
    const int bn = blockIdx.x, bm = blockIdx.y;
    // K/V and rel outputs tolerate hi-only (K=1024); Q needs the full split.
    if (qkv_mode && bn >= 8) nkit = 16;
    const __half* Ab = A + (size_t)bm * 128 * KA;
    const __half* Bb = B + (size_t)bn * 128 * KB;

    float acc[2][8][4];
#pragma unroll
    for (int i = 0; i < 2; i++)
#pragma unroll
        for (int j = 0; j < 8; j++)
#pragma unroll
            for (int c = 0; c < 4; c++) acc[i][j][c] = 0.f;

    const int g = lane >> 3, r = lane & 7;
    const int rowA = wm * 32 + (g & 1) * 8 + r;
    const int achunk = (g >> 1);
    const uint32_t xa = (uint32_t)(rowA & 7);
    uint32_t aRowByte[2];
#pragma unroll
    for (int mt = 0; mt < 2; mt++) aRowByte[mt] = (uint32_t)((rowA + mt * 16) * 128);
    const int rowB = wn * 64 + (g >> 1) * 8 + r;
    const int bchunk = (g & 1);
    const uint32_t xb = (uint32_t)(rowB & 7);
    uint32_t bRowByte[4];
#pragma unroll
    for (int nt2 = 0; nt2 < 4; nt2++) bRowByte[nt2] = (uint32_t)((rowB + nt2 * 16) * 128);

    LOAD_STAGE(0); LOAD_STAGE(1);

    uint32_t af[2][4];
    uint32_t bf[4][4];

    for (int it = 0; it < nkit; it++) {
        if (it + 1 < nkit) asm volatile("cp.async.wait_group 1;");
        else               asm volatile("cp.async.wait_group 0;");
        __syncthreads();
        if (it + 2 < nkit) LOAD_STAGE(it + 2);

        const uint32_t aB = sb + SMEM_A + (uint32_t)((it % 3) * STAGE_BYTES);
        const uint32_t bB = sb + SMEM_B + (uint32_t)((it % 3) * STAGE_BYTES);
#pragma unroll
        for (int ks = 0; ks < 4; ks++) {
            LOAD_FRAGS(ks);
#pragma unroll
            for (int mt = 0; mt < 2; mt++)
#pragma unroll
                for (int nt = 0; nt < 8; nt++) {
                    const uint32_t* bp = bf[nt >> 1];
                    int o = (nt & 1) * 2;
                    MMA16816(acc[mt][nt], af[mt], bp[o], bp[o + 1]);
                }
        }
    }

    const int mrow0 = bm * 128 + wm * 32 + (lane >> 2);
    const int colb  = bn * 128 + wn * 64;
    if (!qkv_mode) {
#pragma unroll
        for (int mt = 0; mt < 2; mt++)
#pragma unroll
            for (int nt = 0; nt < 8; nt++) {
                int col = colb + nt * 8 + (lane & 3) * 2;
                float2 b2 = *(const float2*)&bias[col];
                int row = mrow0 + mt * 16;
                *(float2*)&C[(size_t)row * N + col] =
                    make_float2(acc[mt][nt][0] + b2.x, acc[mt][nt][1] + b2.y);
                *(float2*)&C[(size_t)(row + 8) * N + col] =
                    make_float2(acc[mt][nt][2] + b2.x, acc[mt][nt][3] + b2.y);
            }
    } else {
        const int which = colb >> 10;
        if (which == 3) {
            // rel columns (colb 3072..3583): plain store into rv [6144][512]
#pragma unroll
            for (int mt = 0; mt < 2; mt++)
#pragma unroll
                for (int nt = 0; nt < 8; nt++) {
                    int colg = colb + nt * 8 + (lane & 3) * 2;
                    int col = colg & 1023;            // 3072 offset strips cleanly
                    float2 b2 = *(const float2*)&bias[colg];
                    int row = mrow0 + mt * 16;
                    *(float2*)&C[(size_t)row * 512 + col] =
                        make_float2(acc[mt][nt][0] + b2.x, acc[mt][nt][1] + b2.y);
                    *(float2*)&C[(size_t)(row + 8) * 512 + col] =
                        make_float2(acc[mt][nt][2] + b2.x, acc[mt][nt][3] + b2.y);
                }
        } else if (which == 0) {
            const int hh = (colb >> 6) & 15;
#pragma unroll
            for (int mt = 0; mt < 2; mt++)
#pragma unroll
                for (int nt = 0; nt < 8; nt++) {
                    int dd = nt * 8 + (lane & 3) * 2;
                    float2 b2 = *(const float2*)&bias[colb + dd];
#pragma unroll
                    for (int half = 0; half < 2; half++) {
                        int row = mrow0 + mt * 16 + half * 8;
                        int t = row >> 2, b3 = row & 3;
                        float* basep = qp + ((size_t)((b3 << 4) + hh) * TGT + t) * HDIM + dd;
                        *(float2*)basep = make_float2(
                            (acc[mt][nt][half * 2 + 0] + b2.x) * 0.125f,
                            (acc[mt][nt][half * 2 + 1] + b2.y) * 0.125f);
                    }
                }
        } else {
            const int hh = (colb >> 6) & 15;
            __half* dsth = (which == 1) ? khp : vhp;
#pragma unroll
            for (int mt = 0; mt < 2; mt++)
#pragma unroll
                for (int nt = 0; nt < 8; nt++) {
                    int dd = nt * 8 + (lane & 3) * 2;
                    float2 b2 = *(const float2*)&bias[colb + dd];
#pragma unroll
                    for (int half = 0; half < 2; half++) {
                        int row = mrow0 + mt * 16 + half * 8;
                        int t = row >> 2, b3 = row & 3;
                        __half* basep = dsth + ((size_t)((b3 << 4) + hh) * TGT + t) * HDIM + dd;
                        *(__half2*)basep = __halves2half2(
                            __float2half_rn(acc[mt][nt][half * 2 + 0] + b2.x),
                            __float2half_rn(acc[mt][nt][half * 2 + 1] + b2.y));
                    }
                }
        }
    }
}

// ---------------- tensor-core flash attention ---------------------------------
struct AttnTc {
    __half qh[4096];
    __half ql[4096];
    __half kh[2][4096];
    __half vh[2][4096];
    float relrow[64][32];
    float Ld[64];
    int lut[512];
};

#define LOAD_KV(ci, buf) do {                                                  \
        const __half* _kg = kg + (size_t)(ci) * 64 * HDIM;                     \
        const __half* _vg = vg + (size_t)(ci) * 64 * HDIM;                     \
        uint32_t _kb = kh_base + (uint32_t)(buf) * 8192u;                      \
        uint32_t _vb = vh_base + (uint32_t)(buf) * 8192u;                      \
        _Pragma("unroll")                                                      \
        for (int _c = 0; _c < 4; _c++) {                                       \
            int _ch = tid + _c * 128;                                          \
            int _row = _ch >> 3, _c16 = _ch & 7;                               \
            uint32_t _off = (uint32_t)(_row * 128 + ((_c16 ^ (_row & 7)) * 16)); \
            asm volatile("cp.async.cg.shared.global [%0], [%1], 16;"           \
                :: "r"(_kb + _off), "l"(_kg + _row * 64 + _c16 * 8));          \
            asm volatile("cp.async.cg.shared.global [%0], [%1], 16;"           \
                :: "r"(_vb + _off), "l"(_vg + _row * 64 + _c16 * 8));          \
        }                                                                      \
        asm volatile("cp.async.commit_group;");                                \
    } while (0)

__global__ __launch_bounds__(128)
void attn_tc(const float* __restrict__ q, const __half* __restrict__ kh,
             const __half* __restrict__ vh, const float* __restrict__ relvals,
             const int* __restrict__ bkm, const int* __restrict__ bkn,
             float* __restrict__ ctx)
{
    extern __shared__ char smraw[];
    AttnTc& sm = *reinterpret_cast<AttnTc*>(smraw);
    const int qt = 7 - blockIdx.x;            // biggest tiles first
    const int bh = blockIdx.y, mode = blockIdx.z;
    const int b = bh >> 4, h = bh & 15;
    const int tid = threadIdx.x, wid = tid >> 5, lane = tid & 31;
    const int t0 = qt * 64, n = mode - 1, grow0 = mode * 512 + t0;
    const int qr = lane >> 2, qc = lane & 3;
    const int g = lane >> 3, r8 = lane & 7;

    const uint32_t kh_base = smem_u32(sm.kh), vh_base = smem_u32(sm.vh);
    const __half* kg = kh + (size_t)bh * TGT * HDIM;
    const __half* vg = vh + (size_t)bh * TGT * HDIM;
    const int nloop = qt + 1;

    LOAD_KV(0, 0);

    {
        const int* lutsrc = (mode == 0) ? (bkm + (size_t)511 * 512 + 511)
                                        : (bkn + (size_t)511 * 1024 + 511);
        for (int d = tid; d < 512; d += 128) sm.lut[d] = lutsrc[-d];
    }

    const float* qb = q + ((size_t)bh * TGT + grow0) * HDIM;
    for (int i = tid; i < 512; i += 128) {
        int row = i >> 3, c = i & 7;
        const float* src = qb + row * 64 + c * 8;
        float4 x0 = *(const float4*)src, x1 = *(const float4*)(src + 4);
        float xs[8] = {x0.x, x0.y, x0.z, x0.w, x1.x, x1.y, x1.z, x1.w};
        __half hh[8], ll[8];
#pragma unroll
        for (int j = 0; j < 8; j++) {
            hh[j] = __float2half_rn(xs[j]);
            ll[j] = __float2half_rn(xs[j] - __half2float(hh[j]));
        }
        int idx = row * 64 + ((c ^ (row & 7)) << 3);
        uint4 hv, lv;
        hv.x = pack_h2(hh[0], hh[1]); hv.y = pack_h2(hh[2], hh[3]);
        hv.z = pack_h2(hh[4], hh[5]); hv.w = pack_h2(hh[6], hh[7]);
        lv.x = pack_h2(ll[0], ll[1]); lv.y = pack_h2(ll[2], ll[3]);
        lv.z = pack_h2(ll[4], ll[5]); lv.w = pack_h2(ll[6], ll[7]);
        *(uint4*)&sm.qh[idx] = hv;
        *(uint4*)&sm.ql[idx] = lv;
    }
    for (int idx = tid; idx < 2048; idx += 128) {
        int i = idx >> 5, nb = idx & 31;
        sm.relrow[i][nb] = relvals[((size_t)(grow0 + i) * 4 + b) * 512 + nb * 16 + h];
    }
    __syncthreads();

    const uint32_t qh_base = smem_u32(sm.qh), ql_base = smem_u32(sm.ql);
    const int arow = wid * 16 + (g & 1) * 8 + r8;
    const int achunk = g >> 1;
    uint32_t afh[4][4], afl[4][4];
#pragma unroll
    for (int ks = 0; ks < 4; ks++) {
        uint32_t off = (uint32_t)(arow * 128 + (((ks * 2 + achunk) ^ (arow & 7)) * 16));
        LDSM_X4(afh[ks], qh_base + off);
        LDSM_X4(afl[ks], ql_base + off);
    }

    const int brow8 = (g >> 1) * 8 + r8;
    const int bchunk = g & 1;
    const int vrow8 = (g & 1) * 8 + r8;
    const int vdo = g >> 1;

    float m_i[2] = {-1e30f, -1e30f}, l_i[2] = {0.f, 0.f};
    float of[8][4];
#pragma unroll
    for (int nt = 0; nt < 8; nt++)
#pragma unroll
        for (int c = 0; c < 4; c++) of[nt][c] = 0.f;

    for (int ci = 0; ci < nloop; ci++) {
        const int s0 = ci * 64;
        if (ci + 1 < nloop) {
            LOAD_KV(ci + 1, (ci + 1) & 1);
            asm volatile("cp.async.wait_group 1;");
        } else {
            asm volatile("cp.async.wait_group 0;");
        }
        __syncthreads();
        const uint32_t kbase = kh_base + (uint32_t)(ci & 1) * 8192u;
        const uint32_t vbase = vh_base + (uint32_t)(ci & 1) * 8192u;

        float sacc[8][4];
#pragma unroll
        for (int nt = 0; nt < 8; nt++)
#pragma unroll
            for (int c = 0; c < 4; c++) sacc[nt][c] = 0.f;
#pragma unroll
        for (int ks = 0; ks < 4; ks++) {
            uint32_t bq[4][4];
#pragma unroll
            for (int nt2 = 0; nt2 < 4; nt2++) {
                int krow = nt2 * 16 + brow8;
                uint32_t off = (uint32_t)(krow * 128 + (((ks * 2 + bchunk) ^ (krow & 7)) * 16));
                LDSM_X4(bq[nt2], kbase + off);
            }
#pragma unroll
            for (int nt2 = 0; nt2 < 4; nt2++) {
                MMA16816(sacc[2 * nt2],     afh[ks], bq[nt2][0], bq[nt2][1]);
                MMA16816(sacc[2 * nt2 + 1], afh[ks], bq[nt2][2], bq[nt2][3]);
                MMA16816(sacc[2 * nt2],     afl[ks], bq[nt2][0], bq[nt2][1]);
                MMA16816(sacc[2 * nt2 + 1], afl[ks], bq[nt2][2], bq[nt2][3]);
            }
        }

#pragma unroll
        for (int rh = 0; rh < 2; rh++) {
            int rl = wid * 16 + qr + rh * 8;
            int t_loc = t0 + rl;
            int d0base = t_loc - (s0 + qc * 2);
#pragma unroll
            for (int nt = 0; nt < 8; nt++) {
                int d0 = d0base - nt * 8;
                int d1 = d0 - 1;
                int i0 = d0 < 0 ? 0 : d0;
                int i1 = d1 < 0 ? 0 : d1;
                sacc[nt][rh * 2 + 0] += sm.relrow[rl][sm.lut[i0]] + ((d0 >= 0) ? 0.f : -10000.f);
                sacc[nt][rh * 2 + 1] += sm.relrow[rl][sm.lut[i1]] + ((d1 >= 0) ? 0.f : -10000.f);
            }
        }

#pragma unroll
        for (int rh = 0; rh < 2; rh++) {
            float mc = -1e30f;
#pragma unroll
            for (int nt = 0; nt < 8; nt++) {
                mc = fmaxf(mc, sacc[nt][rh * 2]);
                mc = fmaxf(mc, sacc[nt][rh * 2 + 1]);
            }
            mc = fmaxf(mc, __shfl_xor_sync(0xFFFFFFFFu, mc, 1));
            mc = fmaxf(mc, __shfl_xor_sync(0xFFFFFFFFu, mc, 2));
            float mnew = fmaxf(m_i[rh], mc);
            float al = __expf(m_i[rh] - mnew);
            float ls = 0.f;
#pragma unroll
            for (int nt = 0; nt < 8; nt++) {
                float e0 = __expf(sacc[nt][rh * 2]     - mnew);
                float e1 = __expf(sacc[nt][rh * 2 + 1] - mnew);
                sacc[nt][rh * 2] = e0; sacc[nt][rh * 2 + 1] = e1;
                ls += e0 + e1;
            }
            ls += __shfl_xor_sync(0xFFFFFFFFu, ls, 1);
            ls += __shfl_xor_sync(0xFFFFFFFFu, ls, 2);
            l_i[rh] = l_i[rh] * al + ls;
            m_i[rh] = mnew;
#pragma unroll
            for (int nt = 0; nt < 8; nt++) {
                of[nt][rh * 2] *= al; of[nt][rh * 2 + 1] *= al;
            }
        }

#pragma unroll
        for (int ks = 0; ks < 4; ks++) {
            uint32_t bv[4][4];
#pragma unroll
            for (int nt2 = 0; nt2 < 4; nt2++) {
                int srow = ks * 16 + vrow8;
                int dchunk = nt2 * 2 + vdo;
                uint32_t off = (uint32_t)(srow * 128 + ((dchunk ^ (srow & 7)) * 16));
                LDSM_X4T(bv[nt2], vbase + off);
            }
            uint32_t ph[4];
            {
                float e[8] = {sacc[2*ks][0], sacc[2*ks][1], sacc[2*ks][2], sacc[2*ks][3],
                              sacc[2*ks+1][0], sacc[2*ks+1][1], sacc[2*ks+1][2], sacc[2*ks+1][3]};
                ph[0] = pack_h2(__float2half_rn(e[0]), __float2half_rn(e[1]));
                ph[1] = pack_h2(__float2half_rn(e[2]), __float2half_rn(e[3]));
                ph[2] = pack_h2(__float2half_rn(e[4]), __float2half_rn(e[5]));
                ph[3] = pack_h2(__float2half_rn(e[6]), __float2half_rn(e[7]));
            }
#pragma unroll
            for (int nt2 = 0; nt2 < 4; nt2++) {
                MMA16816(of[2 * nt2],     ph, bv[nt2][0], bv[nt2][1]);
                MMA16816(of[2 * nt2 + 1], ph, bv[nt2][2], bv[nt2][3]);
            }
        }
        __syncthreads();
    }

    if (mode != 0) {
        {
            int row = tid >> 1, hf = tid & 1;
            int t_loc = t0 + row;
            int krow = n * 512 + 512 + t_loc;
            const __half* kr = kh + ((size_t)bh * TGT + krow) * HDIM + hf * 32;
            const float* qr2 = qb + row * 64 + hf * 32;
            float dot = 0.f;
#pragma unroll
            for (int j = 0; j < 16; j++) {
                float2 q2 = *(const float2*)(qr2 + j * 2);
                float2 kf = __half22float2(*(const __half2*)(kr + j * 2));
                dot += q2.x * kf.x + q2.y * kf.y;
            }
            dot += __shfl_xor_sync(0xFFFFFFFFu, dot, 1);
            float L = dot + sm.relrow[row][0];   // bucket(0) = 0
            if (!hf) sm.Ld[row] = L;
        }
        __syncthreads();
#pragma unroll
        for (int rh = 0; rh < 2; rh++) {
            int rl = wid * 16 + qr + rh * 8;
            int t_loc = t0 + rl;
            float L = sm.Ld[rl];
            float mnew = fmaxf(m_i[rh], L);
            float al = __expf(m_i[rh] - mnew);
            float p = __expf(L - mnew);
            l_i[rh] = l_i[rh] * al + p;
            m_i[rh] = mnew;
            const __half* vr = vh + ((size_t)bh * TGT + n * 512 + 512 + t_loc) * HDIM + qc * 2;
#pragma unroll
            for (int nt = 0; nt < 8; nt++) {
                float2 v2 = __half22float2(*(const __half2*)(vr + nt * 8));
                of[nt][rh * 2]     = of[nt][rh * 2]     * al + p * v2.x;
                of[nt][rh * 2 + 1] = of[nt][rh * 2 + 1] * al + p * v2.y;
            }
        }
    }

#pragma unroll
    for (int rh = 0; rh < 2; rh++) {
        int rl = wid * 16 + qr + rh * 8;
        float inv = 1.0f / l_i[rh];
        float* cb = ctx + ((size_t)(grow0 + rl) * 4 + b) * EDIM + h * 64 + qc * 2;
#pragma unroll
        for (int nt = 0; nt < 8; nt++)
            *(float2*)(cb + nt * 8) = make_float2(of[nt][rh * 2] * inv,
                                                  of[nt][rh * 2 + 1] * inv);
    }
}

// ---------------- launch -----------------------------------------------------
extern "C" void kernel_launch(void* const* d_in, const int* in_sizes, int n_in,
                              void* d_out, int out_size)
{
    const float* hidden = (const float*)d_in[0];
    const float* w_in   = (const float*)d_in[1];
    const float* b_in   = (const float*)d_in[2];
    const float* rel_w  = (const float*)d_in[3];
    const float* rel_b  = (const float*)d_in[4];
    const float* out_w  = (const float*)d_in[5];
    const float* out_b  = (const float*)d_in[6];
    const int* bkm = (const int*)d_in[9];
    const int* bkn = (const int*)d_in[10];
    float* out = (float*)d_out;

    float *qp, *rv, *ctx, *biascat;
    __half *khp, *vhp, *A2, *Wcat, *Wout2;
    cudaGetSymbolAddress((void**)&qp,  g_q);
    cudaGetSymbolAddress((void**)&khp, g_kh);
    cudaGetSymbolAddress((void**)&vhp, g_vh);
    cudaGetSymbolAddress((void**)&rv,  g_relvals);
    cudaGetSymbolAddress((void**)&ctx, g_ctx);
    cudaGetSymbolAddress((void**)&A2,    g_A2);
    cudaGetSymbolAddress((void**)&Wcat,  g_Wcat);
    cudaGetSymbolAddress((void**)&Wout2, g_Wout2);
    cudaGetSymbolAddress((void**)&biascat, g_biascat);

    cudaFuncSetAttribute(gemm_mma, cudaFuncAttributeMaxDynamicSharedMemorySize, GEMM_SMEM);
    cudaFuncSetAttribute(attn_tc, cudaFuncAttributeMaxDynamicSharedMemorySize,
                         (int)sizeof(AttnTc));

    // 0) fused conversion (+bias concat block)
    convert_all<<<10753, 256>>>(hidden, w_in, rel_w, out_w, b_in, rel_b,
                                A2, Wcat, Wout2, biascat);

    // 1) QKV + rel fused via weight concat (grid.x = 24 qkv + 4 rel tiles)
    gemm_mma<<<dim3(NCAT / 128, ROWS_ALL / 128), 256, GEMM_SMEM>>>(
        A2, Wcat, biascat, rv, 512, 32, 1, qp, khp, vhp);

    // 2) tensor-core flash attention
    attn_tc<<<dim3(8, 64, 3), 128, sizeof(AttnTc)>>>(qp, khp, vhp, rv, bkm, bkn, ctx);

    // 3) output projection
    convert_act<<<ROWS_ALL, 256>>>(ctx, A2);
    gemm_mma<<<dim3(1024 / 128, ROWS_ALL / 128), 256, GEMM_SMEM>>>(
        A2, Wout2, out_b, out, 1024, 32, 0, nullptr, nullptr, nullptr);
}